// round 3
// baseline (speedup 1.0000x reference)
#include <cuda_runtime.h>
#include <math.h>

// Problem constants
#define PB   16      // batch
#define PC   256     // channels
#define PN   4096    // H*W
#define PNH  4       // heads
#define PHD  32      // head dim
#define PNM  4       // memory tokens
#define PHID 128     // NH*HD
#define QROWS 384    // 3*HID

// ---------------- scratch (static device memory; no allocation) ----------------
__device__ float g_ws[QROWS * PC];                     // scaled qkv weights (g_in & sqrt(C) folded)
__device__ float g_invn[PB * PN];                      // 1/||x||_C per pixel
__device__ float g_qkv[(size_t)PB * QROWS * PN];       // qkv activations  (~100 MB)
__device__ float g_stat[2][PB * PNH * PHD];            // k softmax: rowmax, 1/rowsum
__device__ float g_ctxp[8][PB * PNH * PHD * PHD];      // partial contexts (8 token chunks)
__device__ float g_M[(size_t)PB * PC * PHID];          // folded  w_out . context  per batch

// ---------------- K0: scale weights: ws[o][c] = w_qkv[o][c] * g_in[c] * sqrt(C) ----------------
__global__ void k_prep_w(const float* __restrict__ w_qkv, const float* __restrict__ g_in) {
    int i = blockIdx.x * 256 + threadIdx.x;
    if (i < QROWS * PC) {
        int c = i & (PC - 1);
        g_ws[i] = w_qkv[i] * g_in[c] * 16.0f;   // sqrt(256) = 16
    }
}

// ---------------- K1: per-pixel inverse channel norm ----------------
__global__ void k_invnorm(const float* __restrict__ x) {
    int p = blockIdx.x * 256 + threadIdx.x;   // pixel within batch
    int b = blockIdx.y;
    const float* xp = x + (size_t)b * PC * PN + p;
    float s = 0.0f;
#pragma unroll 8
    for (int c = 0; c < PC; c++) {
        float v = xp[(size_t)c * PN];
        s += v * v;
    }
    g_invn[b * PN + p] = 1.0f / fmaxf(sqrtf(s), 1e-12f);
}

// ---------------- K2: qkv GEMM  qkv[b] = (ws @ x[b]) * invn_col ----------------
// 128x128 tile, BK=32, 256 threads, 8x8 per-thread register tile
__global__ void k_qkv_gemm(const float* __restrict__ x) {
    const int BM = 128, BN = 128, BK = 32;
    __shared__ float As[BK][BM + 4];   // pad 4 -> conflict-free & float4-aligned reads
    __shared__ float Bs[BK][BN];
    int bn = blockIdx.x, bm = blockIdx.y, b = blockIdx.z;
    int tid = threadIdx.x;
    int mbase = bm * BM, nbase = bn * BN;
    int ty = tid >> 4, tx = tid & 15;
    int row0 = ty * 8, col0 = tx * 8;
    float acc[8][8];
#pragma unroll
    for (int i = 0; i < 8; i++)
#pragma unroll
        for (int j = 0; j < 8; j++) acc[i][j] = 0.0f;

    for (int kb = 0; kb < PC; kb += BK) {
        // load A tile (ws): 128 rows x 32 cols -> transposed into As
#pragma unroll
        for (int i = 0; i < 4; i++) {
            int f4 = tid + i * 256;                 // 0..1023
            int r = f4 >> 3, c4 = (f4 & 7) << 2;
            float4 v = *reinterpret_cast<const float4*>(&g_ws[(mbase + r) * PC + kb + c4]);
            As[c4 + 0][r] = v.x; As[c4 + 1][r] = v.y;
            As[c4 + 2][r] = v.z; As[c4 + 3][r] = v.w;
        }
        // load B tile (x): 32 rows (channels) x 128 cols (pixels)
#pragma unroll
        for (int i = 0; i < 4; i++) {
            int f4 = tid + i * 256;
            int r = f4 >> 5, c4 = (f4 & 31) << 2;
            float4 v = *reinterpret_cast<const float4*>(
                &x[((size_t)(b * PC + kb + r)) * PN + nbase + c4]);
            *reinterpret_cast<float4*>(&Bs[r][c4]) = v;
        }
        __syncthreads();
#pragma unroll
        for (int k = 0; k < BK; k++) {
            float a[8], bb[8];
            *reinterpret_cast<float4*>(&a[0]) = *reinterpret_cast<const float4*>(&As[k][row0]);
            *reinterpret_cast<float4*>(&a[4]) = *reinterpret_cast<const float4*>(&As[k][row0 + 4]);
            *reinterpret_cast<float4*>(&bb[0]) = *reinterpret_cast<const float4*>(&Bs[k][col0]);
            *reinterpret_cast<float4*>(&bb[4]) = *reinterpret_cast<const float4*>(&Bs[k][col0 + 4]);
#pragma unroll
            for (int i = 0; i < 8; i++)
#pragma unroll
                for (int j = 0; j < 8; j++) acc[i][j] += a[i] * bb[j];
        }
        __syncthreads();
    }
    // epilogue: scale by per-pixel invnorm, store
    float s[8];
#pragma unroll
    for (int j = 0; j < 8; j++) s[j] = g_invn[b * PN + nbase + col0 + j];
#pragma unroll
    for (int i = 0; i < 8; i++) {
        size_t off = ((size_t)b * QROWS + mbase + row0 + i) * PN + nbase + col0;
        float4 v0, v1;
        v0.x = acc[i][0] * s[0]; v0.y = acc[i][1] * s[1];
        v0.z = acc[i][2] * s[2]; v0.w = acc[i][3] * s[3];
        v1.x = acc[i][4] * s[4]; v1.y = acc[i][5] * s[5];
        v1.z = acc[i][6] * s[6]; v1.w = acc[i][7] * s[7];
        *reinterpret_cast<float4*>(&g_qkv[off]) = v0;
        *reinterpret_cast<float4*>(&g_qkv[off + 4]) = v1;
    }
}

// ---------------- K3a: k row softmax stats (max, 1/sumexp) over 4096 + 4 memory tokens ----------------
// one warp per row (b,h,d); 2048 rows total
__global__ void k_kstats(const float* __restrict__ mem_kv) {
    int gwarp = (blockIdx.x * blockDim.x + threadIdx.x) >> 5;
    int lane = threadIdx.x & 31;
    if (gwarp >= PB * PNH * PHD) return;
    int d = gwarp & 31, h = (gwarp >> 5) & 3, b = gwarp >> 7;
    const float* krow = &g_qkv[((size_t)b * QROWS + PHID + h * PHD + d) * PN];
    float m = -1e30f, s = 0.0f;
    for (int p = lane; p < PN; p += 32) {
        float v = krow[p];
        if (v > m) { s = s * __expf(m - v) + 1.0f; m = v; }
        else       { s += __expf(v - m); }
    }
    if (lane < PNM) {
        float v = mem_kv[((0 * PNH + h) * PHD + d) * PNM + lane];
        if (v > m) { s = s * __expf(m - v) + 1.0f; m = v; }
        else       { s += __expf(v - m); }
    }
#pragma unroll
    for (int o = 16; o > 0; o >>= 1) {
        float m2 = __shfl_xor_sync(0xffffffffu, m, o);
        float s2 = __shfl_xor_sync(0xffffffffu, s, o);
        float mm = fmaxf(m, m2);
        s = s * __expf(m - mm) + s2 * __expf(m2 - mm);
        m = mm;
    }
    if (lane == 0) { g_stat[0][gwarp] = m; g_stat[1][gwarp] = 1.0f / s; }
}

// ---------------- K3b: partial context  ctx[d][e] = sum_n softmax_k[d,n]*v[e,n] ----------------
// grid (8 token chunks, NH, B); chunk 0 also adds the 4 memory tokens
__global__ void k_context(const float* __restrict__ mem_kv) {
    __shared__ float Ks[PHD][68];       // pad 68: conflict-free, row not float4 (scalar stores)
    __shared__ float Vt[64][33];        // transposed v tile
    __shared__ float rmax[PHD], rinv[PHD];
    int tc = blockIdx.x, h = blockIdx.y, b = blockIdx.z;
    int tid = threadIdx.x;
    if (tid < PHD) {
        int rowid = (b * PNH + h) * PHD + tid;
        rmax[tid] = g_stat[0][rowid];
        rinv[tid] = g_stat[1][rowid];
    }
    __syncthreads();
    int d = tid >> 3;
    int eg = (tid & 7) << 2;
    float acc[4] = {0.f, 0.f, 0.f, 0.f};
    if (tc == 0) {
#pragma unroll
        for (int m = 0; m < PNM; m++) {
            float kv = __expf(mem_kv[((0 * PNH + h) * PHD + d) * PNM + m] - rmax[d]) * rinv[d];
#pragma unroll
            for (int i = 0; i < 4; i++)
                acc[i] += kv * mem_kv[((1 * PNH + h) * PHD + eg + i) * PNM + m];
        }
    }
    int pbase = tc * 512;
    for (int t = 0; t < 8; t++) {
        int p0 = pbase + t * 64;
        // K tile 32x64, exp-normalized at load
#pragma unroll
        for (int i = 0; i < 2; i++) {
            int f4 = tid + i * 256;                  // 512 float4
            int r = f4 >> 4, c4 = (f4 & 15) << 2;
            float4 v = *reinterpret_cast<const float4*>(
                &g_qkv[((size_t)b * QROWS + PHID + h * PHD + r) * PN + p0 + c4]);
            float mx = rmax[r], ri = rinv[r];
            Ks[r][c4 + 0] = __expf(v.x - mx) * ri;
            Ks[r][c4 + 1] = __expf(v.y - mx) * ri;
            Ks[r][c4 + 2] = __expf(v.z - mx) * ri;
            Ks[r][c4 + 3] = __expf(v.w - mx) * ri;
        }
        // V tile 32x64 -> transposed
#pragma unroll
        for (int i = 0; i < 2; i++) {
            int f4 = tid + i * 256;
            int r = f4 >> 4, c4 = (f4 & 15) << 2;
            float4 v = *reinterpret_cast<const float4*>(
                &g_qkv[((size_t)b * QROWS + 2 * PHID + h * PHD + r) * PN + p0 + c4]);
            Vt[c4 + 0][r] = v.x; Vt[c4 + 1][r] = v.y;
            Vt[c4 + 2][r] = v.z; Vt[c4 + 3][r] = v.w;
        }
        __syncthreads();
#pragma unroll
        for (int n = 0; n < 64; n++) {
            float kv = Ks[d][n];
#pragma unroll
            for (int i = 0; i < 4; i++) acc[i] += kv * Vt[n][eg + i];
        }
        __syncthreads();
    }
    size_t base = ((size_t)(b * PNH + h) * PHD + d) * PHD + eg;
#pragma unroll
    for (int i = 0; i < 4; i++) g_ctxp[tc][base + i] = acc[i];
}

// ---------------- K4: reduce partial contexts + fold M = w_out . ctx ----------------
// M[b][o][h*32+d] = sum_e w_out[o][h*32+e] * ctx[b][h][d][e]
__global__ void k_fold(const float* __restrict__ w_out) {
    __shared__ float ctx[PNH * PHD * PHD];   // [h][d][e] flat, 16 KB
    int b = blockIdx.x;
    int tid = threadIdx.x;
    for (int idx = tid; idx < PNH * PHD * PHD; idx += 256) {
        float s = 0.0f;
#pragma unroll
        for (int tc = 0; tc < 8; tc++) s += g_ctxp[tc][b * (PNH * PHD * PHD) + idx];
        ctx[idx] = s;
    }
    __syncthreads();
    int o = tid;
    for (int h = 0; h < PNH; h++) {
        float w[PHD];
#pragma unroll
        for (int e = 0; e < PHD; e++) w[e] = w_out[o * PHID + h * PHD + e];
        for (int dd = 0; dd < PHD; dd++) {
            float s = 0.0f;
#pragma unroll
            for (int e = 0; e < PHD; e++) s += w[e] * ctx[(h * PHD + dd) * PHD + e];
            g_M[((size_t)b * PC + o) * PHID + h * PHD + dd] = s;
        }
    }
}

// ---------------- K5: fused q-softmax + output GEMM + bias + final RMS norm ----------------
// per block: all 256 output channels x 32 pixels.  Out = M[b] @ softmax_d(q)*scale + b_out, then RMS over C.
__global__ void k_out(const float* __restrict__ b_out,
                      const float* __restrict__ g_out,
                      float* __restrict__ out) {
    __shared__ float Qs[PHID][33];      // q tile (softmaxed in place)
    __shared__ float As[16][260];       // M chunk transposed [k][o], padded
    __shared__ float red[32][32];       // column partial sum-of-squares
    __shared__ float invr[32];
    int pb = blockIdx.x * 32;
    int b = blockIdx.y;
    int tid = threadIdx.x;

    // load q tile [128 rows x 32 pixels]
#pragma unroll
    for (int i = 0; i < 4; i++) {
        int f4 = tid + i * 256;                    // 1024 float4
        int r = f4 >> 3, c4 = (f4 & 7) << 2;
        float4 v = *reinterpret_cast<const float4*>(
            &g_qkv[((size_t)b * QROWS + r) * PN + pb + c4]);
        Qs[r][c4 + 0] = v.x; Qs[r][c4 + 1] = v.y;
        Qs[r][c4 + 2] = v.z; Qs[r][c4 + 3] = v.w;
    }
    __syncthreads();

    // softmax over head_dim (32) per (head, pixel), times HD^-0.5
    if (tid < 128) {
        int p = tid & 31, h = tid >> 5;
        float m = -1e30f;
#pragma unroll
        for (int dd = 0; dd < PHD; dd++) m = fmaxf(m, Qs[h * PHD + dd][p]);
        float e[PHD];
        float s = 0.0f;
#pragma unroll
        for (int dd = 0; dd < PHD; dd++) { e[dd] = __expf(Qs[h * PHD + dd][p] - m); s += e[dd]; }
        float inv = 0.17677669529663687f / s;     // (1/sqrt(32)) / sumexp
#pragma unroll
        for (int dd = 0; dd < PHD; dd++) Qs[h * PHD + dd][p] = e[dd] * inv;
    }
    __syncthreads();

    // GEMM: 256 threads = 32 rowgroups (8 rows) x 8 colgroups (4 cols)
    int rg = tid >> 3, cg = tid & 7;
    int o0 = rg * 8, p0 = cg * 4;
    float acc[8][4];
#pragma unroll
    for (int i = 0; i < 8; i++)
#pragma unroll
        for (int j = 0; j < 4; j++) acc[i][j] = 0.0f;

    for (int kb = 0; kb < PHID; kb += 16) {
        // stage M chunk [256 o x 16 k] transposed
#pragma unroll
        for (int i = 0; i < 4; i++) {
            int f4 = tid + i * 256;                 // 1024 float4
            int r = f4 >> 2, c4 = (f4 & 3) << 2;
            float4 v = *reinterpret_cast<const float4*>(
                &g_M[((size_t)b * PC + r) * PHID + kb + c4]);
            As[c4 + 0][r] = v.x; As[c4 + 1][r] = v.y;
            As[c4 + 2][r] = v.z; As[c4 + 3][r] = v.w;
        }
        __syncthreads();
#pragma unroll
        for (int k = 0; k < 16; k++) {
            float qv[4], a[8];
#pragma unroll
            for (int j = 0; j < 4; j++) qv[j] = Qs[kb + k][p0 + j];
            *reinterpret_cast<float4*>(&a[0]) = *reinterpret_cast<const float4*>(&As[k][o0]);
            *reinterpret_cast<float4*>(&a[4]) = *reinterpret_cast<const float4*>(&As[k][o0 + 4]);
#pragma unroll
            for (int i = 0; i < 8; i++)
#pragma unroll
                for (int j = 0; j < 4; j++) acc[i][j] += a[i] * qv[j];
        }
        __syncthreads();
    }

    // bias, column sum-of-squares
    float sq[4] = {0.f, 0.f, 0.f, 0.f};
#pragma unroll
    for (int i = 0; i < 8; i++) {
        float bo = b_out[o0 + i];
#pragma unroll
        for (int j = 0; j < 4; j++) {
            acc[i][j] += bo;
            sq[j] += acc[i][j] * acc[i][j];
        }
    }
#pragma unroll
    for (int j = 0; j < 4; j++) red[rg][p0 + j] = sq[j];
    __syncthreads();
    if (tid < 32) {
        float s = 0.0f;
#pragma unroll
        for (int r = 0; r < 32; r++) s += red[r][tid];
        invr[tid] = 16.0f / fmaxf(sqrtf(s), 1e-12f);
    }
    __syncthreads();

    float iv[4];
#pragma unroll
    for (int j = 0; j < 4; j++) iv[j] = invr[p0 + j];
#pragma unroll
    for (int i = 0; i < 8; i++) {
        float go = g_out[o0 + i];
        float4 v;
        v.x = acc[i][0] * iv[0] * go;
        v.y = acc[i][1] * iv[1] * go;
        v.z = acc[i][2] * iv[2] * go;
        v.w = acc[i][3] * iv[3] * go;
        *reinterpret_cast<float4*>(
            &out[((size_t)(b * PC + o0 + i)) * PN + pb + p0]) = v;
    }
}

// ---------------- launch ----------------
extern "C" void kernel_launch(void* const* d_in, const int* in_sizes, int n_in,
                              void* d_out, int out_size) {
    const float* x      = (const float*)d_in[0];
    const float* g_in   = (const float*)d_in[1];
    const float* mem_kv = (const float*)d_in[2];
    const float* w_qkv  = (const float*)d_in[3];
    const float* w_out  = (const float*)d_in[4];
    const float* b_out  = (const float*)d_in[5];
    const float* g_out  = (const float*)d_in[6];
    float* out = (float*)d_out;

    k_prep_w <<<QROWS, 256>>>(w_qkv, g_in);
    k_invnorm<<<dim3(PN / 256, PB), 256>>>(x);
    k_qkv_gemm<<<dim3(PN / 128, QROWS / 128, PB), 256>>>(x);
    k_kstats <<<256, 256>>>(mem_kv);
    k_context<<<dim3(8, PNH, PB), 256>>>(mem_kv);
    k_fold   <<<PB, 256>>>(w_out);
    k_out    <<<dim3(PN / 32, PB), 256>>>(b_out, g_out, out);
}

// round 7
// speedup vs baseline: 1.0018x; 1.0018x over previous
#include <cuda_runtime.h>
#include <math.h>

// Problem constants
#define PB   16      // batch
#define PC   256     // channels
#define PN   4096    // H*W
#define PNH  4       // heads
#define PHD  32      // head dim
#define PNM  4       // memory tokens
#define PHID 128     // NH*HD
#define QROWS 384    // 3*HID

typedef unsigned long long u64;

// ---------------- f32x2 packed-math helpers (sm_103a FFMA2 pipe) ----------------
__device__ __forceinline__ u64 fma2(u64 a, u64 b, u64 c) {
    u64 d;
    asm("fma.rn.f32x2 %0, %1, %2, %3;" : "=l"(d) : "l"(a), "l"(b), "l"(c));
    return d;
}
__device__ __forceinline__ u64 pack2(float lo, float hi) {
    u64 r; asm("mov.b64 %0, {%1, %2};" : "=l"(r) : "f"(lo), "f"(hi)); return r;
}
__device__ __forceinline__ float2 unpack2(u64 v) {
    float2 r; asm("mov.b64 {%0, %1}, %2;" : "=f"(r.x), "=f"(r.y) : "l"(v)); return r;
}

// ---------------- scratch (static device memory; no allocation) ----------------
__device__ float g_ws[QROWS * PC];                     // scaled qkv weights (g_in & sqrt(C) folded)
__device__ float g_invn[PB * PN];                      // 1/||x||_C per pixel
__device__ float g_qkv[(size_t)PB * QROWS * PN];       // qkv activations  (~100 MB)
__device__ float g_stat[2][PB * PNH * PHD];            // k softmax: rowmax, 1/rowsum
__device__ float g_ctxp[8][PB * PNH * PHD * PHD];      // partial contexts (8 token chunks)
__device__ float g_M[(size_t)PB * PC * PHID];          // folded  w_out . context  per batch

// ---------------- K0: scale weights: ws[o][c] = w_qkv[o][c] * g_in[c] * sqrt(C) ----------------
__global__ void k_prep_w(const float* __restrict__ w_qkv, const float* __restrict__ g_in) {
    int i = blockIdx.x * 256 + threadIdx.x;
    if (i < QROWS * PC) {
        int c = i & (PC - 1);
        g_ws[i] = w_qkv[i] * g_in[c] * 16.0f;   // sqrt(256) = 16
    }
}

// ---------------- K1: per-pixel inverse channel norm (4 independent chains) ----------------
__global__ void k_invnorm(const float* __restrict__ x) {
    int p = blockIdx.x * 256 + threadIdx.x;   // pixel within batch
    int b = blockIdx.y;
    const float* xp = x + (size_t)b * PC * PN + p;
    float s0 = 0.f, s1 = 0.f, s2 = 0.f, s3 = 0.f;
#pragma unroll
    for (int c = 0; c < PC; c += 4) {
        float v0 = xp[(size_t)(c + 0) * PN];
        float v1 = xp[(size_t)(c + 1) * PN];
        float v2 = xp[(size_t)(c + 2) * PN];
        float v3 = xp[(size_t)(c + 3) * PN];
        s0 += v0 * v0; s1 += v1 * v1; s2 += v2 * v2; s3 += v3 * v3;
    }
    float s = (s0 + s1) + (s2 + s3);
    g_invn[b * PN + p] = 1.0f / fmaxf(sqrtf(s), 1e-12f);
}

// ---------------- K2: qkv GEMM  qkv[b] = (ws @ x[b]) * invn_col  (FFMA2) ----------------
// 128x128 tile, BK=32, 256 threads, 8x8 per-thread tile packed as 8x4 f32x2
__global__ void k_qkv_gemm(const float* __restrict__ x) {
    const int BM = 128, BN = 128, BK = 32;
    __shared__ float As[BK][BM + 4];   // pad 4 -> conflict-free & 16B-aligned rows
    __shared__ float Bs[BK][BN];
    int bn = blockIdx.x, bm = blockIdx.y, b = blockIdx.z;
    int tid = threadIdx.x;
    int mbase = bm * BM, nbase = bn * BN;
    int ty = tid >> 4, tx = tid & 15;
    int row0 = ty * 8, col0 = tx * 8;
    u64 accp[8][4];
#pragma unroll
    for (int i = 0; i < 8; i++)
#pragma unroll
        for (int j = 0; j < 4; j++) accp[i][j] = 0ull;

    for (int kb = 0; kb < PC; kb += BK) {
        // load A tile (ws): 128 rows x 32 cols -> transposed into As
#pragma unroll
        for (int i = 0; i < 4; i++) {
            int f4 = tid + i * 256;                 // 0..1023
            int r = f4 >> 3, c4 = (f4 & 7) << 2;
            float4 v = *reinterpret_cast<const float4*>(&g_ws[(mbase + r) * PC + kb + c4]);
            As[c4 + 0][r] = v.x; As[c4 + 1][r] = v.y;
            As[c4 + 2][r] = v.z; As[c4 + 3][r] = v.w;
        }
        // load B tile (x): 32 rows (channels) x 128 cols (pixels)
#pragma unroll
        for (int i = 0; i < 4; i++) {
            int f4 = tid + i * 256;
            int r = f4 >> 5, c4 = (f4 & 31) << 2;
            float4 v = *reinterpret_cast<const float4*>(
                &x[((size_t)(b * PC + kb + r)) * PN + nbase + c4]);
            *reinterpret_cast<float4*>(&Bs[r][c4]) = v;
        }
        __syncthreads();
#pragma unroll
        for (int k = 0; k < BK; k++) {
            float a[8];
            *reinterpret_cast<float4*>(&a[0]) = *reinterpret_cast<const float4*>(&As[k][row0]);
            *reinterpret_cast<float4*>(&a[4]) = *reinterpret_cast<const float4*>(&As[k][row0 + 4]);
            // B pairs read directly as packed f32x2 (16B-aligned)
            ulonglong2 b01 = *reinterpret_cast<const ulonglong2*>(&Bs[k][col0]);
            ulonglong2 b23 = *reinterpret_cast<const ulonglong2*>(&Bs[k][col0 + 4]);
            u64 bp[4] = {b01.x, b01.y, b23.x, b23.y};
#pragma unroll
            for (int i = 0; i < 8; i++) {
                u64 ad = pack2(a[i], a[i]);
#pragma unroll
                for (int j = 0; j < 4; j++) accp[i][j] = fma2(ad, bp[j], accp[i][j]);
            }
        }
        __syncthreads();
    }
    // epilogue: scale by per-pixel invnorm, store
    float s[8];
#pragma unroll
    for (int j = 0; j < 8; j++) s[j] = g_invn[b * PN + nbase + col0 + j];
#pragma unroll
    for (int i = 0; i < 8; i++) {
        float acc[8];
#pragma unroll
        for (int j = 0; j < 4; j++) {
            float2 p = unpack2(accp[i][j]);
            acc[2 * j] = p.x; acc[2 * j + 1] = p.y;
        }
        size_t off = ((size_t)b * QROWS + mbase + row0 + i) * PN + nbase + col0;
        float4 v0, v1;
        v0.x = acc[0] * s[0]; v0.y = acc[1] * s[1];
        v0.z = acc[2] * s[2]; v0.w = acc[3] * s[3];
        v1.x = acc[4] * s[4]; v1.y = acc[5] * s[5];
        v1.z = acc[6] * s[6]; v1.w = acc[7] * s[7];
        *reinterpret_cast<float4*>(&g_qkv[off]) = v0;
        *reinterpret_cast<float4*>(&g_qkv[off + 4]) = v1;
    }
}

// ---------------- K3a: k row softmax stats, two-pass with 4-way ILP ----------------
// one warp per row (b,h,d); 2048 rows total
__global__ void k_kstats(const float* __restrict__ mem_kv) {
    int gwarp = (blockIdx.x * blockDim.x + threadIdx.x) >> 5;
    int lane = threadIdx.x & 31;
    if (gwarp >= PB * PNH * PHD) return;
    int d = gwarp & 31, h = (gwarp >> 5) & 3, b = gwarp >> 7;
    const float* krow = &g_qkv[((size_t)b * QROWS + PHID + h * PHD + d) * PN];

    // pass 1: max (4 independent chains)
    float m0 = -1e30f, m1 = -1e30f, m2 = -1e30f, m3 = -1e30f;
    for (int p = lane; p < PN; p += 128) {
        m0 = fmaxf(m0, krow[p]);
        m1 = fmaxf(m1, krow[p + 32]);
        m2 = fmaxf(m2, krow[p + 64]);
        m3 = fmaxf(m3, krow[p + 96]);
    }
    float m = fmaxf(fmaxf(m0, m1), fmaxf(m2, m3));
    if (lane < PNM)
        m = fmaxf(m, mem_kv[((0 * PNH + h) * PHD + d) * PNM + lane]);
#pragma unroll
    for (int o = 16; o > 0; o >>= 1)
        m = fmaxf(m, __shfl_xor_sync(0xffffffffu, m, o));

    // pass 2: sum of exp(v - m) (4 independent chains)
    float s0 = 0.f, s1 = 0.f, s2 = 0.f, s3 = 0.f;
    for (int p = lane; p < PN; p += 128) {
        s0 += __expf(krow[p] - m);
        s1 += __expf(krow[p + 32] - m);
        s2 += __expf(krow[p + 64] - m);
        s3 += __expf(krow[p + 96] - m);
    }
    float s = (s0 + s1) + (s2 + s3);
    if (lane < PNM)
        s += __expf(mem_kv[((0 * PNH + h) * PHD + d) * PNM + lane] - m);
#pragma unroll
    for (int o = 16; o > 0; o >>= 1)
        s += __shfl_xor_sync(0xffffffffu, s, o);
    if (lane == 0) { g_stat[0][gwarp] = m; g_stat[1][gwarp] = 1.0f / s; }
}

// ---------------- K3b: partial context  ctx[d][e] = sum_n softmax_k[d,n]*v[e,n]  (FFMA2) ----------------
// grid (8 token chunks, NH, B); chunk 0 also adds the 4 memory tokens
__global__ void k_context(const float* __restrict__ mem_kv) {
    __shared__ float Ks[PHD][68];       // pad 68: conflict-free (scalar reads)
    __shared__ float Vt[64][34];        // transposed v tile; pad 34 keeps rows 8B-aligned
    __shared__ float rmax[PHD], rinv[PHD];
    int tc = blockIdx.x, h = blockIdx.y, b = blockIdx.z;
    int tid = threadIdx.x;
    if (tid < PHD) {
        int rowid = (b * PNH + h) * PHD + tid;
        rmax[tid] = g_stat[0][rowid];
        rinv[tid] = g_stat[1][rowid];
    }
    __syncthreads();
    int d = tid >> 3;
    int eg = (tid & 7) << 2;
    float macc[4] = {0.f, 0.f, 0.f, 0.f};
    if (tc == 0) {
#pragma unroll
        for (int m = 0; m < PNM; m++) {
            float kv = __expf(mem_kv[((0 * PNH + h) * PHD + d) * PNM + m] - rmax[d]) * rinv[d];
#pragma unroll
            for (int i = 0; i < 4; i++)
                macc[i] += kv * mem_kv[((1 * PNH + h) * PHD + eg + i) * PNM + m];
        }
    }
    u64 accp[2] = {0ull, 0ull};
    int pbase = tc * 512;
    for (int t = 0; t < 8; t++) {
        int p0 = pbase + t * 64;
        // K tile 32x64, exp-normalized at load
#pragma unroll
        for (int i = 0; i < 2; i++) {
            int f4 = tid + i * 256;                  // 512 float4
            int r = f4 >> 4, c4 = (f4 & 15) << 2;
            float4 v = *reinterpret_cast<const float4*>(
                &g_qkv[((size_t)b * QROWS + PHID + h * PHD + r) * PN + p0 + c4]);
            float mx = rmax[r], ri = rinv[r];
            Ks[r][c4 + 0] = __expf(v.x - mx) * ri;
            Ks[r][c4 + 1] = __expf(v.y - mx) * ri;
            Ks[r][c4 + 2] = __expf(v.z - mx) * ri;
            Ks[r][c4 + 3] = __expf(v.w - mx) * ri;
        }
        // V tile 32x64 -> transposed
#pragma unroll
        for (int i = 0; i < 2; i++) {
            int f4 = tid + i * 256;
            int r = f4 >> 4, c4 = (f4 & 15) << 2;
            float4 v = *reinterpret_cast<const float4*>(
                &g_qkv[((size_t)b * QROWS + 2 * PHID + h * PHD + r) * PN + p0 + c4]);
            Vt[c4 + 0][r] = v.x; Vt[c4 + 1][r] = v.y;
            Vt[c4 + 2][r] = v.z; Vt[c4 + 3][r] = v.w;
        }
        __syncthreads();
#pragma unroll
        for (int n = 0; n < 64; n++) {
            u64 kv2 = pack2(Ks[d][n], Ks[d][n]);
            u64 v0 = *reinterpret_cast<const u64*>(&Vt[n][eg]);
            u64 v1 = *reinterpret_cast<const u64*>(&Vt[n][eg + 2]);
            accp[0] = fma2(kv2, v0, accp[0]);
            accp[1] = fma2(kv2, v1, accp[1]);
        }
        __syncthreads();
    }
    size_t base = ((size_t)(b * PNH + h) * PHD + d) * PHD + eg;
    float2 p0 = unpack2(accp[0]);
    float2 p1 = unpack2(accp[1]);
    g_ctxp[tc][base + 0] = p0.x + macc[0];
    g_ctxp[tc][base + 1] = p0.y + macc[1];
    g_ctxp[tc][base + 2] = p1.x + macc[2];
    g_ctxp[tc][base + 3] = p1.y + macc[3];
}

// ---------------- K4: reduce partial contexts + fold M = w_out . ctx ----------------
__global__ void k_fold(const float* __restrict__ w_out) {
    __shared__ float ctx[PNH * PHD * PHD];   // [h][d][e] flat, 16 KB
    int b = blockIdx.x;
    int tid = threadIdx.x;
    for (int idx = tid; idx < PNH * PHD * PHD; idx += 256) {
        float s = 0.0f;
#pragma unroll
        for (int tc = 0; tc < 8; tc++) s += g_ctxp[tc][b * (PNH * PHD * PHD) + idx];
        ctx[idx] = s;
    }
    __syncthreads();
    int o = tid;
    for (int h = 0; h < PNH; h++) {
        float w[PHD];
#pragma unroll
        for (int e = 0; e < PHD; e++) w[e] = w_out[o * PHID + h * PHD + e];
        for (int dd = 0; dd < PHD; dd++) {
            float s = 0.0f;
#pragma unroll
            for (int e = 0; e < PHD; e++) s += w[e] * ctx[(h * PHD + dd) * PHD + e];
            g_M[((size_t)b * PC + o) * PHID + h * PHD + dd] = s;
        }
    }
}

// ---------------- K5: fused q-softmax + output GEMM + bias + final RMS norm (FFMA2) ----------------
__global__ void k_out(const float* __restrict__ b_out,
                      const float* __restrict__ g_out,
                      float* __restrict__ out) {
    __shared__ float Qs[PHID][33];      // q tile (softmaxed in place)
    __shared__ float As[16][260];       // M chunk transposed [k][o]; rows 16B-aligned
    __shared__ float red[32][32];       // column partial sum-of-squares
    __shared__ float invr[32];
    int pb = blockIdx.x * 32;
    int b = blockIdx.y;
    int tid = threadIdx.x;

    // load q tile [128 rows x 32 pixels]
#pragma unroll
    for (int i = 0; i < 4; i++) {
        int f4 = tid + i * 256;                    // 1024 float4
        int r = f4 >> 3, c4 = (f4 & 7) << 2;
        float4 v = *reinterpret_cast<const float4*>(
            &g_qkv[((size_t)b * QROWS + r) * PN + pb + c4]);
        Qs[r][c4 + 0] = v.x; Qs[r][c4 + 1] = v.y;
        Qs[r][c4 + 2] = v.z; Qs[r][c4 + 3] = v.w;
    }
    __syncthreads();

    // softmax over head_dim (32) per (head, pixel), times HD^-0.5
    if (tid < 128) {
        int p = tid & 31, h = tid >> 5;
        float m = -1e30f;
#pragma unroll
        for (int dd = 0; dd < PHD; dd++) m = fmaxf(m, Qs[h * PHD + dd][p]);
        float e[PHD];
        float s = 0.0f;
#pragma unroll
        for (int dd = 0; dd < PHD; dd++) { e[dd] = __expf(Qs[h * PHD + dd][p] - m); s += e[dd]; }
        float inv = 0.17677669529663687f / s;     // (1/sqrt(32)) / sumexp
#pragma unroll
        for (int dd = 0; dd < PHD; dd++) Qs[h * PHD + dd][p] = e[dd] * inv;
    }
    __syncthreads();

    // GEMM: 256 threads = 32 rowgroups (8 rows) x 8 colgroups (4 cols)
    // acc packed over channel pairs: accp[i2][j] = rows (2*i2, 2*i2+1), col j
    int rg = tid >> 3, cg = tid & 7;
    int o0 = rg * 8, p0 = cg * 4;
    u64 accp[4][4];
#pragma unroll
    for (int i = 0; i < 4; i++)
#pragma unroll
        for (int j = 0; j < 4; j++) accp[i][j] = 0ull;

    for (int kb = 0; kb < PHID; kb += 16) {
        // stage M chunk [256 o x 16 k] transposed
#pragma unroll
        for (int i = 0; i < 4; i++) {
            int f4 = tid + i * 256;                 // 1024 float4
            int r = f4 >> 2, c4 = (f4 & 3) << 2;
            float4 v = *reinterpret_cast<const float4*>(
                &g_M[((size_t)b * PC + r) * PHID + kb + c4]);
            As[c4 + 0][r] = v.x; As[c4 + 1][r] = v.y;
            As[c4 + 2][r] = v.z; As[c4 + 3][r] = v.w;
        }
        __syncthreads();
#pragma unroll
        for (int k = 0; k < 16; k++) {
            // A pairs direct packed loads (16B-aligned)
            ulonglong2 a01 = *reinterpret_cast<const ulonglong2*>(&As[k][o0]);
            ulonglong2 a23 = *reinterpret_cast<const ulonglong2*>(&As[k][o0 + 4]);
            u64 ap[4] = {a01.x, a01.y, a23.x, a23.y};
#pragma unroll
            for (int j = 0; j < 4; j++) {
                float qv = Qs[kb + k][p0 + j];
                u64 qd = pack2(qv, qv);
#pragma unroll
                for (int i = 0; i < 4; i++) accp[i][j] = fma2(ap[i], qd, accp[i][j]);
            }
        }
        __syncthreads();
    }

    // unpack to acc[8][4]
    float acc[8][4];
#pragma unroll
    for (int i2 = 0; i2 < 4; i2++)
#pragma unroll
        for (int j = 0; j < 4; j++) {
            float2 p = unpack2(accp[i2][j]);
            acc[2 * i2][j] = p.x;
            acc[2 * i2 + 1][j] = p.y;
        }

    // bias, column sum-of-squares
    float sq[4] = {0.f, 0.f, 0.f, 0.f};
#pragma unroll
    for (int i = 0; i < 8; i++) {
        float bo = b_out[o0 + i];
#pragma unroll
        for (int j = 0; j < 4; j++) {
            acc[i][j] += bo;
            sq[j] += acc[i][j] * acc[i][j];
        }
    }
#pragma unroll
    for (int j = 0; j < 4; j++) red[rg][p0 + j] = sq[j];
    __syncthreads();
    if (tid < 32) {
        float s = 0.0f;
#pragma unroll
        for (int r = 0; r < 32; r++) s += red[r][tid];
        invr[tid] = 16.0f / fmaxf(sqrtf(s), 1e-12f);
    }
    __syncthreads();

    float iv[4];
#pragma unroll
    for (int j = 0; j < 4; j++) iv[j] = invr[p0 + j];
#pragma unroll
    for (int i = 0; i < 8; i++) {
        float go = g_out[o0 + i];
        float4 v;
        v.x = acc[i][0] * iv[0] * go;
        v.y = acc[i][1] * iv[1] * go;
        v.z = acc[i][2] * iv[2] * go;
        v.w = acc[i][3] * iv[3] * go;
        *reinterpret_cast<float4*>(
            &out[((size_t)(b * PC + o0 + i)) * PN + pb + p0]) = v;
    }
}

// ---------------- launch ----------------
extern "C" void kernel_launch(void* const* d_in, const int* in_sizes, int n_in,
                              void* d_out, int out_size) {
    const float* x      = (const float*)d_in[0];
    const float* g_in   = (const float*)d_in[1];
    const float* mem_kv = (const float*)d_in[2];
    const float* w_qkv  = (const float*)d_in[3];
    const float* w_out  = (const float*)d_in[4];
    const float* b_out  = (const float*)d_in[5];
    const float* g_out  = (const float*)d_in[6];
    float* out = (float*)d_out;

    k_prep_w <<<QROWS, 256>>>(w_qkv, g_in);
    k_invnorm<<<dim3(PN / 256, PB), 256>>>(x);
    k_qkv_gemm<<<dim3(PN / 128, QROWS / 128, PB), 256>>>(x);
    k_kstats <<<512, 128>>>(mem_kv);
    k_context<<<dim3(8, PNH, PB), 256>>>(mem_kv);
    k_fold   <<<PB, 256>>>(w_out);
    k_out    <<<dim3(PN / 32, PB), 256>>>(b_out, g_out, out);
}

// round 9
// speedup vs baseline: 1.3834x; 1.3808x over previous
#include <cuda_runtime.h>
#include <math.h>
#include <stdint.h>

// Problem constants
#define PB   16      // batch
#define PC   256     // channels
#define PN   4096    // H*W
#define PNH  4       // heads
#define PHD  32      // head dim
#define PNM  4       // memory tokens
#define PHID 128     // NH*HD
#define QROWS 384    // 3*HID
#define KX   768     // expanded K = 3*PC  (AhBh + AhBl + AlBh)

typedef unsigned long long u64;
typedef unsigned int u32;

// ---------------- scratch (static device memory; no allocation) ----------------
__device__ unsigned short g_wx[QROWS * KX];            // A' = [Ah, Ah, Al] per row
__device__ unsigned short g_xx[(size_t)PB * PN * KX];  // B' = [Bh, Bl, Bh] per pixel (~100 MB)
__device__ float g_invn[PB * PN];                      // 1/||x||_C per pixel
__device__ float g_qkv[(size_t)PB * QROWS * PN];       // qkv activations (~100 MB)
__device__ float g_stat[2][PB * PNH * PHD];            // k softmax: rowmax, 1/rowsum
__device__ float g_ctxp[8][PB * PNH * PHD * PHD];      // partial contexts (8 token chunks)
__device__ float g_M[(size_t)PB * PC * PHID];          // folded  w_out . context  per batch

// ---------------- small helpers ----------------
__device__ __forceinline__ unsigned bf16_rn(float v) {
    unsigned u = __float_as_uint(v);
    return (u + 0x7FFFu + ((u >> 16) & 1u)) >> 16;
}
__device__ __forceinline__ float bf16_tof(unsigned b) { return __uint_as_float(b << 16); }

__device__ __forceinline__ u32 smem_u32(const void* p) {
    u32 a;
    asm("{ .reg .u64 t; cvta.to.shared.u64 t, %1; cvt.u32.u64 %0, t; }" : "=r"(a) : "l"(p));
    return a;
}

// f32x2 packed helpers (k_out / k_context)
__device__ __forceinline__ u64 fma2(u64 a, u64 b, u64 c) {
    u64 d; asm("fma.rn.f32x2 %0, %1, %2, %3;" : "=l"(d) : "l"(a), "l"(b), "l"(c)); return d;
}
__device__ __forceinline__ u64 pack2(float lo, float hi) {
    u64 r; asm("mov.b64 %0, {%1, %2};" : "=l"(r) : "f"(lo), "f"(hi)); return r;
}
__device__ __forceinline__ float2 unpack2(u64 v) {
    float2 r; asm("mov.b64 {%0, %1}, %2;" : "=f"(r.x), "=f"(r.y) : "l"(v)); return r;
}

// ---------------- HMMA helpers (baseline ISA: ldmatrix + mma.sync) ----------------
__device__ __forceinline__ void ldsm4(u32* r, u32 addr) {
    asm volatile("ldmatrix.sync.aligned.m8n8.x4.shared.b16 {%0,%1,%2,%3}, [%4];"
                 : "=r"(r[0]), "=r"(r[1]), "=r"(r[2]), "=r"(r[3]) : "r"(addr));
}
__device__ __forceinline__ void mma16816(float* d, const u32* a, const u32* b) {
    asm volatile(
        "mma.sync.aligned.m16n8k16.row.col.f32.bf16.bf16.f32 "
        "{%0,%1,%2,%3}, {%4,%5,%6,%7}, {%8,%9}, {%0,%1,%2,%3};"
        : "+f"(d[0]), "+f"(d[1]), "+f"(d[2]), "+f"(d[3])
        : "r"(a[0]), "r"(a[1]), "r"(a[2]), "r"(a[3]), "r"(b[0]), "r"(b[1]));
}

// ---------------- K0a: weight convert  A' = [Ah, Ah, Al] of (w_qkv * g_in * sqrt(C)) ----------------
__global__ void k_convw(const float* __restrict__ w_qkv, const float* __restrict__ g_in) {
    int i = blockIdx.x * 256 + threadIdx.x;    // i = row*256 + c
    if (i < QROWS * PC) {
        int row = i >> 8, c = i & 255;
        float v = w_qkv[i] * g_in[c] * 16.0f;  // sqrt(256) = 16
        unsigned hb = bf16_rn(v);
        unsigned lb = bf16_rn(v - bf16_tof(hb));
        g_wx[row * KX + c]       = (unsigned short)hb;
        g_wx[row * KX + 256 + c] = (unsigned short)hb;
        g_wx[row * KX + 512 + c] = (unsigned short)lb;
    }
}

// ---------------- K0b: x transpose + split:  [b][c][n] -> B'[b][n][768] = [Bh, Bl, Bh] ----------------
__global__ void k_convx(const float* __restrict__ x) {
    __shared__ float ts[64][65];
    int n0 = blockIdx.x * 64, c0 = blockIdx.y * 64, b = blockIdx.z;
    int tid = threadIdx.x;
#pragma unroll
    for (int i = 0; i < 4; i++) {
        int f4 = tid + i * 256;                 // 1024 float4
        int r = f4 >> 4, col4 = (f4 & 15) << 2;
        float4 v = *reinterpret_cast<const float4*>(
            &x[((size_t)b * PC + c0 + r) * PN + n0 + col4]);
        ts[r][col4 + 0] = v.x; ts[r][col4 + 1] = v.y;
        ts[r][col4 + 2] = v.z; ts[r][col4 + 3] = v.w;
    }
    __syncthreads();
#pragma unroll
    for (int i = 0; i < 8; i++) {
        int e2 = tid + i * 256;                 // 2048 bf16-pairs
        int n_ = e2 >> 5, cp = (e2 & 31) << 1;
        float v0 = ts[cp][n_], v1 = ts[cp + 1][n_];
        unsigned h0 = bf16_rn(v0), h1 = bf16_rn(v1);
        unsigned l0 = bf16_rn(v0 - bf16_tof(h0));
        unsigned l1 = bf16_rn(v1 - bf16_tof(h1));
        u32 hi = (h1 << 16) | h0, lo = (l1 << 16) | l0;
        size_t base = ((size_t)b * PN + n0 + n_) * KX + c0 + cp;
        *reinterpret_cast<u32*>(&g_xx[base])       = hi;
        *reinterpret_cast<u32*>(&g_xx[base + 256]) = lo;
        *reinterpret_cast<u32*>(&g_xx[base + 512]) = hi;
    }
}

// ---------------- K1: per-pixel inverse channel norm ----------------
__global__ void k_invnorm(const float* __restrict__ x) {
    int p = blockIdx.x * 256 + threadIdx.x;
    int b = blockIdx.y;
    const float* xp = x + (size_t)b * PC * PN + p;
    float s0 = 0.f, s1 = 0.f, s2 = 0.f, s3 = 0.f;
#pragma unroll
    for (int c = 0; c < PC; c += 4) {
        float v0 = xp[(size_t)(c + 0) * PN];
        float v1 = xp[(size_t)(c + 1) * PN];
        float v2 = xp[(size_t)(c + 2) * PN];
        float v3 = xp[(size_t)(c + 3) * PN];
        s0 += v0 * v0; s1 += v1 * v1; s2 += v2 * v2; s3 += v3 * v3;
    }
    float s = (s0 + s1) + (s2 + s3);
    g_invn[b * PN + p] = 1.0f / fmaxf(sqrtf(s), 1e-12f);
}

// ---------------- K2: qkv GEMM on HMMA (mma.sync bf16, K'=768) ----------------
// CTA: D[128 m x 128 n]; 8 warps in 4(m) x 2(n); warp tile 32x64; KC=64 chunks.
__global__ void __launch_bounds__(256, 2) k_qkv_mma() {
    __shared__ __align__(16) unsigned short Asm[128 * 64];   // SW128-swizzled [m][k]
    __shared__ __align__(16) unsigned short Bsm[128 * 64];   // SW128-swizzled [n][k]
    __shared__ float inv_s[128];
    int tid = threadIdx.x, lane = tid & 31, wid = tid >> 5;
    int nb = blockIdx.x * 128, mb = blockIdx.y * 128, b = blockIdx.z;
    if (tid < 128) inv_s[tid] = g_invn[b * PN + nb + tid];
    int wm = (wid & 3) * 32, wn = (wid >> 2) * 64;
    u32 a_base = smem_u32(Asm), b_base = smem_u32(Bsm);

    float acc[2][8][4];
#pragma unroll
    for (int im = 0; im < 2; im++)
#pragma unroll
        for (int jn = 0; jn < 8; jn++)
#pragma unroll
            for (int q = 0; q < 4; q++) acc[im][jn][q] = 0.0f;

    // precomputed swizzled ldmatrix offsets (per lane)
    u32 a_off[2], b_off[4];
#pragma unroll
    for (int im = 0; im < 2; im++) {
        int arow = wm + im * 16 + (lane & 15);
        u32 bo = (u32)(arow * 128) + ((lane >> 4) << 4);
        a_off[im] = bo ^ ((bo >> 3) & 0x70);
    }
#pragma unroll
    for (int j2 = 0; j2 < 4; j2++) {
        int nrow = wn + j2 * 16 + ((lane >> 4) << 3) + (lane & 7);
        u32 bo = (u32)(nrow * 128) + (((lane >> 3) & 1) << 4);
        b_off[j2] = bo ^ ((bo >> 3) & 0x70);
    }

    for (int ch = 0; ch < 12; ch++) {
        // stage tiles: 128 rows x 64 bf16 (=128B rows), SW128 swizzle
#pragma unroll
        for (int i = 0; i < 4; i++) {
            int u = tid + i * 256;                // 1024 uint4 per array
            int r = u >> 3, c8 = (u & 7) << 3;
            u32 bo = (u32)((r << 7) + (c8 << 1));
            bo ^= (bo >> 3) & 0x70;
            *reinterpret_cast<uint4*>((char*)Asm + bo) =
                *reinterpret_cast<const uint4*>(&g_wx[(size_t)(mb + r) * KX + ch * 64 + c8]);
            *reinterpret_cast<uint4*>((char*)Bsm + bo) =
                *reinterpret_cast<const uint4*>(&g_xx[((size_t)b * PN + nb + r) * KX + ch * 64 + c8]);
        }
        __syncthreads();
#pragma unroll
        for (int kk = 0; kk < 4; kk++) {
            // swizzle XORs bytes 4-6 with row%8; kk*32 has bits 5-6 -> include in XOR input.
            // a_off/b_off already swizzled for kk=0; adding kk*32 must re-swizzle bits:
            // (bo + kk*32) swizzle differs; recompute cheaply: kk*32 only touches bits 5,6
            // which are part of the XOR *input* only via (bo>>3)&0x70 -> bits 7-9 (row). So
            // adding kk*32 to the *unswizzled* offset == XOR kk*32 onto swizzled offset
            // (bits 5-6 not in XOR mask 0x70, and no carry into bit 7 since base bits5-6=0).
            u32 kadd = (u32)(kk * 32);
            u32 a[2][4];
            ldsm4(a[0], a_base + (a_off[0] ^ kadd));
            ldsm4(a[1], a_base + (a_off[1] ^ kadd));
            u32 bf[8][2];
#pragma unroll
            for (int j2 = 0; j2 < 4; j2++) {
                u32 r4[4];
                ldsm4(r4, b_base + (b_off[j2] ^ kadd));
                bf[2 * j2][0] = r4[0]; bf[2 * j2][1] = r4[1];
                bf[2 * j2 + 1][0] = r4[2]; bf[2 * j2 + 1][1] = r4[3];
            }
#pragma unroll
            for (int im = 0; im < 2; im++)
#pragma unroll
                for (int jn = 0; jn < 8; jn++)
                    mma16816(acc[im][jn], a[im], bf[jn]);
        }
        __syncthreads();
    }

    // epilogue: scale by invn(col), store float2 per atom-half
    int r0 = wm + (lane >> 2);
    int cb = wn + (lane & 3) * 2;
#pragma unroll
    for (int im = 0; im < 2; im++) {
#pragma unroll
        for (int jn = 0; jn < 8; jn++) {
            int c = cb + jn * 8;
            float ivx = inv_s[c], ivy = inv_s[c + 1];
            size_t rowA = (size_t)b * QROWS + mb + r0 + im * 16;
            float2 v0 = {acc[im][jn][0] * ivx, acc[im][jn][1] * ivy};
            float2 v1 = {acc[im][jn][2] * ivx, acc[im][jn][3] * ivy};
            *reinterpret_cast<float2*>(&g_qkv[rowA * PN + nb + c]) = v0;
            *reinterpret_cast<float2*>(&g_qkv[(rowA + 8) * PN + nb + c]) = v1;
        }
    }
}

// ---------------- K3a: k row softmax stats ----------------
__global__ void k_kstats(const float* __restrict__ mem_kv) {
    int gwarp = (blockIdx.x * blockDim.x + threadIdx.x) >> 5;
    int lane = threadIdx.x & 31;
    if (gwarp >= PB * PNH * PHD) return;
    int d = gwarp & 31, h = (gwarp >> 5) & 3, b = gwarp >> 7;
    const float* krow = &g_qkv[((size_t)b * QROWS + PHID + h * PHD + d) * PN];

    float m0 = -1e30f, m1 = -1e30f, m2 = -1e30f, m3 = -1e30f;
    for (int p = lane; p < PN; p += 128) {
        m0 = fmaxf(m0, krow[p]);
        m1 = fmaxf(m1, krow[p + 32]);
        m2 = fmaxf(m2, krow[p + 64]);
        m3 = fmaxf(m3, krow[p + 96]);
    }
    float m = fmaxf(fmaxf(m0, m1), fmaxf(m2, m3));
    if (lane < PNM)
        m = fmaxf(m, mem_kv[((0 * PNH + h) * PHD + d) * PNM + lane]);
#pragma unroll
    for (int o = 16; o > 0; o >>= 1)
        m = fmaxf(m, __shfl_xor_sync(0xffffffffu, m, o));

    float s0 = 0.f, s1 = 0.f, s2 = 0.f, s3 = 0.f;
    for (int p = lane; p < PN; p += 128) {
        s0 += __expf(krow[p] - m);
        s1 += __expf(krow[p + 32] - m);
        s2 += __expf(krow[p + 64] - m);
        s3 += __expf(krow[p + 96] - m);
    }
    float s = (s0 + s1) + (s2 + s3);
    if (lane < PNM)
        s += __expf(mem_kv[((0 * PNH + h) * PHD + d) * PNM + lane] - m);
#pragma unroll
    for (int o = 16; o > 0; o >>= 1)
        s += __shfl_xor_sync(0xffffffffu, s, o);
    if (lane == 0) { g_stat[0][gwarp] = m; g_stat[1][gwarp] = 1.0f / s; }
}

// ---------------- K3b: partial context ----------------
__global__ void k_context(const float* __restrict__ mem_kv) {
    __shared__ float Ks[PHD][68];
    __shared__ float Vt[64][34];
    __shared__ float rmax[PHD], rinv[PHD];
    int tc = blockIdx.x, h = blockIdx.y, b = blockIdx.z;
    int tid = threadIdx.x;
    if (tid < PHD) {
        int rowid = (b * PNH + h) * PHD + tid;
        rmax[tid] = g_stat[0][rowid];
        rinv[tid] = g_stat[1][rowid];
    }
    __syncthreads();
    int d = tid >> 3;
    int eg = (tid & 7) << 2;
    float macc[4] = {0.f, 0.f, 0.f, 0.f};
    if (tc == 0) {
#pragma unroll
        for (int m = 0; m < PNM; m++) {
            float kv = __expf(mem_kv[((0 * PNH + h) * PHD + d) * PNM + m] - rmax[d]) * rinv[d];
#pragma unroll
            for (int i = 0; i < 4; i++)
                macc[i] += kv * mem_kv[((1 * PNH + h) * PHD + eg + i) * PNM + m];
        }
    }
    u64 accp[2] = {0ull, 0ull};
    int pbase = tc * 512;
    for (int t = 0; t < 8; t++) {
        int p0 = pbase + t * 64;
#pragma unroll
        for (int i = 0; i < 2; i++) {
            int f4 = tid + i * 256;
            int r = f4 >> 4, c4 = (f4 & 15) << 2;
            float4 v = *reinterpret_cast<const float4*>(
                &g_qkv[((size_t)b * QROWS + PHID + h * PHD + r) * PN + p0 + c4]);
            float mx = rmax[r], ri = rinv[r];
            Ks[r][c4 + 0] = __expf(v.x - mx) * ri;
            Ks[r][c4 + 1] = __expf(v.y - mx) * ri;
            Ks[r][c4 + 2] = __expf(v.z - mx) * ri;
            Ks[r][c4 + 3] = __expf(v.w - mx) * ri;
        }
#pragma unroll
        for (int i = 0; i < 2; i++) {
            int f4 = tid + i * 256;
            int r = f4 >> 4, c4 = (f4 & 15) << 2;
            float4 v = *reinterpret_cast<const float4*>(
                &g_qkv[((size_t)b * QROWS + 2 * PHID + h * PHD + r) * PN + p0 + c4]);
            Vt[c4 + 0][r] = v.x; Vt[c4 + 1][r] = v.y;
            Vt[c4 + 2][r] = v.z; Vt[c4 + 3][r] = v.w;
        }
        __syncthreads();
#pragma unroll
        for (int n = 0; n < 64; n++) {
            u64 kv2 = pack2(Ks[d][n], Ks[d][n]);
            u64 v0 = *reinterpret_cast<const u64*>(&Vt[n][eg]);
            u64 v1 = *reinterpret_cast<const u64*>(&Vt[n][eg + 2]);
            accp[0] = fma2(kv2, v0, accp[0]);
            accp[1] = fma2(kv2, v1, accp[1]);
        }
        __syncthreads();
    }
    size_t base = ((size_t)(b * PNH + h) * PHD + d) * PHD + eg;
    float2 p0 = unpack2(accp[0]);
    float2 p1 = unpack2(accp[1]);
    g_ctxp[tc][base + 0] = p0.x + macc[0];
    g_ctxp[tc][base + 1] = p0.y + macc[1];
    g_ctxp[tc][base + 2] = p1.x + macc[2];
    g_ctxp[tc][base + 3] = p1.y + macc[3];
}

// ---------------- K4: reduce partial contexts + fold M = w_out . ctx ----------------
__global__ void k_fold(const float* __restrict__ w_out) {
    __shared__ float ctx[PNH * PHD * PHD];
    int b = blockIdx.x;
    int tid = threadIdx.x;
    for (int idx = tid; idx < PNH * PHD * PHD; idx += 256) {
        float s = 0.0f;
#pragma unroll
        for (int tc = 0; tc < 8; tc++) s += g_ctxp[tc][b * (PNH * PHD * PHD) + idx];
        ctx[idx] = s;
    }
    __syncthreads();
    int o = tid;
    for (int h = 0; h < PNH; h++) {
        float w[PHD];
#pragma unroll
        for (int e = 0; e < PHD; e++) w[e] = w_out[o * PHID + h * PHD + e];
        for (int dd = 0; dd < PHD; dd++) {
            float s = 0.0f;
#pragma unroll
            for (int e = 0; e < PHD; e++) s += w[e] * ctx[(h * PHD + dd) * PHD + e];
            g_M[((size_t)b * PC + o) * PHID + h * PHD + dd] = s;
        }
    }
}

// ---------------- K5: fused q-softmax + output GEMM + bias + final RMS norm ----------------
__global__ void k_out(const float* __restrict__ b_out,
                      const float* __restrict__ g_out,
                      float* __restrict__ out) {
    __shared__ float Qs[PHID][33];
    __shared__ float As[16][260];
    __shared__ float red[32][32];
    __shared__ float invr[32];
    int pb = blockIdx.x * 32;
    int b = blockIdx.y;
    int tid = threadIdx.x;

#pragma unroll
    for (int i = 0; i < 4; i++) {
        int f4 = tid + i * 256;
        int r = f4 >> 3, c4 = (f4 & 7) << 2;
        float4 v = *reinterpret_cast<const float4*>(
            &g_qkv[((size_t)b * QROWS + r) * PN + pb + c4]);
        Qs[r][c4 + 0] = v.x; Qs[r][c4 + 1] = v.y;
        Qs[r][c4 + 2] = v.z; Qs[r][c4 + 3] = v.w;
    }
    __syncthreads();

    if (tid < 128) {
        int p = tid & 31, h = tid >> 5;
        float m = -1e30f;
#pragma unroll
        for (int dd = 0; dd < PHD; dd++) m = fmaxf(m, Qs[h * PHD + dd][p]);
        float e[PHD];
        float s = 0.0f;
#pragma unroll
        for (int dd = 0; dd < PHD; dd++) { e[dd] = __expf(Qs[h * PHD + dd][p] - m); s += e[dd]; }
        float inv = 0.17677669529663687f / s;
#pragma unroll
        for (int dd = 0; dd < PHD; dd++) Qs[h * PHD + dd][p] = e[dd] * inv;
    }
    __syncthreads();

    int rg = tid >> 3, cg = tid & 7;
    int o0 = rg * 8, p0 = cg * 4;
    u64 accp[4][4];
#pragma unroll
    for (int i = 0; i < 4; i++)
#pragma unroll
        for (int j = 0; j < 4; j++) accp[i][j] = 0ull;

    for (int kb = 0; kb < PHID; kb += 16) {
#pragma unroll
        for (int i = 0; i < 4; i++) {
            int f4 = tid + i * 256;
            int r = f4 >> 2, c4 = (f4 & 3) << 2;
            float4 v = *reinterpret_cast<const float4*>(
                &g_M[((size_t)b * PC + r) * PHID + kb + c4]);
            As[c4 + 0][r] = v.x; As[c4 + 1][r] = v.y;
            As[c4 + 2][r] = v.z; As[c4 + 3][r] = v.w;
        }
        __syncthreads();
#pragma unroll
        for (int k = 0; k < 16; k++) {
            ulonglong2 a01 = *reinterpret_cast<const ulonglong2*>(&As[k][o0]);
            ulonglong2 a23 = *reinterpret_cast<const ulonglong2*>(&As[k][o0 + 4]);
            u64 ap[4] = {a01.x, a01.y, a23.x, a23.y};
#pragma unroll
            for (int j = 0; j < 4; j++) {
                float qv = Qs[kb + k][p0 + j];
                u64 qd = pack2(qv, qv);
#pragma unroll
                for (int i = 0; i < 4; i++) accp[i][j] = fma2(ap[i], qd, accp[i][j]);
            }
        }
        __syncthreads();
    }

    float acc[8][4];
#pragma unroll
    for (int i2 = 0; i2 < 4; i2++)
#pragma unroll
        for (int j = 0; j < 4; j++) {
            float2 p = unpack2(accp[i2][j]);
            acc[2 * i2][j] = p.x;
            acc[2 * i2 + 1][j] = p.y;
        }

    float sq[4] = {0.f, 0.f, 0.f, 0.f};
#pragma unroll
    for (int i = 0; i < 8; i++) {
        float bo = b_out[o0 + i];
#pragma unroll
        for (int j = 0; j < 4; j++) {
            acc[i][j] += bo;
            sq[j] += acc[i][j] * acc[i][j];
        }
    }
#pragma unroll
    for (int j = 0; j < 4; j++) red[rg][p0 + j] = sq[j];
    __syncthreads();
    if (tid < 32) {
        float s = 0.0f;
#pragma unroll
        for (int r = 0; r < 32; r++) s += red[r][tid];
        invr[tid] = 16.0f / fmaxf(sqrtf(s), 1e-12f);
    }
    __syncthreads();

    float iv[4];
#pragma unroll
    for (int j = 0; j < 4; j++) iv[j] = invr[p0 + j];
#pragma unroll
    for (int i = 0; i < 8; i++) {
        float go = g_out[o0 + i];
        float4 v;
        v.x = acc[i][0] * iv[0] * go;
        v.y = acc[i][1] * iv[1] * go;
        v.z = acc[i][2] * iv[2] * go;
        v.w = acc[i][3] * iv[3] * go;
        *reinterpret_cast<float4*>(
            &out[((size_t)(b * PC + o0 + i)) * PN + pb + p0]) = v;
    }
}

// ---------------- launch ----------------
extern "C" void kernel_launch(void* const* d_in, const int* in_sizes, int n_in,
                              void* d_out, int out_size) {
    const float* x      = (const float*)d_in[0];
    const float* g_in   = (const float*)d_in[1];
    const float* mem_kv = (const float*)d_in[2];
    const float* w_qkv  = (const float*)d_in[3];
    const float* w_out  = (const float*)d_in[4];
    const float* b_out  = (const float*)d_in[5];
    const float* g_out  = (const float*)d_in[6];
    float* out = (float*)d_out;

    k_convw  <<<QROWS, 256>>>(w_qkv, g_in);
    k_invnorm<<<dim3(PN / 256, PB), 256>>>(x);
    k_convx  <<<dim3(PN / 64, PC / 64, PB), 256>>>(x);
    k_qkv_mma<<<dim3(PN / 128, QROWS / 128, PB), 256>>>();
    k_kstats <<<512, 128>>>(mem_kv);
    k_context<<<dim3(8, PNH, PB), 256>>>(mem_kv);
    k_fold   <<<PB, 256>>>(w_out);
    k_out    <<<dim3(PN / 32, PB), 256>>>(b_out, g_out, out);
}

// round 10
// speedup vs baseline: 1.5431x; 1.1154x over previous
#include <cuda_runtime.h>
#include <math.h>
#include <stdint.h>

// Problem constants
#define PB   16      // batch
#define PC   256     // channels
#define PN   4096    // H*W
#define PNH  4       // heads
#define PHD  32      // head dim
#define PNM  4       // memory tokens
#define PHID 128     // NH*HD
#define QROWS 384    // 3*HID
#define KX   768     // expanded K = 3*PC  (AhBh + AhBl + AlBh)

typedef unsigned long long u64;
typedef unsigned int u32;

// ---------------- scratch (static device memory; no allocation) ----------------
__device__ unsigned short g_wx[QROWS * KX];            // A' = [Ah, Ah, Al] per row
__device__ unsigned short g_xx[(size_t)PB * PN * KX];  // B' = [Bh, Bl, Bh] per pixel (~100 MB)
__device__ float g_invn[PB * PN];                      // 1/||x||_C per pixel
__device__ float g_qkv[(size_t)PB * QROWS * PN];       // qkv activations (~100 MB)
__device__ float g_stat[2][PB * PNH * PHD];            // k softmax: rowmax, 1/rowsum
__device__ float g_ctxp[8][PB * PNH * PHD * PHD];      // partial contexts (8 token chunks)
__device__ unsigned short g_Mh[PB * PC * PHID];        // folded M = w_out . ctx, bf16 hi
__device__ unsigned short g_Ml[PB * PC * PHID];        // bf16 lo

// ---------------- small helpers ----------------
__device__ __forceinline__ unsigned bf16_rn(float v) {
    unsigned u = __float_as_uint(v);
    return (u + 0x7FFFu + ((u >> 16) & 1u)) >> 16;
}
__device__ __forceinline__ float bf16_tof(unsigned b) { return __uint_as_float(b << 16); }

__device__ __forceinline__ u32 smem_u32(const void* p) {
    u32 a;
    asm("{ .reg .u64 t; cvta.to.shared.u64 t, %1; cvt.u32.u64 %0, t; }" : "=r"(a) : "l"(p));
    return a;
}

// f32x2 packed helpers (k_context)
__device__ __forceinline__ u64 fma2(u64 a, u64 b, u64 c) {
    u64 d; asm("fma.rn.f32x2 %0, %1, %2, %3;" : "=l"(d) : "l"(a), "l"(b), "l"(c)); return d;
}
__device__ __forceinline__ u64 pack2(float lo, float hi) {
    u64 r; asm("mov.b64 %0, {%1, %2};" : "=l"(r) : "f"(lo), "f"(hi)); return r;
}
__device__ __forceinline__ float2 unpack2(u64 v) {
    float2 r; asm("mov.b64 {%0, %1}, %2;" : "=f"(r.x), "=f"(r.y) : "l"(v)); return r;
}

// ---------------- HMMA helpers (baseline ISA: ldmatrix + mma.sync + cp.async) ----------------
__device__ __forceinline__ void ldsm4(u32* r, u32 addr) {
    asm volatile("ldmatrix.sync.aligned.m8n8.x4.shared.b16 {%0,%1,%2,%3}, [%4];"
                 : "=r"(r[0]), "=r"(r[1]), "=r"(r[2]), "=r"(r[3]) : "r"(addr));
}
__device__ __forceinline__ void mma16816(float* d, const u32* a, const u32* b) {
    asm volatile(
        "mma.sync.aligned.m16n8k16.row.col.f32.bf16.bf16.f32 "
        "{%0,%1,%2,%3}, {%4,%5,%6,%7}, {%8,%9}, {%0,%1,%2,%3};"
        : "+f"(d[0]), "+f"(d[1]), "+f"(d[2]), "+f"(d[3])
        : "r"(a[0]), "r"(a[1]), "r"(a[2]), "r"(a[3]), "r"(b[0]), "r"(b[1]));
}
__device__ __forceinline__ void cpa16(u32 dst, const void* src) {
    asm volatile("cp.async.ca.shared.global [%0], [%1], 16;" :: "r"(dst), "l"(src));
}
__device__ __forceinline__ void cpa_commit() {
    asm volatile("cp.async.commit_group;" ::: "memory");
}
__device__ __forceinline__ void cpa_wait1() {
    asm volatile("cp.async.wait_group 1;" ::: "memory");
}
__device__ __forceinline__ void cpa_wait0() {
    asm volatile("cp.async.wait_group 0;" ::: "memory");
}

// ---------------- K0a: weight convert  A' = [Ah, Ah, Al] of (w_qkv * g_in * sqrt(C)) ----------------
__global__ void k_convw(const float* __restrict__ w_qkv, const float* __restrict__ g_in) {
    int i = blockIdx.x * 256 + threadIdx.x;    // i = row*256 + c
    if (i < QROWS * PC) {
        int row = i >> 8, c = i & 255;
        float v = w_qkv[i] * g_in[c] * 16.0f;  // sqrt(256) = 16
        unsigned hb = bf16_rn(v);
        unsigned lb = bf16_rn(v - bf16_tof(hb));
        g_wx[row * KX + c]       = (unsigned short)hb;
        g_wx[row * KX + 256 + c] = (unsigned short)hb;
        g_wx[row * KX + 512 + c] = (unsigned short)lb;
    }
}

// ---------------- K0b: x transpose + split:  [b][c][n] -> B'[b][n][768] = [Bh, Bl, Bh] ----------------
__global__ void k_convx(const float* __restrict__ x) {
    __shared__ float ts[64][65];
    int n0 = blockIdx.x * 64, c0 = blockIdx.y * 64, b = blockIdx.z;
    int tid = threadIdx.x;
#pragma unroll
    for (int i = 0; i < 4; i++) {
        int f4 = tid + i * 256;                 // 1024 float4
        int r = f4 >> 4, col4 = (f4 & 15) << 2;
        float4 v = *reinterpret_cast<const float4*>(
            &x[((size_t)b * PC + c0 + r) * PN + n0 + col4]);
        ts[r][col4 + 0] = v.x; ts[r][col4 + 1] = v.y;
        ts[r][col4 + 2] = v.z; ts[r][col4 + 3] = v.w;
    }
    __syncthreads();
#pragma unroll
    for (int i = 0; i < 8; i++) {
        int e2 = tid + i * 256;                 // 2048 bf16-pairs
        int n_ = e2 >> 5, cp = (e2 & 31) << 1;
        float v0 = ts[cp][n_], v1 = ts[cp + 1][n_];
        unsigned h0 = bf16_rn(v0), h1 = bf16_rn(v1);
        unsigned l0 = bf16_rn(v0 - bf16_tof(h0));
        unsigned l1 = bf16_rn(v1 - bf16_tof(h1));
        u32 hi = (h1 << 16) | h0, lo = (l1 << 16) | l0;
        size_t base = ((size_t)b * PN + n0 + n_) * KX + c0 + cp;
        *reinterpret_cast<u32*>(&g_xx[base])       = hi;
        *reinterpret_cast<u32*>(&g_xx[base + 256]) = lo;
        *reinterpret_cast<u32*>(&g_xx[base + 512]) = hi;
    }
}

// ---------------- K1: per-pixel inverse channel norm ----------------
__global__ void k_invnorm(const float* __restrict__ x) {
    int p = blockIdx.x * 256 + threadIdx.x;
    int b = blockIdx.y;
    const float* xp = x + (size_t)b * PC * PN + p;
    float s0 = 0.f, s1 = 0.f, s2 = 0.f, s3 = 0.f;
#pragma unroll
    for (int c = 0; c < PC; c += 4) {
        float v0 = xp[(size_t)(c + 0) * PN];
        float v1 = xp[(size_t)(c + 1) * PN];
        float v2 = xp[(size_t)(c + 2) * PN];
        float v3 = xp[(size_t)(c + 3) * PN];
        s0 += v0 * v0; s1 += v1 * v1; s2 += v2 * v2; s3 += v3 * v3;
    }
    float s = (s0 + s1) + (s2 + s3);
    g_invn[b * PN + p] = 1.0f / fmaxf(sqrtf(s), 1e-12f);
}

// ---------------- K2: qkv GEMM on HMMA, cp.async double-buffered ----------------
// CTA: D[128 m x 128 n]; 8 warps 4(m)x2(n); warp tile 32x64; 12 K-chunks of 64.
// dyn smem: A0 @0, A1 @16384, B0 @32768, B1 @49152, inv @65536 (512B) -> 66048 B
#define QKV_SMEM 66048
__global__ void __launch_bounds__(256, 2) k_qkv_mma() {
    extern __shared__ char dyn[];
    u32 base = smem_u32(dyn);
    float* inv_s = reinterpret_cast<float*>(dyn + 65536);
    int tid = threadIdx.x, lane = tid & 31, wid = tid >> 5;
    int nb = blockIdx.x * 128, mb = blockIdx.y * 128, b = blockIdx.z;
    if (tid < 128) inv_s[tid] = g_invn[b * PN + nb + tid];
    int wm = (wid & 3) * 32, wn = (wid >> 2) * 64;

    float acc[2][8][4];
#pragma unroll
    for (int im = 0; im < 2; im++)
#pragma unroll
        for (int jn = 0; jn < 8; jn++)
#pragma unroll
            for (int q = 0; q < 4; q++) acc[im][jn][q] = 0.0f;

    // per-lane staging addresses (swizzled), per thread: 4 rows
    u32 st_bo[4];
    int st_r[4], st_c8[4];
#pragma unroll
    for (int i = 0; i < 4; i++) {
        int u = tid + i * 256;
        st_r[i] = u >> 3; st_c8[i] = (u & 7) << 3;
        u32 bo = (u32)((st_r[i] << 7) + (st_c8[i] << 1));
        st_bo[i] = bo ^ ((bo >> 3) & 0x70);
    }
    // ldmatrix offsets (swizzled, for kk=0)
    u32 a_off[2], b_off[4];
#pragma unroll
    for (int im = 0; im < 2; im++) {
        int arow = wm + im * 16 + (lane & 15);
        u32 bo = (u32)(arow * 128) + ((lane >> 4) << 4);
        a_off[im] = bo ^ ((bo >> 3) & 0x70);
    }
#pragma unroll
    for (int j2 = 0; j2 < 4; j2++) {
        int nrow = wn + j2 * 16 + ((lane >> 4) << 3) + (lane & 7);
        u32 bo = (u32)(nrow * 128) + (((lane >> 3) & 1) << 4);
        b_off[j2] = bo ^ ((bo >> 3) & 0x70);
    }

    // prologue: stage chunk 0 into buffer 0
#pragma unroll
    for (int i = 0; i < 4; i++) {
        cpa16(base + st_bo[i],
              &g_wx[(size_t)(mb + st_r[i]) * KX + st_c8[i]]);
        cpa16(base + 32768 + st_bo[i],
              &g_xx[((size_t)b * PN + nb + st_r[i]) * KX + st_c8[i]]);
    }
    cpa_commit();

    for (int ch = 0; ch < 12; ch++) {
        if (ch < 11) {
            u32 sb = (u32)(((ch + 1) & 1) * 16384);
#pragma unroll
            for (int i = 0; i < 4; i++) {
                cpa16(base + sb + st_bo[i],
                      &g_wx[(size_t)(mb + st_r[i]) * KX + (ch + 1) * 64 + st_c8[i]]);
                cpa16(base + 32768 + sb + st_bo[i],
                      &g_xx[((size_t)b * PN + nb + st_r[i]) * KX + (ch + 1) * 64 + st_c8[i]]);
            }
            cpa_commit();
            cpa_wait1();
        } else {
            cpa_wait0();
        }
        __syncthreads();
        u32 aU = base + (u32)((ch & 1) * 16384);
        u32 bU = base + 32768 + (u32)((ch & 1) * 16384);
#pragma unroll
        for (int kk = 0; kk < 4; kk++) {
            u32 kadd = (u32)(kk * 32);   // XOR-safe (bits 5-6 outside swizzle mask, no carry)
            u32 a[2][4];
            ldsm4(a[0], aU + (a_off[0] ^ kadd));
            ldsm4(a[1], aU + (a_off[1] ^ kadd));
            u32 bf[8][2];
#pragma unroll
            for (int j2 = 0; j2 < 4; j2++) {
                u32 r4[4];
                ldsm4(r4, bU + (b_off[j2] ^ kadd));
                bf[2 * j2][0] = r4[0]; bf[2 * j2][1] = r4[1];
                bf[2 * j2 + 1][0] = r4[2]; bf[2 * j2 + 1][1] = r4[3];
            }
#pragma unroll
            for (int im = 0; im < 2; im++)
#pragma unroll
                for (int jn = 0; jn < 8; jn++)
                    mma16816(acc[im][jn], a[im], bf[jn]);
        }
        __syncthreads();
    }

    // epilogue: scale by invn(col), store float2 per atom-half
    int r0 = wm + (lane >> 2);
    int cb = wn + (lane & 3) * 2;
#pragma unroll
    for (int im = 0; im < 2; im++) {
#pragma unroll
        for (int jn = 0; jn < 8; jn++) {
            int c = cb + jn * 8;
            float ivx = inv_s[c], ivy = inv_s[c + 1];
            size_t rowA = (size_t)b * QROWS + mb + r0 + im * 16;
            float2 v0 = {acc[im][jn][0] * ivx, acc[im][jn][1] * ivy};
            float2 v1 = {acc[im][jn][2] * ivx, acc[im][jn][3] * ivy};
            *reinterpret_cast<float2*>(&g_qkv[rowA * PN + nb + c]) = v0;
            *reinterpret_cast<float2*>(&g_qkv[(rowA + 8) * PN + nb + c]) = v1;
        }
    }
}

// ---------------- K3a: k row softmax stats ----------------
__global__ void k_kstats(const float* __restrict__ mem_kv) {
    int gwarp = (blockIdx.x * blockDim.x + threadIdx.x) >> 5;
    int lane = threadIdx.x & 31;
    if (gwarp >= PB * PNH * PHD) return;
    int d = gwarp & 31, h = (gwarp >> 5) & 3, b = gwarp >> 7;
    const float* krow = &g_qkv[((size_t)b * QROWS + PHID + h * PHD + d) * PN];

    float m0 = -1e30f, m1 = -1e30f, m2 = -1e30f, m3 = -1e30f;
    for (int p = lane; p < PN; p += 128) {
        m0 = fmaxf(m0, krow[p]);
        m1 = fmaxf(m1, krow[p + 32]);
        m2 = fmaxf(m2, krow[p + 64]);
        m3 = fmaxf(m3, krow[p + 96]);
    }
    float m = fmaxf(fmaxf(m0, m1), fmaxf(m2, m3));
    if (lane < PNM)
        m = fmaxf(m, mem_kv[((0 * PNH + h) * PHD + d) * PNM + lane]);
#pragma unroll
    for (int o = 16; o > 0; o >>= 1)
        m = fmaxf(m, __shfl_xor_sync(0xffffffffu, m, o));

    float s0 = 0.f, s1 = 0.f, s2 = 0.f, s3 = 0.f;
    for (int p = lane; p < PN; p += 128) {
        s0 += __expf(krow[p] - m);
        s1 += __expf(krow[p + 32] - m);
        s2 += __expf(krow[p + 64] - m);
        s3 += __expf(krow[p + 96] - m);
    }
    float s = (s0 + s1) + (s2 + s3);
    if (lane < PNM)
        s += __expf(mem_kv[((0 * PNH + h) * PHD + d) * PNM + lane] - m);
#pragma unroll
    for (int o = 16; o > 0; o >>= 1)
        s += __shfl_xor_sync(0xffffffffu, s, o);
    if (lane == 0) { g_stat[0][gwarp] = m; g_stat[1][gwarp] = 1.0f / s; }
}

// ---------------- K3b: partial context ----------------
__global__ void k_context(const float* __restrict__ mem_kv) {
    __shared__ float Ks[PHD][68];
    __shared__ float Vt[64][34];
    __shared__ float rmax[PHD], rinv[PHD];
    int tc = blockIdx.x, h = blockIdx.y, b = blockIdx.z;
    int tid = threadIdx.x;
    if (tid < PHD) {
        int rowid = (b * PNH + h) * PHD + tid;
        rmax[tid] = g_stat[0][rowid];
        rinv[tid] = g_stat[1][rowid];
    }
    __syncthreads();
    int d = tid >> 3;
    int eg = (tid & 7) << 2;
    float macc[4] = {0.f, 0.f, 0.f, 0.f};
    if (tc == 0) {
#pragma unroll
        for (int m = 0; m < PNM; m++) {
            float kv = __expf(mem_kv[((0 * PNH + h) * PHD + d) * PNM + m] - rmax[d]) * rinv[d];
#pragma unroll
            for (int i = 0; i < 4; i++)
                macc[i] += kv * mem_kv[((1 * PNH + h) * PHD + eg + i) * PNM + m];
        }
    }
    u64 accp[2] = {0ull, 0ull};
    int pbase = tc * 512;
    for (int t = 0; t < 8; t++) {
        int p0 = pbase + t * 64;
#pragma unroll
        for (int i = 0; i < 2; i++) {
            int f4 = tid + i * 256;
            int r = f4 >> 4, c4 = (f4 & 15) << 2;
            float4 v = *reinterpret_cast<const float4*>(
                &g_qkv[((size_t)b * QROWS + PHID + h * PHD + r) * PN + p0 + c4]);
            float mx = rmax[r], ri = rinv[r];
            Ks[r][c4 + 0] = __expf(v.x - mx) * ri;
            Ks[r][c4 + 1] = __expf(v.y - mx) * ri;
            Ks[r][c4 + 2] = __expf(v.z - mx) * ri;
            Ks[r][c4 + 3] = __expf(v.w - mx) * ri;
        }
#pragma unroll
        for (int i = 0; i < 2; i++) {
            int f4 = tid + i * 256;
            int r = f4 >> 4, c4 = (f4 & 15) << 2;
            float4 v = *reinterpret_cast<const float4*>(
                &g_qkv[((size_t)b * QROWS + 2 * PHID + h * PHD + r) * PN + p0 + c4]);
            Vt[c4 + 0][r] = v.x; Vt[c4 + 1][r] = v.y;
            Vt[c4 + 2][r] = v.z; Vt[c4 + 3][r] = v.w;
        }
        __syncthreads();
#pragma unroll
        for (int n = 0; n < 64; n++) {
            u64 kv2 = pack2(Ks[d][n], Ks[d][n]);
            u64 v0 = *reinterpret_cast<const u64*>(&Vt[n][eg]);
            u64 v1 = *reinterpret_cast<const u64*>(&Vt[n][eg + 2]);
            accp[0] = fma2(kv2, v0, accp[0]);
            accp[1] = fma2(kv2, v1, accp[1]);
        }
        __syncthreads();
    }
    size_t base = ((size_t)(b * PNH + h) * PHD + d) * PHD + eg;
    float2 p0 = unpack2(accp[0]);
    float2 p1 = unpack2(accp[1]);
    g_ctxp[tc][base + 0] = p0.x + macc[0];
    g_ctxp[tc][base + 1] = p0.y + macc[1];
    g_ctxp[tc][base + 2] = p1.x + macc[2];
    g_ctxp[tc][base + 3] = p1.y + macc[3];
}

// ---------------- K4: reduce partials + fold M = w_out . ctx -> bf16 hi/lo ----------------
__global__ void k_fold(const float* __restrict__ w_out) {
    __shared__ float ctx[PNH * PHD * PHD];
    int b = blockIdx.x;
    int tid = threadIdx.x;
    for (int idx = tid; idx < PNH * PHD * PHD; idx += 256) {
        float s = 0.0f;
#pragma unroll
        for (int tc = 0; tc < 8; tc++) s += g_ctxp[tc][b * (PNH * PHD * PHD) + idx];
        ctx[idx] = s;
    }
    __syncthreads();
    int o = tid;
    for (int h = 0; h < PNH; h++) {
        float w[PHD];
#pragma unroll
        for (int e = 0; e < PHD; e++) w[e] = w_out[o * PHID + h * PHD + e];
        for (int dd = 0; dd < PHD; dd++) {
            float s = 0.0f;
#pragma unroll
            for (int e = 0; e < PHD; e++) s += w[e] * ctx[(h * PHD + dd) * PHD + e];
            unsigned hb = bf16_rn(s);
            unsigned lb = bf16_rn(s - bf16_tof(hb));
            int idx = (b * PC + o) * PHID + h * PHD + dd;
            g_Mh[idx] = (unsigned short)hb;
            g_Ml[idx] = (unsigned short)lb;
        }
    }
}

// ---------------- K5: fused q-softmax + output GEMM (HMMA) + bias + RMS norm ----------------
// CTA: o=256 (all channels) x p=64 pixels.  K' = 3 terms x 128 = 6 chunks of 64.
// dyn smem: Qh0 @0, Qh1 @8192, Ql0 @16384, Ql1 @24576, Mstage/qload @32768 (32KB),
//           red @65536 (4x64 f), invr @66560 (64 f)  -> 66816 B
#define OUT_SMEM 66816
__global__ void __launch_bounds__(256, 2) k_out_mma(
    const float* __restrict__ b_out,
    const float* __restrict__ g_out,
    float* __restrict__ out) {
    extern __shared__ char dyn[];
    u32 base = smem_u32(dyn);
    float* msf = reinterpret_cast<float*>(dyn + 32768);   // [128][64] f32 qload / M stage
    float* red = reinterpret_cast<float*>(dyn + 65536);   // [4][64]
    float* invr = reinterpret_cast<float*>(dyn + 66560);  // [64]
    int tid = threadIdx.x, lane = tid & 31, wid = tid >> 5;
    int p0 = blockIdx.x * 64, b = blockIdx.y;

    // --- load q f32 tile [128 rows][64 pixels] ---
#pragma unroll
    for (int i = 0; i < 8; i++) {
        int f4 = tid + i * 256;                 // 2048 float4
        int r = f4 >> 4, c4 = (f4 & 15) << 2;
        *reinterpret_cast<float4*>(&msf[r * 64 + c4]) =
            *reinterpret_cast<const float4*>(&g_qkv[((size_t)b * QROWS + r) * PN + p0 + c4]);
    }
    __syncthreads();

    // --- softmax over head_dim per (head, pixel); write bf16 hi/lo Q tiles ---
    {
        int p = tid & 63, h = tid >> 6;          // 4 heads x 64 pixels = 256 threads
        float e[PHD];
        float m = -1e30f;
#pragma unroll
        for (int dd = 0; dd < PHD; dd++) m = fmaxf(m, msf[(h * PHD + dd) * 64 + p]);
        float s = 0.0f;
#pragma unroll
        for (int dd = 0; dd < PHD; dd++) { e[dd] = __expf(msf[(h * PHD + dd) * 64 + p] - m); s += e[dd]; }
        float sc = 0.17677669529663687f / s;     // (1/sqrt(32)) / sumexp
        int kc = h >> 1;                          // K-half
        int klb = (h & 1) * 32;                   // k offset within half
        u32 qh_base = base + (u32)(kc * 8192);
        u32 ql_base = base + 16384u + (u32)(kc * 8192);
        __syncthreads();                          // all reads of msf done before Q writes? (Q separate; sync for msf reuse later only)
#pragma unroll
        for (int dd = 0; dd < PHD; dd += 2) {
            float v0 = e[dd] * sc, v1 = e[dd + 1] * sc;
            unsigned h0 = bf16_rn(v0), h1 = bf16_rn(v1);
            unsigned l0 = bf16_rn(v0 - bf16_tof(h0));
            unsigned l1 = bf16_rn(v1 - bf16_tof(h1));
            u32 bo = (u32)(p * 128 + (klb + dd) * 2);
            bo ^= (bo >> 3) & 0x70;
            *reinterpret_cast<u32*>(dyn + (qh_base - base) + bo) = (h1 << 16) | h0;
            *reinterpret_cast<u32*>(dyn + (ql_base - base) + bo) = (l1 << 16) | l0;
        }
    }
    __syncthreads();

    // --- GEMM: 8 warps = 4(m: 64 rows) x 2(n: 32 cols); acc[4 im][4 jn][4] ---
    int wm = wid & 3, wn = wid >> 2;
    float acc[4][4][4];
#pragma unroll
    for (int im = 0; im < 4; im++)
#pragma unroll
        for (int jn = 0; jn < 4; jn++)
#pragma unroll
            for (int q = 0; q < 4; q++) acc[im][jn][q] = 0.0f;

    u32 a_off[4], b_off[2];
#pragma unroll
    for (int im = 0; im < 4; im++) {
        int arow = wm * 64 + im * 16 + (lane & 15);
        u32 bo = (u32)(arow * 128) + ((lane >> 4) << 4);
        a_off[im] = bo ^ ((bo >> 3) & 0x70);
    }
#pragma unroll
    for (int j2 = 0; j2 < 2; j2++) {
        int nrow = wn * 32 + j2 * 16 + ((lane >> 4) << 3) + (lane & 7);
        u32 bo = (u32)(nrow * 128) + (((lane >> 3) & 1) << 4);
        b_off[j2] = bo ^ ((bo >> 3) & 0x70);
    }
    u32 mstage = base + 32768u;

    for (int s = 0; s < 6; s++) {
        int t = s >> 1, kc = s & 1;
        const unsigned short* Asrc = (t == 2) ? g_Ml : g_Mh;
        u32 qbase = base + (u32)((t == 1 ? 16384 : 0) + kc * 8192);
        // stage M chunk [256 rows][64 k] bf16, SW128 swizzled
#pragma unroll
        for (int i = 0; i < 8; i++) {
            int u = tid + i * 256;                // 2048 uint4
            int r = u >> 3, c8 = (u & 7) << 3;
            u32 bo = (u32)((r << 7) + (c8 << 1));
            bo ^= (bo >> 3) & 0x70;
            *reinterpret_cast<uint4*>(dyn + 32768 + bo) =
                *reinterpret_cast<const uint4*>(&Asrc[(b * PC + r) * PHID + kc * 64 + c8]);
        }
        __syncthreads();
#pragma unroll
        for (int kk = 0; kk < 4; kk++) {
            u32 kadd = (u32)(kk * 32);
            u32 a[4][4];
#pragma unroll
            for (int im = 0; im < 4; im++) ldsm4(a[im], mstage + (a_off[im] ^ kadd));
            u32 bf[4][2];
#pragma unroll
            for (int j2 = 0; j2 < 2; j2++) {
                u32 r4[4];
                ldsm4(r4, qbase + (b_off[j2] ^ kadd));
                bf[2 * j2][0] = r4[0]; bf[2 * j2][1] = r4[1];
                bf[2 * j2 + 1][0] = r4[2]; bf[2 * j2 + 1][1] = r4[3];
            }
#pragma unroll
            for (int im = 0; im < 4; im++)
#pragma unroll
                for (int jn = 0; jn < 4; jn++)
                    mma16816(acc[im][jn], a[im], bf[jn]);
        }
        __syncthreads();
    }

    // --- epilogue: bias, per-pixel RMS over all 256 channels, g_out scale, store ---
    float bo0[4], bo8[4], go0[4], go8[4];
#pragma unroll
    for (int im = 0; im < 4; im++) {
        int r = wm * 64 + im * 16 + (lane >> 2);
        bo0[im] = b_out[r];  bo8[im] = b_out[r + 8];
        go0[im] = g_out[r];  go8[im] = g_out[r + 8];
    }
#pragma unroll
    for (int jn = 0; jn < 4; jn++) {
        float sq0 = 0.f, sq1 = 0.f;
#pragma unroll
        for (int im = 0; im < 4; im++) {
            acc[im][jn][0] += bo0[im]; acc[im][jn][1] += bo0[im];
            acc[im][jn][2] += bo8[im]; acc[im][jn][3] += bo8[im];
            sq0 += acc[im][jn][0] * acc[im][jn][0] + acc[im][jn][2] * acc[im][jn][2];
            sq1 += acc[im][jn][1] * acc[im][jn][1] + acc[im][jn][3] * acc[im][jn][3];
        }
        // reduce over the 8 lanes sharing (lane&3): strides 4, 8, 16
#pragma unroll
        for (int off = 4; off < 32; off <<= 1) {
            sq0 += __shfl_xor_sync(0xffffffffu, sq0, off);
            sq1 += __shfl_xor_sync(0xffffffffu, sq1, off);
        }
        if (lane < 4) {
            int c = wn * 32 + jn * 8 + lane * 2;
            red[wm * 64 + c] = sq0;
            red[wm * 64 + c + 1] = sq1;
        }
    }
    __syncthreads();
    if (tid < 64) {
        float s = red[tid] + red[64 + tid] + red[128 + tid] + red[192 + tid];
        invr[tid] = 16.0f / fmaxf(sqrtf(s), 1e-12f);
    }
    __syncthreads();
#pragma unroll
    for (int im = 0; im < 4; im++) {
        int r = wm * 64 + im * 16 + (lane >> 2);
#pragma unroll
        for (int jn = 0; jn < 4; jn++) {
            int c = wn * 32 + jn * 8 + (lane & 3) * 2;
            float iv0 = invr[c], iv1 = invr[c + 1];
            float2 v0 = {acc[im][jn][0] * iv0 * go0[im], acc[im][jn][1] * iv1 * go0[im]};
            float2 v1 = {acc[im][jn][2] * iv0 * go8[im], acc[im][jn][3] * iv1 * go8[im]};
            *reinterpret_cast<float2*>(&out[((size_t)(b * PC + r)) * PN + p0 + c]) = v0;
            *reinterpret_cast<float2*>(&out[((size_t)(b * PC + r + 8)) * PN + p0 + c]) = v1;
        }
    }
}

// ---------------- launch ----------------
extern "C" void kernel_launch(void* const* d_in, const int* in_sizes, int n_in,
                              void* d_out, int out_size) {
    const float* x      = (const float*)d_in[0];
    const float* g_in   = (const float*)d_in[1];
    const float* mem_kv = (const float*)d_in[2];
    const float* w_qkv  = (const float*)d_in[3];
    const float* w_out  = (const float*)d_in[4];
    const float* b_out  = (const float*)d_in[5];
    const float* g_out  = (const float*)d_in[6];
    float* out = (float*)d_out;

    static int attr_done = 0;
    if (!attr_done) {
        cudaFuncSetAttribute(k_qkv_mma, cudaFuncAttributeMaxDynamicSharedMemorySize, QKV_SMEM);
        cudaFuncSetAttribute(k_out_mma, cudaFuncAttributeMaxDynamicSharedMemorySize, OUT_SMEM);
        attr_done = 1;
    }

    k_convw  <<<QROWS, 256>>>(w_qkv, g_in);
    k_invnorm<<<dim3(PN / 256, PB), 256>>>(x);
    k_convx  <<<dim3(PN / 64, PC / 64, PB), 256>>>(x);
    k_qkv_mma<<<dim3(PN / 128, QROWS / 128, PB), 256, QKV_SMEM>>>();
    k_kstats <<<512, 128>>>(mem_kv);
    k_context<<<dim3(8, PNH, PB), 256>>>(mem_kv);
    k_fold   <<<PB, 256>>>(w_out);
    k_out_mma<<<dim3(PN / 64, PB), 256, OUT_SMEM>>>(b_out, g_out, out);
}

// round 11
// speedup vs baseline: 1.5558x; 1.0082x over previous
#include <cuda_runtime.h>
#include <math.h>
#include <stdint.h>

// Problem constants
#define PB   16      // batch
#define PC   256     // channels
#define PN   4096    // H*W
#define PNH  4       // heads
#define PHD  32      // head dim
#define PNM  4       // memory tokens
#define PHID 128     // NH*HD
#define QROWS 384    // 3*HID

typedef unsigned long long u64;
typedef unsigned int u32;

// ---------------- scratch (static device memory; no allocation) ----------------
__device__ unsigned short g_wh[QROWS * PC];            // bf16 hi of scaled qkv weights
__device__ unsigned short g_wl[QROWS * PC];            // bf16 lo
__device__ unsigned short g_xh[(size_t)PB * PN * PC];  // bf16 hi of x, [b][n][c]
__device__ unsigned short g_xl[(size_t)PB * PN * PC];  // bf16 lo
__device__ float g_invn[PB * PN];                      // 1/||x||_C per pixel
__device__ float g_qkv[(size_t)PB * QROWS * PN];       // qkv activations (~100 MB)
__device__ float g_stat[2][PB * PNH * PHD];            // k softmax: rowmax, 1/rowsum
__device__ float g_ctxp[8][PB * PNH * PHD * PHD];      // partial contexts (8 token chunks)
__device__ unsigned short g_Mh[PB * PC * PHID];        // folded M = w_out . ctx, bf16 hi
__device__ unsigned short g_Ml[PB * PC * PHID];        // bf16 lo

// ---------------- small helpers ----------------
__device__ __forceinline__ unsigned bf16_rn(float v) {
    unsigned u = __float_as_uint(v);
    return (u + 0x7FFFu + ((u >> 16) & 1u)) >> 16;
}
__device__ __forceinline__ float bf16_tof(unsigned b) { return __uint_as_float(b << 16); }

__device__ __forceinline__ u32 smem_u32(const void* p) {
    u32 a;
    asm("{ .reg .u64 t; cvta.to.shared.u64 t, %1; cvt.u32.u64 %0, t; }" : "=r"(a) : "l"(p));
    return a;
}

// f32x2 packed helpers (k_context)
__device__ __forceinline__ u64 fma2(u64 a, u64 b, u64 c) {
    u64 d; asm("fma.rn.f32x2 %0, %1, %2, %3;" : "=l"(d) : "l"(a), "l"(b), "l"(c)); return d;
}
__device__ __forceinline__ u64 pack2(float lo, float hi) {
    u64 r; asm("mov.b64 %0, {%1, %2};" : "=l"(r) : "f"(lo), "f"(hi)); return r;
}
__device__ __forceinline__ float2 unpack2(u64 v) {
    float2 r; asm("mov.b64 {%0, %1}, %2;" : "=f"(r.x), "=f"(r.y) : "l"(v)); return r;
}

// ---------------- HMMA helpers (baseline ISA: ldmatrix + mma.sync + cp.async) ----------------
__device__ __forceinline__ void ldsm4(u32* r, u32 addr) {
    asm volatile("ldmatrix.sync.aligned.m8n8.x4.shared.b16 {%0,%1,%2,%3}, [%4];"
                 : "=r"(r[0]), "=r"(r[1]), "=r"(r[2]), "=r"(r[3]) : "r"(addr));
}
__device__ __forceinline__ void mma16816(float* d, const u32* a, const u32* b) {
    asm volatile(
        "mma.sync.aligned.m16n8k16.row.col.f32.bf16.bf16.f32 "
        "{%0,%1,%2,%3}, {%4,%5,%6,%7}, {%8,%9}, {%0,%1,%2,%3};"
        : "+f"(d[0]), "+f"(d[1]), "+f"(d[2]), "+f"(d[3])
        : "r"(a[0]), "r"(a[1]), "r"(a[2]), "r"(a[3]), "r"(b[0]), "r"(b[1]));
}
__device__ __forceinline__ void cpa16(u32 dst, const void* src) {
    asm volatile("cp.async.ca.shared.global [%0], [%1], 16;" :: "r"(dst), "l"(src));
}
__device__ __forceinline__ void cpa_commit() {
    asm volatile("cp.async.commit_group;" ::: "memory");
}
__device__ __forceinline__ void cpa_wait1() {
    asm volatile("cp.async.wait_group 1;" ::: "memory");
}
__device__ __forceinline__ void cpa_wait0() {
    asm volatile("cp.async.wait_group 0;" ::: "memory");
}

// ---------------- K0a: weight convert  hi/lo of (w_qkv * g_in * sqrt(C)) ----------------
__global__ void k_convw(const float* __restrict__ w_qkv, const float* __restrict__ g_in) {
    int i = blockIdx.x * 256 + threadIdx.x;    // i = row*256 + c
    if (i < QROWS * PC) {
        int c = i & 255;
        float v = w_qkv[i] * g_in[c] * 16.0f;  // sqrt(256) = 16
        unsigned hb = bf16_rn(v);
        unsigned lb = bf16_rn(v - bf16_tof(hb));
        g_wh[i] = (unsigned short)hb;
        g_wl[i] = (unsigned short)lb;
    }
}

// ---------------- K0b: x transpose + bf16 hi/lo split:  [b][c][n] -> [b][n][c] ----------------
__global__ void k_convx(const float* __restrict__ x) {
    __shared__ float ts[64][65];
    int n0 = blockIdx.x * 64, c0 = blockIdx.y * 64, b = blockIdx.z;
    int tid = threadIdx.x;
#pragma unroll
    for (int i = 0; i < 4; i++) {
        int f4 = tid + i * 256;                 // 1024 float4
        int r = f4 >> 4, col4 = (f4 & 15) << 2;
        float4 v = *reinterpret_cast<const float4*>(
            &x[((size_t)b * PC + c0 + r) * PN + n0 + col4]);
        ts[r][col4 + 0] = v.x; ts[r][col4 + 1] = v.y;
        ts[r][col4 + 2] = v.z; ts[r][col4 + 3] = v.w;
    }
    __syncthreads();
#pragma unroll
    for (int i = 0; i < 8; i++) {
        int e2 = tid + i * 256;                 // 2048 bf16-pairs
        int n_ = e2 >> 5, cp = (e2 & 31) << 1;
        float v0 = ts[cp][n_], v1 = ts[cp + 1][n_];
        unsigned h0 = bf16_rn(v0), h1 = bf16_rn(v1);
        unsigned l0 = bf16_rn(v0 - bf16_tof(h0));
        unsigned l1 = bf16_rn(v1 - bf16_tof(h1));
        size_t e = ((size_t)b * PN + n0 + n_) * PC + c0 + cp;
        reinterpret_cast<u32*>(g_xh)[e >> 1] = (h1 << 16) | h0;
        reinterpret_cast<u32*>(g_xl)[e >> 1] = (l1 << 16) | l0;
    }
}

// ---------------- K1: per-pixel inverse channel norm ----------------
__global__ void k_invnorm(const float* __restrict__ x) {
    int p = blockIdx.x * 256 + threadIdx.x;
    int b = blockIdx.y;
    const float* xp = x + (size_t)b * PC * PN + p;
    float s0 = 0.f, s1 = 0.f, s2 = 0.f, s3 = 0.f;
#pragma unroll
    for (int c = 0; c < PC; c += 4) {
        float v0 = xp[(size_t)(c + 0) * PN];
        float v1 = xp[(size_t)(c + 1) * PN];
        float v2 = xp[(size_t)(c + 2) * PN];
        float v3 = xp[(size_t)(c + 3) * PN];
        s0 += v0 * v0; s1 += v1 * v1; s2 += v2 * v2; s3 += v3 * v3;
    }
    float s = (s0 + s1) + (s2 + s3);
    g_invn[b * PN + p] = 1.0f / fmaxf(sqrtf(s), 1e-12f);
}

// ---------------- K2: qkv GEMM on HMMA; 3-term hi/lo combined in-register ----------------
// CTA: D[128 m x 128 n]; 8 warps 4(m)x2(n); 8 chunks of 32 channels.
// Per chunk, arrays hold [hi(cols 0-31) | lo(cols 32-63)] -> 128B rows, SW128.
// dyn smem: A0 @0, B0 @16384, A1 @32768, B1 @49152, inv @65536 -> 66048 B
#define QKV_SMEM 66048
__global__ void __launch_bounds__(256, 2) k_qkv_mma() {
    extern __shared__ char dyn[];
    u32 base = smem_u32(dyn);
    float* inv_s = reinterpret_cast<float*>(dyn + 65536);
    int tid = threadIdx.x, lane = tid & 31, wid = tid >> 5;
    int nb = blockIdx.x * 128, mb = blockIdx.y * 128, b = blockIdx.z;
    if (tid < 128) inv_s[tid] = g_invn[b * PN + nb + tid];
    int wm = (wid & 3) * 32, wn = (wid >> 2) * 64;

    float acc[2][8][4];
#pragma unroll
    for (int im = 0; im < 2; im++)
#pragma unroll
        for (int jn = 0; jn < 8; jn++)
#pragma unroll
            for (int q = 0; q < 4; q++) acc[im][jn][q] = 0.0f;

    // per-thread staging: 4 uint4 per array; source = hi for c8<32, lo for c8>=32
    u32 st_bo[4];
    const unsigned short* st_wsrc[4];
    const unsigned short* st_xsrc[4];
#pragma unroll
    for (int i = 0; i < 4; i++) {
        int u = tid + i * 256;
        int r = u >> 3, c8 = (u & 7) << 3;
        u32 bo = (u32)((r << 7) + (c8 << 1));
        st_bo[i] = bo ^ ((bo >> 3) & 0x70);
        if (c8 < 32) {
            st_wsrc[i] = &g_wh[(size_t)(mb + r) * PC + c8];
            st_xsrc[i] = &g_xh[((size_t)b * PN + nb + r) * PC + c8];
        } else {
            st_wsrc[i] = &g_wl[(size_t)(mb + r) * PC + c8 - 32];
            st_xsrc[i] = &g_xl[((size_t)b * PN + nb + r) * PC + c8 - 32];
        }
    }
    // ldmatrix offsets (swizzled, kadd=0)
    u32 a_off[2], b_off[4];
#pragma unroll
    for (int im = 0; im < 2; im++) {
        int arow = wm + im * 16 + (lane & 15);
        u32 bo = (u32)(arow * 128) + ((lane >> 4) << 4);
        a_off[im] = bo ^ ((bo >> 3) & 0x70);
    }
#pragma unroll
    for (int j2 = 0; j2 < 4; j2++) {
        int nrow = wn + j2 * 16 + ((lane >> 4) << 3) + (lane & 7);
        u32 bo = (u32)(nrow * 128) + (((lane >> 3) & 1) << 4);
        b_off[j2] = bo ^ ((bo >> 3) & 0x70);
    }

    // prologue: stage chunk 0 into buffer 0
#pragma unroll
    for (int i = 0; i < 4; i++) {
        cpa16(base + st_bo[i], st_wsrc[i]);
        cpa16(base + 16384 + st_bo[i], st_xsrc[i]);
    }
    cpa_commit();

    for (int ch = 0; ch < 8; ch++) {
        if (ch < 7) {
            u32 sb = (u32)(((ch + 1) & 1) * 32768);
            int co = (ch + 1) * 32;
#pragma unroll
            for (int i = 0; i < 4; i++) {
                cpa16(base + sb + st_bo[i], st_wsrc[i] + co);
                cpa16(base + sb + 16384 + st_bo[i], st_xsrc[i] + co);
            }
            cpa_commit();
            cpa_wait1();
        } else {
            cpa_wait0();
        }
        __syncthreads();
        u32 aU = base + (u32)((ch & 1) * 32768);
        u32 bU = aU + 16384u;
#pragma unroll
        for (int kkh = 0; kkh < 2; kkh++) {
            u32 kA = (u32)(kkh * 32);   // hi half; lo half at kA ^ 64 (XOR-safe)
            u32 ah[2][4];
            ldsm4(ah[0], aU + (a_off[0] ^ kA));
            ldsm4(ah[1], aU + (a_off[1] ^ kA));
            u32 bh[8][2];
#pragma unroll
            for (int j2 = 0; j2 < 4; j2++) {
                u32 r4[4];
                ldsm4(r4, bU + (b_off[j2] ^ kA));
                bh[2 * j2][0] = r4[0]; bh[2 * j2][1] = r4[1];
                bh[2 * j2 + 1][0] = r4[2]; bh[2 * j2 + 1][1] = r4[3];
            }
#pragma unroll
            for (int im = 0; im < 2; im++)
#pragma unroll
                for (int jn = 0; jn < 8; jn++)
                    mma16816(acc[im][jn], ah[im], bh[jn]);
            // Ah * Bl
            {
                u32 bl[8][2];
#pragma unroll
                for (int j2 = 0; j2 < 4; j2++) {
                    u32 r4[4];
                    ldsm4(r4, bU + (b_off[j2] ^ (kA + 64)));
                    bl[2 * j2][0] = r4[0]; bl[2 * j2][1] = r4[1];
                    bl[2 * j2 + 1][0] = r4[2]; bl[2 * j2 + 1][1] = r4[3];
                }
#pragma unroll
                for (int im = 0; im < 2; im++)
#pragma unroll
                    for (int jn = 0; jn < 8; jn++)
                        mma16816(acc[im][jn], ah[im], bl[jn]);
            }
            // Al * Bh
            {
                u32 al[2][4];
                ldsm4(al[0], aU + (a_off[0] ^ (kA + 64)));
                ldsm4(al[1], aU + (a_off[1] ^ (kA + 64)));
#pragma unroll
                for (int im = 0; im < 2; im++)
#pragma unroll
                    for (int jn = 0; jn < 8; jn++)
                        mma16816(acc[im][jn], al[im], bh[jn]);
            }
        }
        __syncthreads();
    }

    // epilogue: scale by invn(col), store float2 per atom-half
    int r0 = wm + (lane >> 2);
    int cb = wn + (lane & 3) * 2;
#pragma unroll
    for (int im = 0; im < 2; im++) {
#pragma unroll
        for (int jn = 0; jn < 8; jn++) {
            int c = cb + jn * 8;
            float ivx = inv_s[c], ivy = inv_s[c + 1];
            size_t rowA = (size_t)b * QROWS + mb + r0 + im * 16;
            float2 v0 = {acc[im][jn][0] * ivx, acc[im][jn][1] * ivy};
            float2 v1 = {acc[im][jn][2] * ivx, acc[im][jn][3] * ivy};
            *reinterpret_cast<float2*>(&g_qkv[rowA * PN + nb + c]) = v0;
            *reinterpret_cast<float2*>(&g_qkv[(rowA + 8) * PN + nb + c]) = v1;
        }
    }
}

// ---------------- K3a: k row softmax stats ----------------
__global__ void k_kstats(const float* __restrict__ mem_kv) {
    int gwarp = (blockIdx.x * blockDim.x + threadIdx.x) >> 5;
    int lane = threadIdx.x & 31;
    if (gwarp >= PB * PNH * PHD) return;
    int d = gwarp & 31, h = (gwarp >> 5) & 3, b = gwarp >> 7;
    const float* krow = &g_qkv[((size_t)b * QROWS + PHID + h * PHD + d) * PN];

    float m0 = -1e30f, m1 = -1e30f, m2 = -1e30f, m3 = -1e30f;
    for (int p = lane; p < PN; p += 128) {
        m0 = fmaxf(m0, krow[p]);
        m1 = fmaxf(m1, krow[p + 32]);
        m2 = fmaxf(m2, krow[p + 64]);
        m3 = fmaxf(m3, krow[p + 96]);
    }
    float m = fmaxf(fmaxf(m0, m1), fmaxf(m2, m3));
    if (lane < PNM)
        m = fmaxf(m, mem_kv[((0 * PNH + h) * PHD + d) * PNM + lane]);
#pragma unroll
    for (int o = 16; o > 0; o >>= 1)
        m = fmaxf(m, __shfl_xor_sync(0xffffffffu, m, o));

    float s0 = 0.f, s1 = 0.f, s2 = 0.f, s3 = 0.f;
    for (int p = lane; p < PN; p += 128) {
        s0 += __expf(krow[p] - m);
        s1 += __expf(krow[p + 32] - m);
        s2 += __expf(krow[p + 64] - m);
        s3 += __expf(krow[p + 96] - m);
    }
    float s = (s0 + s1) + (s2 + s3);
    if (lane < PNM)
        s += __expf(mem_kv[((0 * PNH + h) * PHD + d) * PNM + lane] - m);
#pragma unroll
    for (int o = 16; o > 0; o >>= 1)
        s += __shfl_xor_sync(0xffffffffu, s, o);
    if (lane == 0) { g_stat[0][gwarp] = m; g_stat[1][gwarp] = 1.0f / s; }
}

// ---------------- K3b: partial context ----------------
__global__ void k_context(const float* __restrict__ mem_kv) {
    __shared__ float Ks[PHD][68];
    __shared__ float Vt[64][34];
    __shared__ float rmax[PHD], rinv[PHD];
    int tc = blockIdx.x, h = blockIdx.y, b = blockIdx.z;
    int tid = threadIdx.x;
    if (tid < PHD) {
        int rowid = (b * PNH + h) * PHD + tid;
        rmax[tid] = g_stat[0][rowid];
        rinv[tid] = g_stat[1][rowid];
    }
    __syncthreads();
    int d = tid >> 3;
    int eg = (tid & 7) << 2;
    float macc[4] = {0.f, 0.f, 0.f, 0.f};
    if (tc == 0) {
#pragma unroll
        for (int m = 0; m < PNM; m++) {
            float kv = __expf(mem_kv[((0 * PNH + h) * PHD + d) * PNM + m] - rmax[d]) * rinv[d];
#pragma unroll
            for (int i = 0; i < 4; i++)
                macc[i] += kv * mem_kv[((1 * PNH + h) * PHD + eg + i) * PNM + m];
        }
    }
    u64 accp[2] = {0ull, 0ull};
    int pbase = tc * 512;
    for (int t = 0; t < 8; t++) {
        int p0 = pbase + t * 64;
#pragma unroll
        for (int i = 0; i < 2; i++) {
            int f4 = tid + i * 256;
            int r = f4 >> 4, c4 = (f4 & 15) << 2;
            float4 v = *reinterpret_cast<const float4*>(
                &g_qkv[((size_t)b * QROWS + PHID + h * PHD + r) * PN + p0 + c4]);
            float mx = rmax[r], ri = rinv[r];
            Ks[r][c4 + 0] = __expf(v.x - mx) * ri;
            Ks[r][c4 + 1] = __expf(v.y - mx) * ri;
            Ks[r][c4 + 2] = __expf(v.z - mx) * ri;
            Ks[r][c4 + 3] = __expf(v.w - mx) * ri;
        }
#pragma unroll
        for (int i = 0; i < 2; i++) {
            int f4 = tid + i * 256;
            int r = f4 >> 4, c4 = (f4 & 15) << 2;
            float4 v = *reinterpret_cast<const float4*>(
                &g_qkv[((size_t)b * QROWS + 2 * PHID + h * PHD + r) * PN + p0 + c4]);
            Vt[c4 + 0][r] = v.x; Vt[c4 + 1][r] = v.y;
            Vt[c4 + 2][r] = v.z; Vt[c4 + 3][r] = v.w;
        }
        __syncthreads();
#pragma unroll
        for (int n = 0; n < 64; n++) {
            u64 kv2 = pack2(Ks[d][n], Ks[d][n]);
            u64 v0 = *reinterpret_cast<const u64*>(&Vt[n][eg]);
            u64 v1 = *reinterpret_cast<const u64*>(&Vt[n][eg + 2]);
            accp[0] = fma2(kv2, v0, accp[0]);
            accp[1] = fma2(kv2, v1, accp[1]);
        }
        __syncthreads();
    }
    size_t base = ((size_t)(b * PNH + h) * PHD + d) * PHD + eg;
    float2 p0 = unpack2(accp[0]);
    float2 p1 = unpack2(accp[1]);
    g_ctxp[tc][base + 0] = p0.x + macc[0];
    g_ctxp[tc][base + 1] = p0.y + macc[1];
    g_ctxp[tc][base + 2] = p1.x + macc[2];
    g_ctxp[tc][base + 3] = p1.y + macc[3];
}

// ---------------- K4: reduce partials + fold M = w_out . ctx -> bf16 hi/lo ----------------
__global__ void k_fold(const float* __restrict__ w_out) {
    __shared__ float ctx[PNH * PHD * PHD];
    int b = blockIdx.x;
    int tid = threadIdx.x;
    for (int idx = tid; idx < PNH * PHD * PHD; idx += 256) {
        float s = 0.0f;
#pragma unroll
        for (int tc = 0; tc < 8; tc++) s += g_ctxp[tc][b * (PNH * PHD * PHD) + idx];
        ctx[idx] = s;
    }
    __syncthreads();
    int o = tid;
    for (int h = 0; h < PNH; h++) {
        float w[PHD];
#pragma unroll
        for (int e = 0; e < PHD; e++) w[e] = w_out[o * PHID + h * PHD + e];
        for (int dd = 0; dd < PHD; dd++) {
            float s = 0.0f;
#pragma unroll
            for (int e = 0; e < PHD; e++) s += w[e] * ctx[(h * PHD + dd) * PHD + e];
            unsigned hb = bf16_rn(s);
            unsigned lb = bf16_rn(s - bf16_tof(hb));
            int idx = (b * PC + o) * PHID + h * PHD + dd;
            g_Mh[idx] = (unsigned short)hb;
            g_Ml[idx] = (unsigned short)lb;
        }
    }
}

// ---------------- K5: fused q-softmax + output GEMM (HMMA) + bias + RMS norm ----------------
// CTA: o=256 x p=64.  2 kc rounds; per round stage Mh+Ml, 3 in-register term combos.
// dyn smem: Qh0 @0, Qh1 @8192, Ql0 @16384, Ql1 @24576, Mh @32768 (32KB, overlaps f32 qload),
//           Ml @65536 (32KB), red @98304 (1KB), invr @99328 (256B) -> 99584 B
#define OUT_SMEM 99584
__global__ void __launch_bounds__(256, 2) k_out_mma(
    const float* __restrict__ b_out,
    const float* __restrict__ g_out,
    float* __restrict__ out) {
    extern __shared__ char dyn[];
    u32 base = smem_u32(dyn);
    float* msf = reinterpret_cast<float*>(dyn + 32768);   // f32 q load region (reused as Mh stage)
    float* red = reinterpret_cast<float*>(dyn + 98304);   // [4][64]
    float* invr = reinterpret_cast<float*>(dyn + 99328);  // [64]
    int tid = threadIdx.x, lane = tid & 31, wid = tid >> 5;
    int p0 = blockIdx.x * 64, b = blockIdx.y;

    // --- load q f32 tile [128 rows][64 pixels] ---
#pragma unroll
    for (int i = 0; i < 8; i++) {
        int f4 = tid + i * 256;                 // 2048 float4
        int r = f4 >> 4, c4 = (f4 & 15) << 2;
        *reinterpret_cast<float4*>(&msf[r * 64 + c4]) =
            *reinterpret_cast<const float4*>(&g_qkv[((size_t)b * QROWS + r) * PN + p0 + c4]);
    }
    __syncthreads();

    // --- softmax over head_dim per (head, pixel); write bf16 hi/lo Q tiles ---
    {
        int p = tid & 63, h = tid >> 6;          // 4 heads x 64 pixels
        float e[PHD];
        float m = -1e30f;
#pragma unroll
        for (int dd = 0; dd < PHD; dd++) m = fmaxf(m, msf[(h * PHD + dd) * 64 + p]);
        float s = 0.0f;
#pragma unroll
        for (int dd = 0; dd < PHD; dd++) { e[dd] = __expf(msf[(h * PHD + dd) * 64 + p] - m); s += e[dd]; }
        float sc = 0.17677669529663687f / s;     // (1/sqrt(32)) / sumexp
        int kc = h >> 1;
        int klb = (h & 1) * 32;
        u32 qh_off = (u32)(kc * 8192);
        u32 ql_off = 16384u + (u32)(kc * 8192);
        __syncthreads();                          // msf reads complete before Mh staging reuse
#pragma unroll
        for (int dd = 0; dd < PHD; dd += 2) {
            float v0 = e[dd] * sc, v1 = e[dd + 1] * sc;
            unsigned h0 = bf16_rn(v0), h1 = bf16_rn(v1);
            unsigned l0 = bf16_rn(v0 - bf16_tof(h0));
            unsigned l1 = bf16_rn(v1 - bf16_tof(h1));
            u32 bo = (u32)(p * 128 + (klb + dd) * 2);
            bo ^= (bo >> 3) & 0x70;
            *reinterpret_cast<u32*>(dyn + qh_off + bo) = (h1 << 16) | h0;
            *reinterpret_cast<u32*>(dyn + ql_off + bo) = (l1 << 16) | l0;
        }
    }
    __syncthreads();

    // --- GEMM: 8 warps = 4(m: 64 rows) x 2(n: 32 cols) ---
    int wm = wid & 3, wn = wid >> 2;
    float acc[4][4][4];
#pragma unroll
    for (int im = 0; im < 4; im++)
#pragma unroll
        for (int jn = 0; jn < 4; jn++)
#pragma unroll
            for (int q = 0; q < 4; q++) acc[im][jn][q] = 0.0f;

    u32 a_off[4], b_off[2];
#pragma unroll
    for (int im = 0; im < 4; im++) {
        int arow = wm * 64 + im * 16 + (lane & 15);
        u32 bo = (u32)(arow * 128) + ((lane >> 4) << 4);
        a_off[im] = bo ^ ((bo >> 3) & 0x70);
    }
#pragma unroll
    for (int j2 = 0; j2 < 2; j2++) {
        int nrow = wn * 32 + j2 * 16 + ((lane >> 4) << 3) + (lane & 7);
        u32 bo = (u32)(nrow * 128) + (((lane >> 3) & 1) << 4);
        b_off[j2] = bo ^ ((bo >> 3) & 0x70);
    }
    u32 mh_base = base + 32768u, ml_base = base + 65536u;

    for (int kc = 0; kc < 2; kc++) {
        u32 qh = base + (u32)(kc * 8192);
        u32 ql = base + 16384u + (u32)(kc * 8192);
        // stage Mh + Ml chunks [256 rows][64 k] bf16, SW128 swizzled
#pragma unroll
        for (int i = 0; i < 8; i++) {
            int u = tid + i * 256;                // 2048 uint4 each
            int r = u >> 3, c8 = (u & 7) << 3;
            u32 bo = (u32)((r << 7) + (c8 << 1));
            bo ^= (bo >> 3) & 0x70;
            int gi = (b * PC + r) * PHID + kc * 64 + c8;
            *reinterpret_cast<uint4*>(dyn + 32768 + bo) =
                *reinterpret_cast<const uint4*>(&g_Mh[gi]);
            *reinterpret_cast<uint4*>(dyn + 65536 + bo) =
                *reinterpret_cast<const uint4*>(&g_Ml[gi]);
        }
        __syncthreads();
#pragma unroll
        for (int kk = 0; kk < 4; kk++) {
            u32 kadd = (u32)(kk * 32);
            u32 a[4][4];
#pragma unroll
            for (int im = 0; im < 4; im++) ldsm4(a[im], mh_base + (a_off[im] ^ kadd));
            u32 bh[4][2];
#pragma unroll
            for (int j2 = 0; j2 < 2; j2++) {
                u32 r4[4];
                ldsm4(r4, qh + (b_off[j2] ^ kadd));
                bh[2 * j2][0] = r4[0]; bh[2 * j2][1] = r4[1];
                bh[2 * j2 + 1][0] = r4[2]; bh[2 * j2 + 1][1] = r4[3];
            }
#pragma unroll
            for (int im = 0; im < 4; im++)
#pragma unroll
                for (int jn = 0; jn < 4; jn++)
                    mma16816(acc[im][jn], a[im], bh[jn]);
            // Mh * Ql
            {
                u32 bl[4][2];
#pragma unroll
                for (int j2 = 0; j2 < 2; j2++) {
                    u32 r4[4];
                    ldsm4(r4, ql + (b_off[j2] ^ kadd));
                    bl[2 * j2][0] = r4[0]; bl[2 * j2][1] = r4[1];
                    bl[2 * j2 + 1][0] = r4[2]; bl[2 * j2 + 1][1] = r4[3];
                }
#pragma unroll
                for (int im = 0; im < 4; im++)
#pragma unroll
                    for (int jn = 0; jn < 4; jn++)
                        mma16816(acc[im][jn], a[im], bl[jn]);
            }
            // Ml * Qh
            {
                u32 al[4][4];
#pragma unroll
                for (int im = 0; im < 4; im++) ldsm4(al[im], ml_base + (a_off[im] ^ kadd));
#pragma unroll
                for (int im = 0; im < 4; im++)
#pragma unroll
                    for (int jn = 0; jn < 4; jn++)
                        mma16816(acc[im][jn], al[im], bh[jn]);
            }
        }
        __syncthreads();
    }

    // --- epilogue: bias, per-pixel RMS over all 256 channels, g_out scale, store ---
    float bo0[4], bo8[4], go0[4], go8[4];
#pragma unroll
    for (int im = 0; im < 4; im++) {
        int r = wm * 64 + im * 16 + (lane >> 2);
        bo0[im] = b_out[r];  bo8[im] = b_out[r + 8];
        go0[im] = g_out[r];  go8[im] = g_out[r + 8];
    }
#pragma unroll
    for (int jn = 0; jn < 4; jn++) {
        float sq0 = 0.f, sq1 = 0.f;
#pragma unroll
        for (int im = 0; im < 4; im++) {
            acc[im][jn][0] += bo0[im]; acc[im][jn][1] += bo0[im];
            acc[im][jn][2] += bo8[im]; acc[im][jn][3] += bo8[im];
            sq0 += acc[im][jn][0] * acc[im][jn][0] + acc[im][jn][2] * acc[im][jn][2];
            sq1 += acc[im][jn][1] * acc[im][jn][1] + acc[im][jn][3] * acc[im][jn][3];
        }
#pragma unroll
        for (int off = 4; off < 32; off <<= 1) {
            sq0 += __shfl_xor_sync(0xffffffffu, sq0, off);
            sq1 += __shfl_xor_sync(0xffffffffu, sq1, off);
        }
        if (lane < 4) {
            int c = wn * 32 + jn * 8 + lane * 2;
            red[wm * 64 + c] = sq0;
            red[wm * 64 + c + 1] = sq1;
        }
    }
    __syncthreads();
    if (tid < 64) {
        float s = red[tid] + red[64 + tid] + red[128 + tid] + red[192 + tid];
        invr[tid] = 16.0f / fmaxf(sqrtf(s), 1e-12f);
    }
    __syncthreads();
#pragma unroll
    for (int im = 0; im < 4; im++) {
        int r = wm * 64 + im * 16 + (lane >> 2);
#pragma unroll
        for (int jn = 0; jn < 4; jn++) {
            int c = wn * 32 + jn * 8 + (lane & 3) * 2;
            float iv0 = invr[c], iv1 = invr[c + 1];
            float2 v0 = {acc[im][jn][0] * iv0 * go0[im], acc[im][jn][1] * iv1 * go0[im]};
            float2 v1 = {acc[im][jn][2] * iv0 * go8[im], acc[im][jn][3] * iv1 * go8[im]};
            *reinterpret_cast<float2*>(&out[((size_t)(b * PC + r)) * PN + p0 + c]) = v0;
            *reinterpret_cast<float2*>(&out[((size_t)(b * PC + r + 8)) * PN + p0 + c]) = v1;
        }
    }
}

// ---------------- launch ----------------
extern "C" void kernel_launch(void* const* d_in, const int* in_sizes, int n_in,
                              void* d_out, int out_size) {
    const float* x      = (const float*)d_in[0];
    const float* g_in   = (const float*)d_in[1];
    const float* mem_kv = (const float*)d_in[2];
    const float* w_qkv  = (const float*)d_in[3];
    const float* w_out  = (const float*)d_in[4];
    const float* b_out  = (const float*)d_in[5];
    const float* g_out  = (const float*)d_in[6];
    float* out = (float*)d_out;

    static int attr_done = 0;
    if (!attr_done) {
        cudaFuncSetAttribute(k_qkv_mma, cudaFuncAttributeMaxDynamicSharedMemorySize, QKV_SMEM);
        cudaFuncSetAttribute(k_out_mma, cudaFuncAttributeMaxDynamicSharedMemorySize, OUT_SMEM);
        attr_done = 1;
    }

    k_convw  <<<QROWS, 256>>>(w_qkv, g_in);
    k_invnorm<<<dim3(PN / 256, PB), 256>>>(x);
    k_convx  <<<dim3(PN / 64, PC / 64, PB), 256>>>(x);
    k_qkv_mma<<<dim3(PN / 128, QROWS / 128, PB), 256, QKV_SMEM>>>();
    k_kstats <<<512, 128>>>(mem_kv);
    k_context<<<dim3(8, PNH, PB), 256>>>(mem_kv);
    k_fold   <<<PB, 256>>>(w_out);
    k_out_mma<<<dim3(PN / 64, PB), 256, OUT_SMEM>>>(b_out, g_out, out);
}

// round 12
// speedup vs baseline: 1.5983x; 1.0273x over previous
#include <cuda_runtime.h>
#include <math.h>
#include <stdint.h>

// Problem constants
#define PB   16      // batch
#define PC   256     // channels
#define PN   4096    // H*W
#define PNH  4       // heads
#define PHD  32      // head dim
#define PNM  4       // memory tokens
#define PHID 128     // NH*HD
#define QROWS 384    // 3*HID

typedef unsigned long long u64;
typedef unsigned int u32;

// ---------------- scratch (static device memory; no allocation) ----------------
__device__ unsigned short g_wh[QROWS * PC];            // bf16 hi of scaled qkv weights
__device__ unsigned short g_wl[QROWS * PC];            // bf16 lo
__device__ unsigned short g_xh[(size_t)PB * PN * PC];  // bf16 hi of normalized x, [b][n][c]
__device__ unsigned short g_xl[(size_t)PB * PN * PC];  // bf16 lo
__device__ float g_qkv[(size_t)PB * QROWS * PN];       // qkv activations (~100 MB)
__device__ float g_stat[2][PB * PNH * PHD];            // k softmax: rowmax, 1/rowsum
__device__ float g_ctxp[8][PB * PNH * PHD * PHD];      // partial contexts (8 token chunks)
__device__ unsigned short g_Mh[PB * PC * PHID];        // folded M = w_out . ctx, bf16 hi
__device__ unsigned short g_Ml[PB * PC * PHID];        // bf16 lo

// ---------------- small helpers ----------------
__device__ __forceinline__ unsigned bf16_rn(float v) {
    unsigned u = __float_as_uint(v);
    return (u + 0x7FFFu + ((u >> 16) & 1u)) >> 16;
}
__device__ __forceinline__ float bf16_tof(unsigned b) { return __uint_as_float(b << 16); }

__device__ __forceinline__ u32 smem_u32(const void* p) {
    u32 a;
    asm("{ .reg .u64 t; cvta.to.shared.u64 t, %1; cvt.u32.u64 %0, t; }" : "=r"(a) : "l"(p));
    return a;
}

// f32x2 packed helpers (k_context)
__device__ __forceinline__ u64 fma2(u64 a, u64 b, u64 c) {
    u64 d; asm("fma.rn.f32x2 %0, %1, %2, %3;" : "=l"(d) : "l"(a), "l"(b), "l"(c)); return d;
}
__device__ __forceinline__ u64 pack2(float lo, float hi) {
    u64 r; asm("mov.b64 %0, {%1, %2};" : "=l"(r) : "f"(lo), "f"(hi)); return r;
}
__device__ __forceinline__ float2 unpack2(u64 v) {
    float2 r; asm("mov.b64 {%0, %1}, %2;" : "=f"(r.x), "=f"(r.y) : "l"(v)); return r;
}

// ---------------- HMMA helpers (baseline ISA: ldmatrix + mma.sync + cp.async) ----------------
__device__ __forceinline__ void ldsm4(u32* r, u32 addr) {
    asm volatile("ldmatrix.sync.aligned.m8n8.x4.shared.b16 {%0,%1,%2,%3}, [%4];"
                 : "=r"(r[0]), "=r"(r[1]), "=r"(r[2]), "=r"(r[3]) : "r"(addr));
}
__device__ __forceinline__ void mma16816(float* d, const u32* a, const u32* b) {
    asm volatile(
        "mma.sync.aligned.m16n8k16.row.col.f32.bf16.bf16.f32 "
        "{%0,%1,%2,%3}, {%4,%5,%6,%7}, {%8,%9}, {%0,%1,%2,%3};"
        : "+f"(d[0]), "+f"(d[1]), "+f"(d[2]), "+f"(d[3])
        : "r"(a[0]), "r"(a[1]), "r"(a[2]), "r"(a[3]), "r"(b[0]), "r"(b[1]));
}
__device__ __forceinline__ void cpa16(u32 dst, const void* src) {
    asm volatile("cp.async.ca.shared.global [%0], [%1], 16;" :: "r"(dst), "l"(src));
}
__device__ __forceinline__ void cpa_commit() {
    asm volatile("cp.async.commit_group;" ::: "memory");
}
__device__ __forceinline__ void cpa_wait1() {
    asm volatile("cp.async.wait_group 1;" ::: "memory");
}
__device__ __forceinline__ void cpa_wait0() {
    asm volatile("cp.async.wait_group 0;" ::: "memory");
}

// ---------------- K0a: weight convert  hi/lo of (w_qkv * g_in * sqrt(C)) ----------------
__global__ void k_convw(const float* __restrict__ w_qkv, const float* __restrict__ g_in) {
    int i = blockIdx.x * 256 + threadIdx.x;    // i = row*256 + c
    if (i < QROWS * PC) {
        int c = i & 255;
        float v = w_qkv[i] * g_in[c] * 16.0f;  // sqrt(256) = 16
        unsigned hb = bf16_rn(v);
        unsigned lb = bf16_rn(v - bf16_tof(hb));
        g_wh[i] = (unsigned short)hb;
        g_wl[i] = (unsigned short)lb;
    }
}

// ---------------- K0b: fused channel-RMS + transpose + bf16 hi/lo split ----------------
// Per block: 64 pixels x all 256 channels.  xh/xl get x * invn folded in.
// dyn smem: xs[256][66] f32 @0 (67584 B), ss[4][64] @67584, inv[64] @68608 -> 68864 B
#define NORMX_SMEM 68864
__global__ void __launch_bounds__(256) k_normx(const float* __restrict__ x) {
    extern __shared__ char dsm[];
    float* xs = reinterpret_cast<float*>(dsm);            // [c][p], pitch 66
    float* ss = reinterpret_cast<float*>(dsm + 67584);    // [4][64]
    float* inv = reinterpret_cast<float*>(dsm + 68608);   // [64]
    int n0 = blockIdx.x * 64, b = blockIdx.y;
    int tid = threadIdx.x;

    // load x [256 c][64 p]
#pragma unroll
    for (int i = 0; i < 16; i++) {
        int f4 = tid + i * 256;                 // 4096 float4
        int c = f4 >> 4, p4 = (f4 & 15) << 2;
        float4 v = *reinterpret_cast<const float4*>(
            &x[((size_t)b * PC + c) * PN + n0 + p4]);
        float* row = &xs[c * 66 + p4];
        row[0] = v.x; row[1] = v.y; row[2] = v.z; row[3] = v.w;
    }
    __syncthreads();

    // per-pixel sum of squares (4 threads per pixel)
    {
        int p = tid & 63, q = tid >> 6;
        float s = 0.0f;
#pragma unroll 8
        for (int c2 = 0; c2 < 64; c2++) {
            float v = xs[(q * 64 + c2) * 66 + p];
            s += v * v;
        }
        ss[q * 64 + p] = s;
    }
    __syncthreads();
    if (tid < 64) {
        float s = ss[tid] + ss[64 + tid] + ss[128 + tid] + ss[192 + tid];
        inv[tid] = 1.0f / fmaxf(sqrtf(s), 1e-12f);
    }
    __syncthreads();

    // write transposed bf16 hi/lo: [b][n][c], invn folded
#pragma unroll
    for (int i = 0; i < 32; i++) {
        int e2 = tid + i * 256;                 // 8192 pairs
        int n_ = e2 >> 7, cp = (e2 & 127) << 1;
        float iv = inv[n_];
        float v0 = xs[cp * 66 + n_] * iv;
        float v1 = xs[(cp + 1) * 66 + n_] * iv;
        unsigned h0 = bf16_rn(v0), h1 = bf16_rn(v1);
        unsigned l0 = bf16_rn(v0 - bf16_tof(h0));
        unsigned l1 = bf16_rn(v1 - bf16_tof(h1));
        size_t e = ((size_t)b * PN + n0 + n_) * PC + cp;
        reinterpret_cast<u32*>(g_xh)[e >> 1] = (h1 << 16) | h0;
        reinterpret_cast<u32*>(g_xl)[e >> 1] = (l1 << 16) | l0;
    }
}

// ---------------- K2: qkv GEMM on HMMA; 3-stage cp.async, 1 barrier/chunk ----------------
// CTA: D[128 m x 128 n]; 8 warps 4(m)x2(n); 8 chunks of 32 channels.
// Per chunk arrays hold [hi(0-31) | lo(32-63)] -> 128B rows, SW128.
// dyn smem: stage s at s*32768 (A @+0, B @+16384), 3 stages -> 98304 B
#define QKV_SMEM 98304
__global__ void __launch_bounds__(256, 2) k_qkv_mma() {
    extern __shared__ char dyn[];
    u32 base = smem_u32(dyn);
    int tid = threadIdx.x, lane = tid & 31, wid = tid >> 5;
    int nb = blockIdx.x * 128, mb = blockIdx.y * 128, b = blockIdx.z;
    int wm = (wid & 3) * 32, wn = (wid >> 2) * 64;

    float acc[2][8][4];
#pragma unroll
    for (int im = 0; im < 2; im++)
#pragma unroll
        for (int jn = 0; jn < 8; jn++)
#pragma unroll
            for (int q = 0; q < 4; q++) acc[im][jn][q] = 0.0f;

    // per-thread staging: 4 uint4 per array; source = hi for c8<32, lo for c8>=32
    u32 st_bo[4];
    const unsigned short* st_wsrc[4];
    const unsigned short* st_xsrc[4];
#pragma unroll
    for (int i = 0; i < 4; i++) {
        int u = tid + i * 256;
        int r = u >> 3, c8 = (u & 7) << 3;
        u32 bo = (u32)((r << 7) + (c8 << 1));
        st_bo[i] = bo ^ ((bo >> 3) & 0x70);
        if (c8 < 32) {
            st_wsrc[i] = &g_wh[(size_t)(mb + r) * PC + c8];
            st_xsrc[i] = &g_xh[((size_t)b * PN + nb + r) * PC + c8];
        } else {
            st_wsrc[i] = &g_wl[(size_t)(mb + r) * PC + c8 - 32];
            st_xsrc[i] = &g_xl[((size_t)b * PN + nb + r) * PC + c8 - 32];
        }
    }
    // ldmatrix offsets (swizzled, kadd=0)
    u32 a_off[2], b_off[4];
#pragma unroll
    for (int im = 0; im < 2; im++) {
        int arow = wm + im * 16 + (lane & 15);
        u32 bo = (u32)(arow * 128) + ((lane >> 4) << 4);
        a_off[im] = bo ^ ((bo >> 3) & 0x70);
    }
#pragma unroll
    for (int j2 = 0; j2 < 4; j2++) {
        int nrow = wn + j2 * 16 + ((lane >> 4) << 3) + (lane & 7);
        u32 bo = (u32)(nrow * 128) + (((lane >> 3) & 1) << 4);
        b_off[j2] = bo ^ ((bo >> 3) & 0x70);
    }

    // prologue: stage chunks 0, 1
#pragma unroll
    for (int s = 0; s < 2; s++) {
        u32 sb = base + (u32)(s * 32768);
        int co = s * 32;
#pragma unroll
        for (int i = 0; i < 4; i++) {
            cpa16(sb + st_bo[i], st_wsrc[i] + co);
            cpa16(sb + 16384 + st_bo[i], st_xsrc[i] + co);
        }
        cpa_commit();
    }

    for (int ch = 0; ch < 8; ch++) {
        if (ch < 7) cpa_wait1(); else cpa_wait0();
        __syncthreads();          // all threads done with chunk ch-1 reads; data of ch arrived
        if (ch + 2 < 8) {
            u32 sb = base + (u32)(((ch + 2) % 3) * 32768);
            int co = (ch + 2) * 32;
#pragma unroll
            for (int i = 0; i < 4; i++) {
                cpa16(sb + st_bo[i], st_wsrc[i] + co);
                cpa16(sb + 16384 + st_bo[i], st_xsrc[i] + co);
            }
            cpa_commit();
        }
        u32 aU = base + (u32)((ch % 3) * 32768);
        u32 bU = aU + 16384u;
#pragma unroll
        for (int kkh = 0; kkh < 2; kkh++) {
            u32 kA = (u32)(kkh * 32);   // hi half; lo half at ^ (kA+64) (XOR-safe)
            u32 ah[2][4];
            ldsm4(ah[0], aU + (a_off[0] ^ kA));
            ldsm4(ah[1], aU + (a_off[1] ^ kA));
            u32 bh[8][2];
#pragma unroll
            for (int j2 = 0; j2 < 4; j2++) {
                u32 r4[4];
                ldsm4(r4, bU + (b_off[j2] ^ kA));
                bh[2 * j2][0] = r4[0]; bh[2 * j2][1] = r4[1];
                bh[2 * j2 + 1][0] = r4[2]; bh[2 * j2 + 1][1] = r4[3];
            }
            // hoist lo-part loads so later mma blocks have operands in flight
            u32 al[2][4];
            ldsm4(al[0], aU + (a_off[0] ^ (kA + 64)));
            ldsm4(al[1], aU + (a_off[1] ^ (kA + 64)));
#pragma unroll
            for (int im = 0; im < 2; im++)
#pragma unroll
                for (int jn = 0; jn < 8; jn++)
                    mma16816(acc[im][jn], ah[im], bh[jn]);
            {
                u32 bl[8][2];
#pragma unroll
                for (int j2 = 0; j2 < 4; j2++) {
                    u32 r4[4];
                    ldsm4(r4, bU + (b_off[j2] ^ (kA + 64)));
                    bl[2 * j2][0] = r4[0]; bl[2 * j2][1] = r4[1];
                    bl[2 * j2 + 1][0] = r4[2]; bl[2 * j2 + 1][1] = r4[3];
                }
#pragma unroll
                for (int im = 0; im < 2; im++)
#pragma unroll
                    for (int jn = 0; jn < 8; jn++)
                        mma16816(acc[im][jn], ah[im], bl[jn]);
            }
#pragma unroll
            for (int im = 0; im < 2; im++)
#pragma unroll
                for (int jn = 0; jn < 8; jn++)
                    mma16816(acc[im][jn], al[im], bh[jn]);
        }
    }

    // epilogue: store float2 per atom-half (invn already folded into x)
    int r0 = wm + (lane >> 2);
    int cb = wn + (lane & 3) * 2;
#pragma unroll
    for (int im = 0; im < 2; im++) {
#pragma unroll
        for (int jn = 0; jn < 8; jn++) {
            int c = cb + jn * 8;
            size_t rowA = (size_t)b * QROWS + mb + r0 + im * 16;
            float2 v0 = {acc[im][jn][0], acc[im][jn][1]};
            float2 v1 = {acc[im][jn][2], acc[im][jn][3]};
            *reinterpret_cast<float2*>(&g_qkv[rowA * PN + nb + c]) = v0;
            *reinterpret_cast<float2*>(&g_qkv[(rowA + 8) * PN + nb + c]) = v1;
        }
    }
}

// ---------------- K3a: k row softmax stats ----------------
__global__ void k_kstats(const float* __restrict__ mem_kv) {
    int gwarp = (blockIdx.x * blockDim.x + threadIdx.x) >> 5;
    int lane = threadIdx.x & 31;
    if (gwarp >= PB * PNH * PHD) return;
    int d = gwarp & 31, h = (gwarp >> 5) & 3, b = gwarp >> 7;
    const float* krow = &g_qkv[((size_t)b * QROWS + PHID + h * PHD + d) * PN];

    float m0 = -1e30f, m1 = -1e30f, m2 = -1e30f, m3 = -1e30f;
    for (int p = lane; p < PN; p += 128) {
        m0 = fmaxf(m0, krow[p]);
        m1 = fmaxf(m1, krow[p + 32]);
        m2 = fmaxf(m2, krow[p + 64]);
        m3 = fmaxf(m3, krow[p + 96]);
    }
    float m = fmaxf(fmaxf(m0, m1), fmaxf(m2, m3));
    if (lane < PNM)
        m = fmaxf(m, mem_kv[((0 * PNH + h) * PHD + d) * PNM + lane]);
#pragma unroll
    for (int o = 16; o > 0; o >>= 1)
        m = fmaxf(m, __shfl_xor_sync(0xffffffffu, m, o));

    float s0 = 0.f, s1 = 0.f, s2 = 0.f, s3 = 0.f;
    for (int p = lane; p < PN; p += 128) {
        s0 += __expf(krow[p] - m);
        s1 += __expf(krow[p + 32] - m);
        s2 += __expf(krow[p + 64] - m);
        s3 += __expf(krow[p + 96] - m);
    }
    float s = (s0 + s1) + (s2 + s3);
    if (lane < PNM)
        s += __expf(mem_kv[((0 * PNH + h) * PHD + d) * PNM + lane] - m);
#pragma unroll
    for (int o = 16; o > 0; o >>= 1)
        s += __shfl_xor_sync(0xffffffffu, s, o);
    if (lane == 0) { g_stat[0][gwarp] = m; g_stat[1][gwarp] = 1.0f / s; }
}

// ---------------- K3b: partial context ----------------
__global__ void k_context(const float* __restrict__ mem_kv) {
    __shared__ float Ks[PHD][68];
    __shared__ float Vt[64][34];
    __shared__ float rmax[PHD], rinv[PHD];
    int tc = blockIdx.x, h = blockIdx.y, b = blockIdx.z;
    int tid = threadIdx.x;
    if (tid < PHD) {
        int rowid = (b * PNH + h) * PHD + tid;
        rmax[tid] = g_stat[0][rowid];
        rinv[tid] = g_stat[1][rowid];
    }
    __syncthreads();
    int d = tid >> 3;
    int eg = (tid & 7) << 2;
    float macc[4] = {0.f, 0.f, 0.f, 0.f};
    if (tc == 0) {
#pragma unroll
        for (int m = 0; m < PNM; m++) {
            float kv = __expf(mem_kv[((0 * PNH + h) * PHD + d) * PNM + m] - rmax[d]) * rinv[d];
#pragma unroll
            for (int i = 0; i < 4; i++)
                macc[i] += kv * mem_kv[((1 * PNH + h) * PHD + eg + i) * PNM + m];
        }
    }
    u64 accp[2] = {0ull, 0ull};
    int pbase = tc * 512;
    for (int t = 0; t < 8; t++) {
        int p0 = pbase + t * 64;
#pragma unroll
        for (int i = 0; i < 2; i++) {
            int f4 = tid + i * 256;
            int r = f4 >> 4, c4 = (f4 & 15) << 2;
            float4 v = *reinterpret_cast<const float4*>(
                &g_qkv[((size_t)b * QROWS + PHID + h * PHD + r) * PN + p0 + c4]);
            float mx = rmax[r], ri = rinv[r];
            Ks[r][c4 + 0] = __expf(v.x - mx) * ri;
            Ks[r][c4 + 1] = __expf(v.y - mx) * ri;
            Ks[r][c4 + 2] = __expf(v.z - mx) * ri;
            Ks[r][c4 + 3] = __expf(v.w - mx) * ri;
        }
#pragma unroll
        for (int i = 0; i < 2; i++) {
            int f4 = tid + i * 256;
            int r = f4 >> 4, c4 = (f4 & 15) << 2;
            float4 v = *reinterpret_cast<const float4*>(
                &g_qkv[((size_t)b * QROWS + 2 * PHID + h * PHD + r) * PN + p0 + c4]);
            Vt[c4 + 0][r] = v.x; Vt[c4 + 1][r] = v.y;
            Vt[c4 + 2][r] = v.z; Vt[c4 + 3][r] = v.w;
        }
        __syncthreads();
#pragma unroll
        for (int n = 0; n < 64; n++) {
            u64 kv2 = pack2(Ks[d][n], Ks[d][n]);
            u64 v0 = *reinterpret_cast<const u64*>(&Vt[n][eg]);
            u64 v1 = *reinterpret_cast<const u64*>(&Vt[n][eg + 2]);
            accp[0] = fma2(kv2, v0, accp[0]);
            accp[1] = fma2(kv2, v1, accp[1]);
        }
        __syncthreads();
    }
    size_t base = ((size_t)(b * PNH + h) * PHD + d) * PHD + eg;
    float2 p0 = unpack2(accp[0]);
    float2 p1 = unpack2(accp[1]);
    g_ctxp[tc][base + 0] = p0.x + macc[0];
    g_ctxp[tc][base + 1] = p0.y + macc[1];
    g_ctxp[tc][base + 2] = p1.x + macc[2];
    g_ctxp[tc][base + 3] = p1.y + macc[3];
}

// ---------------- K4: reduce partials + fold M = w_out . ctx -> bf16 hi/lo ----------------
__global__ void k_fold(const float* __restrict__ w_out) {
    __shared__ float ctx[PNH * PHD * PHD];
    int b = blockIdx.x;
    int tid = threadIdx.x;
    for (int idx = tid; idx < PNH * PHD * PHD; idx += 256) {
        float s = 0.0f;
#pragma unroll
        for (int tc = 0; tc < 8; tc++) s += g_ctxp[tc][b * (PNH * PHD * PHD) + idx];
        ctx[idx] = s;
    }
    __syncthreads();
    int o = tid;
    for (int h = 0; h < PNH; h++) {
        float w[PHD];
#pragma unroll
        for (int e = 0; e < PHD; e++) w[e] = w_out[o * PHID + h * PHD + e];
        for (int dd = 0; dd < PHD; dd++) {
            float s = 0.0f;
#pragma unroll
            for (int e = 0; e < PHD; e++) s += w[e] * ctx[(h * PHD + dd) * PHD + e];
            unsigned hb = bf16_rn(s);
            unsigned lb = bf16_rn(s - bf16_tof(hb));
            int idx = (b * PC + o) * PHID + h * PHD + dd;
            g_Mh[idx] = (unsigned short)hb;
            g_Ml[idx] = (unsigned short)lb;
        }
    }
}

// ---------------- K5: fused q-softmax + output GEMM (HMMA) + bias + RMS norm ----------------
// CTA: o=256 x p=64.  2 kc rounds; per round stage Mh+Ml, 3 in-register term combos.
// dyn smem: Qh0 @0, Qh1 @8192, Ql0 @16384, Ql1 @24576, Mh @32768 (32KB, overlaps f32 qload),
//           Ml @65536 (32KB), red @98304 (1KB), invr @99328 (256B) -> 99584 B
#define OUT_SMEM 99584
__global__ void __launch_bounds__(256, 2) k_out_mma(
    const float* __restrict__ b_out,
    const float* __restrict__ g_out,
    float* __restrict__ out) {
    extern __shared__ char dyn[];
    u32 base = smem_u32(dyn);
    float* msf = reinterpret_cast<float*>(dyn + 32768);   // f32 q load region (reused as Mh stage)
    float* red = reinterpret_cast<float*>(dyn + 98304);   // [4][64]
    float* invr = reinterpret_cast<float*>(dyn + 99328);  // [64]
    int tid = threadIdx.x, lane = tid & 31, wid = tid >> 5;
    int p0 = blockIdx.x * 64, b = blockIdx.y;

    // --- load q f32 tile [128 rows][64 pixels] ---
#pragma unroll
    for (int i = 0; i < 8; i++) {
        int f4 = tid + i * 256;                 // 2048 float4
        int r = f4 >> 4, c4 = (f4 & 15) << 2;
        *reinterpret_cast<float4*>(&msf[r * 64 + c4]) =
            *reinterpret_cast<const float4*>(&g_qkv[((size_t)b * QROWS + r) * PN + p0 + c4]);
    }
    __syncthreads();

    // --- softmax over head_dim per (head, pixel); write bf16 hi/lo Q tiles ---
    {
        int p = tid & 63, h = tid >> 6;          // 4 heads x 64 pixels
        float e[PHD];
        float m = -1e30f;
#pragma unroll
        for (int dd = 0; dd < PHD; dd++) m = fmaxf(m, msf[(h * PHD + dd) * 64 + p]);
        float s = 0.0f;
#pragma unroll
        for (int dd = 0; dd < PHD; dd++) { e[dd] = __expf(msf[(h * PHD + dd) * 64 + p] - m); s += e[dd]; }
        float sc = 0.17677669529663687f / s;     // (1/sqrt(32)) / sumexp
        int kc = h >> 1;
        int klb = (h & 1) * 32;
        u32 qh_off = (u32)(kc * 8192);
        u32 ql_off = 16384u + (u32)(kc * 8192);
        __syncthreads();                          // msf reads complete before Mh staging reuse
#pragma unroll
        for (int dd = 0; dd < PHD; dd += 2) {
            float v0 = e[dd] * sc, v1 = e[dd + 1] * sc;
            unsigned h0 = bf16_rn(v0), h1 = bf16_rn(v1);
            unsigned l0 = bf16_rn(v0 - bf16_tof(h0));
            unsigned l1 = bf16_rn(v1 - bf16_tof(h1));
            u32 bo = (u32)(p * 128 + (klb + dd) * 2);
            bo ^= (bo >> 3) & 0x70;
            *reinterpret_cast<u32*>(dyn + qh_off + bo) = (h1 << 16) | h0;
            *reinterpret_cast<u32*>(dyn + ql_off + bo) = (l1 << 16) | l0;
        }
    }
    __syncthreads();

    // --- GEMM: 8 warps = 4(m: 64 rows) x 2(n: 32 cols) ---
    int wm = wid & 3, wn = wid >> 2;
    float acc[4][4][4];
#pragma unroll
    for (int im = 0; im < 4; im++)
#pragma unroll
        for (int jn = 0; jn < 4; jn++)
#pragma unroll
            for (int q = 0; q < 4; q++) acc[im][jn][q] = 0.0f;

    u32 a_off[4], b_off[2];
#pragma unroll
    for (int im = 0; im < 4; im++) {
        int arow = wm * 64 + im * 16 + (lane & 15);
        u32 bo = (u32)(arow * 128) + ((lane >> 4) << 4);
        a_off[im] = bo ^ ((bo >> 3) & 0x70);
    }
#pragma unroll
    for (int j2 = 0; j2 < 2; j2++) {
        int nrow = wn * 32 + j2 * 16 + ((lane >> 4) << 3) + (lane & 7);
        u32 bo = (u32)(nrow * 128) + (((lane >> 3) & 1) << 4);
        b_off[j2] = bo ^ ((bo >> 3) & 0x70);
    }
    u32 mh_base = base + 32768u, ml_base = base + 65536u;

    for (int kc = 0; kc < 2; kc++) {
        u32 qh = base + (u32)(kc * 8192);
        u32 ql = base + 16384u + (u32)(kc * 8192);
        // stage Mh + Ml chunks [256 rows][64 k] bf16, SW128 swizzled
#pragma unroll
        for (int i = 0; i < 8; i++) {
            int u = tid + i * 256;                // 2048 uint4 each
            int r = u >> 3, c8 = (u & 7) << 3;
            u32 bo = (u32)((r << 7) + (c8 << 1));
            bo ^= (bo >> 3) & 0x70;
            int gi = (b * PC + r) * PHID + kc * 64 + c8;
            *reinterpret_cast<uint4*>(dyn + 32768 + bo) =
                *reinterpret_cast<const uint4*>(&g_Mh[gi]);
            *reinterpret_cast<uint4*>(dyn + 65536 + bo) =
                *reinterpret_cast<const uint4*>(&g_Ml[gi]);
        }
        __syncthreads();
#pragma unroll
        for (int kk = 0; kk < 4; kk++) {
            u32 kadd = (u32)(kk * 32);
            u32 a[4][4];
#pragma unroll
            for (int im = 0; im < 4; im++) ldsm4(a[im], mh_base + (a_off[im] ^ kadd));
            u32 bh[4][2];
#pragma unroll
            for (int j2 = 0; j2 < 2; j2++) {
                u32 r4[4];
                ldsm4(r4, qh + (b_off[j2] ^ kadd));
                bh[2 * j2][0] = r4[0]; bh[2 * j2][1] = r4[1];
                bh[2 * j2 + 1][0] = r4[2]; bh[2 * j2 + 1][1] = r4[3];
            }
#pragma unroll
            for (int im = 0; im < 4; im++)
#pragma unroll
                for (int jn = 0; jn < 4; jn++)
                    mma16816(acc[im][jn], a[im], bh[jn]);
            // Mh * Ql
            {
                u32 bl[4][2];
#pragma unroll
                for (int j2 = 0; j2 < 2; j2++) {
                    u32 r4[4];
                    ldsm4(r4, ql + (b_off[j2] ^ kadd));
                    bl[2 * j2][0] = r4[0]; bl[2 * j2][1] = r4[1];
                    bl[2 * j2 + 1][0] = r4[2]; bl[2 * j2 + 1][1] = r4[3];
                }
#pragma unroll
                for (int im = 0; im < 4; im++)
#pragma unroll
                    for (int jn = 0; jn < 4; jn++)
                        mma16816(acc[im][jn], a[im], bl[jn]);
            }
            // Ml * Qh
            {
                u32 al[4][4];
#pragma unroll
                for (int im = 0; im < 4; im++) ldsm4(al[im], ml_base + (a_off[im] ^ kadd));
#pragma unroll
                for (int im = 0; im < 4; im++)
#pragma unroll
                    for (int jn = 0; jn < 4; jn++)
                        mma16816(acc[im][jn], al[im], bh[jn]);
            }
        }
        __syncthreads();
    }

    // --- epilogue: bias, per-pixel RMS over all 256 channels, g_out scale, store ---
    float bo0[4], bo8[4], go0[4], go8[4];
#pragma unroll
    for (int im = 0; im < 4; im++) {
        int r = wm * 64 + im * 16 + (lane >> 2);
        bo0[im] = b_out[r];  bo8[im] = b_out[r + 8];
        go0[im] = g_out[r];  go8[im] = g_out[r + 8];
    }
#pragma unroll
    for (int jn = 0; jn < 4; jn++) {
        float sq0 = 0.f, sq1 = 0.f;
#pragma unroll
        for (int im = 0; im < 4; im++) {
            acc[im][jn][0] += bo0[im]; acc[im][jn][1] += bo0[im];
            acc[im][jn][2] += bo8[im]; acc[im][jn][3] += bo8[im];
            sq0 += acc[im][jn][0] * acc[im][jn][0] + acc[im][jn][2] * acc[im][jn][2];
            sq1 += acc[im][jn][1] * acc[im][jn][1] + acc[im][jn][3] * acc[im][jn][3];
        }
#pragma unroll
        for (int off = 4; off < 32; off <<= 1) {
            sq0 += __shfl_xor_sync(0xffffffffu, sq0, off);
            sq1 += __shfl_xor_sync(0xffffffffu, sq1, off);
        }
        if (lane < 4) {
            int c = wn * 32 + jn * 8 + lane * 2;
            red[wm * 64 + c] = sq0;
            red[wm * 64 + c + 1] = sq1;
        }
    }
    __syncthreads();
    if (tid < 64) {
        float s = red[tid] + red[64 + tid] + red[128 + tid] + red[192 + tid];
        invr[tid] = 16.0f / fmaxf(sqrtf(s), 1e-12f);
    }
    __syncthreads();
#pragma unroll
    for (int im = 0; im < 4; im++) {
        int r = wm * 64 + im * 16 + (lane >> 2);
#pragma unroll
        for (int jn = 0; jn < 4; jn++) {
            int c = wn * 32 + jn * 8 + (lane & 3) * 2;
            float iv0 = invr[c], iv1 = invr[c + 1];
            float2 v0 = {acc[im][jn][0] * iv0 * go0[im], acc[im][jn][1] * iv1 * go0[im]};
            float2 v1 = {acc[im][jn][2] * iv0 * go8[im], acc[im][jn][3] * iv1 * go8[im]};
            *reinterpret_cast<float2*>(&out[((size_t)(b * PC + r)) * PN + p0 + c]) = v0;
            *reinterpret_cast<float2*>(&out[((size_t)(b * PC + r + 8)) * PN + p0 + c]) = v1;
        }
    }
}

// ---------------- launch ----------------
extern "C" void kernel_launch(void* const* d_in, const int* in_sizes, int n_in,
                              void* d_out, int out_size) {
    const float* x      = (const float*)d_in[0];
    const float* g_in   = (const float*)d_in[1];
    const float* mem_kv = (const float*)d_in[2];
    const float* w_qkv  = (const float*)d_in[3];
    const float* w_out  = (const float*)d_in[4];
    const float* b_out  = (const float*)d_in[5];
    const float* g_out  = (const float*)d_in[6];
    float* out = (float*)d_out;

    static int attr_done = 0;
    if (!attr_done) {
        cudaFuncSetAttribute(k_normx,   cudaFuncAttributeMaxDynamicSharedMemorySize, NORMX_SMEM);
        cudaFuncSetAttribute(k_qkv_mma, cudaFuncAttributeMaxDynamicSharedMemorySize, QKV_SMEM);
        cudaFuncSetAttribute(k_out_mma, cudaFuncAttributeMaxDynamicSharedMemorySize, OUT_SMEM);
        attr_done = 1;
    }

    k_convw  <<<QROWS, 256>>>(w_qkv, g_in);
    k_normx  <<<dim3(PN / 64, PB), 256, NORMX_SMEM>>>(x);
    k_qkv_mma<<<dim3(PN / 128, QROWS / 128, PB), 256, QKV_SMEM>>>();
    k_kstats <<<512, 128>>>(mem_kv);
    k_context<<<dim3(8, PNH, PB), 256>>>(mem_kv);
    k_fold   <<<PB, 256>>>(w_out);
    k_out_mma<<<dim3(PN / 64, PB), 256, OUT_SMEM>>>(b_out, g_out, out);
}

// round 13
// speedup vs baseline: 1.8041x; 1.1288x over previous
#include <cuda_runtime.h>
#include <cuda_fp16.h>
#include <math.h>
#include <stdint.h>

// Problem constants
#define PB   16      // batch
#define PC   256     // channels
#define PN   4096    // H*W
#define PNH  4       // heads
#define PHD  32      // head dim
#define PNM  4       // memory tokens
#define PHID 128     // NH*HD
#define QROWS 384    // 3*HID

typedef unsigned long long u64;
typedef unsigned int u32;

// ---------------- scratch (static device memory; no allocation) ----------------
__device__ unsigned short g_wh[QROWS * PC];            // fp16 hi of scaled qkv weights
__device__ unsigned short g_wl[QROWS * PC];            // fp16 lo
__device__ unsigned short g_xh[(size_t)PB * PN * PC];  // fp16 of normalized x, [b][n][c]
__device__ float g_qkv[(size_t)PB * QROWS * PN];       // qkv activations (~100 MB)
__device__ float g_stat[2][PB * PNH * PHD];            // k softmax: rowmax, 1/rowsum
__device__ float g_ctxp[8][PB * PNH * PHD * PHD];      // partial contexts (8 token chunks)
__device__ unsigned short g_Mh[PB * PC * PHID];        // folded M = w_out . ctx, fp16 hi
__device__ unsigned short g_Ml[PB * PC * PHID];        // fp16 lo

// ---------------- small helpers ----------------
__device__ __forceinline__ u32 f16_rn(float v) {
    return (u32)__half_as_ushort(__float2half_rn(v));
}
__device__ __forceinline__ float f16_tof(u32 b) {
    return __half2float(__ushort_as_half((unsigned short)b));
}

__device__ __forceinline__ u32 smem_u32(const void* p) {
    u32 a;
    asm("{ .reg .u64 t; cvta.to.shared.u64 t, %1; cvt.u32.u64 %0, t; }" : "=r"(a) : "l"(p));
    return a;
}

// f32x2 packed helpers (k_context)
__device__ __forceinline__ u64 fma2(u64 a, u64 b, u64 c) {
    u64 d; asm("fma.rn.f32x2 %0, %1, %2, %3;" : "=l"(d) : "l"(a), "l"(b), "l"(c)); return d;
}
__device__ __forceinline__ u64 pack2(float lo, float hi) {
    u64 r; asm("mov.b64 %0, {%1, %2};" : "=l"(r) : "f"(lo), "f"(hi)); return r;
}
__device__ __forceinline__ float2 unpack2(u64 v) {
    float2 r; asm("mov.b64 {%0, %1}, %2;" : "=f"(r.x), "=f"(r.y) : "l"(v)); return r;
}

// ---------------- HMMA helpers (baseline ISA: ldmatrix + mma.sync + cp.async) ----------------
__device__ __forceinline__ void ldsm4(u32* r, u32 addr) {
    asm volatile("ldmatrix.sync.aligned.m8n8.x4.shared.b16 {%0,%1,%2,%3}, [%4];"
                 : "=r"(r[0]), "=r"(r[1]), "=r"(r[2]), "=r"(r[3]) : "r"(addr));
}
__device__ __forceinline__ void mma16816(float* d, const u32* a, const u32* b) {
    asm volatile(
        "mma.sync.aligned.m16n8k16.row.col.f32.f16.f16.f32 "
        "{%0,%1,%2,%3}, {%4,%5,%6,%7}, {%8,%9}, {%0,%1,%2,%3};"
        : "+f"(d[0]), "+f"(d[1]), "+f"(d[2]), "+f"(d[3])
        : "r"(a[0]), "r"(a[1]), "r"(a[2]), "r"(a[3]), "r"(b[0]), "r"(b[1]));
}
__device__ __forceinline__ void cpa16(u32 dst, const void* src) {
    asm volatile("cp.async.ca.shared.global [%0], [%1], 16;" :: "r"(dst), "l"(src));
}
__device__ __forceinline__ void cpa_commit() {
    asm volatile("cp.async.commit_group;" ::: "memory");
}
__device__ __forceinline__ void cpa_wait1() {
    asm volatile("cp.async.wait_group 1;" ::: "memory");
}
__device__ __forceinline__ void cpa_wait0() {
    asm volatile("cp.async.wait_group 0;" ::: "memory");
}

// ---------------- K0a: weight convert  fp16 hi/lo of (w_qkv * g_in * sqrt(C)) ----------------
__global__ void k_convw(const float* __restrict__ w_qkv, const float* __restrict__ g_in) {
    int i = blockIdx.x * 256 + threadIdx.x;    // i = row*256 + c
    if (i < QROWS * PC) {
        int c = i & 255;
        float v = w_qkv[i] * g_in[c] * 16.0f;  // sqrt(256) = 16
        u32 hb = f16_rn(v);
        u32 lb = f16_rn(v - f16_tof(hb));
        g_wh[i] = (unsigned short)hb;
        g_wl[i] = (unsigned short)lb;
    }
}

// ---------------- K0b: fused channel-RMS + transpose + fp16 convert (hi only) ----------------
// Per block: 64 pixels x all 256 channels.  xh gets x * invn folded in.
// dyn smem: xs[256][66] f32 @0 (67584 B), ss[4][64] @67584, inv[64] @68608 -> 68864 B
#define NORMX_SMEM 68864
__global__ void __launch_bounds__(256) k_normx(const float* __restrict__ x) {
    extern __shared__ char dsm[];
    float* xs = reinterpret_cast<float*>(dsm);            // [c][p], pitch 66
    float* ss = reinterpret_cast<float*>(dsm + 67584);    // [4][64]
    float* inv = reinterpret_cast<float*>(dsm + 68608);   // [64]
    int n0 = blockIdx.x * 64, b = blockIdx.y;
    int tid = threadIdx.x;

    // load x [256 c][64 p]
#pragma unroll
    for (int i = 0; i < 16; i++) {
        int f4 = tid + i * 256;                 // 4096 float4
        int c = f4 >> 4, p4 = (f4 & 15) << 2;
        float4 v = *reinterpret_cast<const float4*>(
            &x[((size_t)b * PC + c) * PN + n0 + p4]);
        float* row = &xs[c * 66 + p4];
        row[0] = v.x; row[1] = v.y; row[2] = v.z; row[3] = v.w;
    }
    __syncthreads();

    // per-pixel sum of squares (4 threads per pixel)
    {
        int p = tid & 63, q = tid >> 6;
        float s = 0.0f;
#pragma unroll 8
        for (int c2 = 0; c2 < 64; c2++) {
            float v = xs[(q * 64 + c2) * 66 + p];
            s += v * v;
        }
        ss[q * 64 + p] = s;
    }
    __syncthreads();
    if (tid < 64) {
        float s = ss[tid] + ss[64 + tid] + ss[128 + tid] + ss[192 + tid];
        inv[tid] = 1.0f / fmaxf(sqrtf(s), 1e-12f);
    }
    __syncthreads();

    // write transposed fp16: [b][n][c], invn folded
#pragma unroll
    for (int i = 0; i < 32; i++) {
        int e2 = tid + i * 256;                 // 8192 pairs
        int n_ = e2 >> 7, cp = (e2 & 127) << 1;
        float iv = inv[n_];
        float v0 = xs[cp * 66 + n_] * iv;
        float v1 = xs[(cp + 1) * 66 + n_] * iv;
        u32 h0 = f16_rn(v0), h1 = f16_rn(v1);
        size_t e = ((size_t)b * PN + n0 + n_) * PC + cp;
        reinterpret_cast<u32*>(g_xh)[e >> 1] = (h1 << 16) | h0;
    }
}

// ---------------- K2: qkv GEMM on HMMA; 2-term fp16 ((Wh+Wl)*Xh) ----------------
// CTA: D[128 m x 128 n]; 8 warps 4(m)x2(n); 8 chunks of 32 channels.
// A tiles hold [hi(bytes 0-63) | lo(bytes 64-127)]; B tiles hi only (bytes 0-63).
// dyn smem: stage s at s*32768 (A @+0, B @+16384), 3 stages -> 98304 B
#define QKV_SMEM 98304
__global__ void __launch_bounds__(256, 2) k_qkv_mma() {
    extern __shared__ char dyn[];
    u32 base = smem_u32(dyn);
    int tid = threadIdx.x, lane = tid & 31, wid = tid >> 5;
    int nb = blockIdx.x * 128, mb = blockIdx.y * 128, b = blockIdx.z;
    int wm = (wid & 3) * 32, wn = (wid >> 2) * 64;

    float acc[2][8][4];
#pragma unroll
    for (int im = 0; im < 2; im++)
#pragma unroll
        for (int jn = 0; jn < 8; jn++)
#pragma unroll
            for (int q = 0; q < 4; q++) acc[im][jn][q] = 0.0f;

    // per-thread staging: A = [hi|lo]; B = hi only (skip c8>=32)
    u32 st_bo[4];
    const unsigned short* st_wsrc[4];
    const unsigned short* st_xsrc[4];
    bool st_xok[4];
#pragma unroll
    for (int i = 0; i < 4; i++) {
        int u = tid + i * 256;
        int r = u >> 3, c8 = (u & 7) << 3;
        u32 bo = (u32)((r << 7) + (c8 << 1));
        st_bo[i] = bo ^ ((bo >> 3) & 0x70);
        if (c8 < 32) {
            st_wsrc[i] = &g_wh[(size_t)(mb + r) * PC + c8];
            st_xsrc[i] = &g_xh[((size_t)b * PN + nb + r) * PC + c8];
            st_xok[i] = true;
        } else {
            st_wsrc[i] = &g_wl[(size_t)(mb + r) * PC + c8 - 32];
            st_xsrc[i] = 0;
            st_xok[i] = false;
        }
    }
    // ldmatrix offsets (swizzled, kadd=0)
    u32 a_off[2], b_off[4];
#pragma unroll
    for (int im = 0; im < 2; im++) {
        int arow = wm + im * 16 + (lane & 15);
        u32 bo = (u32)(arow * 128) + ((lane >> 4) << 4);
        a_off[im] = bo ^ ((bo >> 3) & 0x70);
    }
#pragma unroll
    for (int j2 = 0; j2 < 4; j2++) {
        int nrow = wn + j2 * 16 + ((lane >> 4) << 3) + (lane & 7);
        u32 bo = (u32)(nrow * 128) + (((lane >> 3) & 1) << 4);
        b_off[j2] = bo ^ ((bo >> 3) & 0x70);
    }

    // prologue: stage chunks 0, 1
#pragma unroll
    for (int s = 0; s < 2; s++) {
        u32 sb = base + (u32)(s * 32768);
        int co = s * 32;
#pragma unroll
        for (int i = 0; i < 4; i++) {
            cpa16(sb + st_bo[i], st_wsrc[i] + co);
            if (st_xok[i]) cpa16(sb + 16384 + st_bo[i], st_xsrc[i] + co);
        }
        cpa_commit();
    }

    for (int ch = 0; ch < 8; ch++) {
        if (ch < 7) cpa_wait1(); else cpa_wait0();
        __syncthreads();
        if (ch + 2 < 8) {
            u32 sb = base + (u32)(((ch + 2) % 3) * 32768);
            int co = (ch + 2) * 32;
#pragma unroll
            for (int i = 0; i < 4; i++) {
                cpa16(sb + st_bo[i], st_wsrc[i] + co);
                if (st_xok[i]) cpa16(sb + 16384 + st_bo[i], st_xsrc[i] + co);
            }
            cpa_commit();
        }
        u32 aU = base + (u32)((ch % 3) * 32768);
        u32 bU = aU + 16384u;
#pragma unroll
        for (int kkh = 0; kkh < 2; kkh++) {
            u32 kA = (u32)(kkh * 32);   // hi bytes [0,64); lo at ^(kA+64)
            u32 ah[2][4];
            ldsm4(ah[0], aU + (a_off[0] ^ kA));
            ldsm4(ah[1], aU + (a_off[1] ^ kA));
            u32 al[2][4];
            ldsm4(al[0], aU + (a_off[0] ^ (kA + 64)));
            ldsm4(al[1], aU + (a_off[1] ^ (kA + 64)));
            u32 bh[8][2];
#pragma unroll
            for (int j2 = 0; j2 < 4; j2++) {
                u32 r4[4];
                ldsm4(r4, bU + (b_off[j2] ^ kA));
                bh[2 * j2][0] = r4[0]; bh[2 * j2][1] = r4[1];
                bh[2 * j2 + 1][0] = r4[2]; bh[2 * j2 + 1][1] = r4[3];
            }
#pragma unroll
            for (int im = 0; im < 2; im++)
#pragma unroll
                for (int jn = 0; jn < 8; jn++)
                    mma16816(acc[im][jn], ah[im], bh[jn]);
#pragma unroll
            for (int im = 0; im < 2; im++)
#pragma unroll
                for (int jn = 0; jn < 8; jn++)
                    mma16816(acc[im][jn], al[im], bh[jn]);
        }
    }

    // epilogue: store float2 per atom-half (invn already folded into x)
    int r0 = wm + (lane >> 2);
    int cb = wn + (lane & 3) * 2;
#pragma unroll
    for (int im = 0; im < 2; im++) {
#pragma unroll
        for (int jn = 0; jn < 8; jn++) {
            int c = cb + jn * 8;
            size_t rowA = (size_t)b * QROWS + mb + r0 + im * 16;
            float2 v0 = {acc[im][jn][0], acc[im][jn][1]};
            float2 v1 = {acc[im][jn][2], acc[im][jn][3]};
            *reinterpret_cast<float2*>(&g_qkv[rowA * PN + nb + c]) = v0;
            *reinterpret_cast<float2*>(&g_qkv[(rowA + 8) * PN + nb + c]) = v1;
        }
    }
}

// ---------------- K3a: k row softmax stats ----------------
__global__ void k_kstats(const float* __restrict__ mem_kv) {
    int gwarp = (blockIdx.x * blockDim.x + threadIdx.x) >> 5;
    int lane = threadIdx.x & 31;
    if (gwarp >= PB * PNH * PHD) return;
    int d = gwarp & 31, h = (gwarp >> 5) & 3, b = gwarp >> 7;
    const float* krow = &g_qkv[((size_t)b * QROWS + PHID + h * PHD + d) * PN];

    float m0 = -1e30f, m1 = -1e30f, m2 = -1e30f, m3 = -1e30f;
    for (int p = lane; p < PN; p += 128) {
        m0 = fmaxf(m0, krow[p]);
        m1 = fmaxf(m1, krow[p + 32]);
        m2 = fmaxf(m2, krow[p + 64]);
        m3 = fmaxf(m3, krow[p + 96]);
    }
    float m = fmaxf(fmaxf(m0, m1), fmaxf(m2, m3));
    if (lane < PNM)
        m = fmaxf(m, mem_kv[((0 * PNH + h) * PHD + d) * PNM + lane]);
#pragma unroll
    for (int o = 16; o > 0; o >>= 1)
        m = fmaxf(m, __shfl_xor_sync(0xffffffffu, m, o));

    float s0 = 0.f, s1 = 0.f, s2 = 0.f, s3 = 0.f;
    for (int p = lane; p < PN; p += 128) {
        s0 += __expf(krow[p] - m);
        s1 += __expf(krow[p + 32] - m);
        s2 += __expf(krow[p + 64] - m);
        s3 += __expf(krow[p + 96] - m);
    }
    float s = (s0 + s1) + (s2 + s3);
    if (lane < PNM)
        s += __expf(mem_kv[((0 * PNH + h) * PHD + d) * PNM + lane] - m);
#pragma unroll
    for (int o = 16; o > 0; o >>= 1)
        s += __shfl_xor_sync(0xffffffffu, s, o);
    if (lane == 0) { g_stat[0][gwarp] = m; g_stat[1][gwarp] = 1.0f / s; }
}

// ---------------- K3b: partial context ----------------
__global__ void k_context(const float* __restrict__ mem_kv) {
    __shared__ float Ks[PHD][68];
    __shared__ float Vt[64][34];
    __shared__ float rmax[PHD], rinv[PHD];
    int tc = blockIdx.x, h = blockIdx.y, b = blockIdx.z;
    int tid = threadIdx.x;
    if (tid < PHD) {
        int rowid = (b * PNH + h) * PHD + tid;
        rmax[tid] = g_stat[0][rowid];
        rinv[tid] = g_stat[1][rowid];
    }
    __syncthreads();
    int d = tid >> 3;
    int eg = (tid & 7) << 2;
    float macc[4] = {0.f, 0.f, 0.f, 0.f};
    if (tc == 0) {
#pragma unroll
        for (int m = 0; m < PNM; m++) {
            float kv = __expf(mem_kv[((0 * PNH + h) * PHD + d) * PNM + m] - rmax[d]) * rinv[d];
#pragma unroll
            for (int i = 0; i < 4; i++)
                macc[i] += kv * mem_kv[((1 * PNH + h) * PHD + eg + i) * PNM + m];
        }
    }
    u64 accp[2] = {0ull, 0ull};
    int pbase = tc * 512;
    for (int t = 0; t < 8; t++) {
        int p0 = pbase + t * 64;
#pragma unroll
        for (int i = 0; i < 2; i++) {
            int f4 = tid + i * 256;
            int r = f4 >> 4, c4 = (f4 & 15) << 2;
            float4 v = *reinterpret_cast<const float4*>(
                &g_qkv[((size_t)b * QROWS + PHID + h * PHD + r) * PN + p0 + c4]);
            float mx = rmax[r], ri = rinv[r];
            Ks[r][c4 + 0] = __expf(v.x - mx) * ri;
            Ks[r][c4 + 1] = __expf(v.y - mx) * ri;
            Ks[r][c4 + 2] = __expf(v.z - mx) * ri;
            Ks[r][c4 + 3] = __expf(v.w - mx) * ri;
        }
#pragma unroll
        for (int i = 0; i < 2; i++) {
            int f4 = tid + i * 256;
            int r = f4 >> 4, c4 = (f4 & 15) << 2;
            float4 v = *reinterpret_cast<const float4*>(
                &g_qkv[((size_t)b * QROWS + 2 * PHID + h * PHD + r) * PN + p0 + c4]);
            Vt[c4 + 0][r] = v.x; Vt[c4 + 1][r] = v.y;
            Vt[c4 + 2][r] = v.z; Vt[c4 + 3][r] = v.w;
        }
        __syncthreads();
#pragma unroll
        for (int n = 0; n < 64; n++) {
            u64 kv2 = pack2(Ks[d][n], Ks[d][n]);
            u64 v0 = *reinterpret_cast<const u64*>(&Vt[n][eg]);
            u64 v1 = *reinterpret_cast<const u64*>(&Vt[n][eg + 2]);
            accp[0] = fma2(kv2, v0, accp[0]);
            accp[1] = fma2(kv2, v1, accp[1]);
        }
        __syncthreads();
    }
    size_t base = ((size_t)(b * PNH + h) * PHD + d) * PHD + eg;
    float2 p0 = unpack2(accp[0]);
    float2 p1 = unpack2(accp[1]);
    g_ctxp[tc][base + 0] = p0.x + macc[0];
    g_ctxp[tc][base + 1] = p0.y + macc[1];
    g_ctxp[tc][base + 2] = p1.x + macc[2];
    g_ctxp[tc][base + 3] = p1.y + macc[3];
}

// ---------------- K4: reduce partials + fold M = w_out . ctx -> fp16 hi/lo ----------------
__global__ void k_fold(const float* __restrict__ w_out) {
    __shared__ float ctx[PNH * PHD * PHD];
    int b = blockIdx.x;
    int tid = threadIdx.x;
    for (int idx = tid; idx < PNH * PHD * PHD; idx += 256) {
        float s = 0.0f;
#pragma unroll
        for (int tc = 0; tc < 8; tc++) s += g_ctxp[tc][b * (PNH * PHD * PHD) + idx];
        ctx[idx] = s;
    }
    __syncthreads();
    int o = tid;
    for (int h = 0; h < PNH; h++) {
        float w[PHD];
#pragma unroll
        for (int e = 0; e < PHD; e++) w[e] = w_out[o * PHID + h * PHD + e];
        for (int dd = 0; dd < PHD; dd++) {
            float s = 0.0f;
#pragma unroll
            for (int e = 0; e < PHD; e++) s += w[e] * ctx[(h * PHD + dd) * PHD + e];
            u32 hb = f16_rn(s);
            u32 lb = f16_rn(s - f16_tof(hb));
            int idx = (b * PC + o) * PHID + h * PHD + dd;
            g_Mh[idx] = (unsigned short)hb;
            g_Ml[idx] = (unsigned short)lb;
        }
    }
}

// ---------------- K5: fused q-softmax + output GEMM (HMMA) + bias + RMS norm ----------------
// CTA: o=256 x p=64.  2 kc rounds; 2-term fp16: (Mh+Ml) * Qh.
// dyn smem: Qh0 @0, Qh1 @8192, (16384..32768 unused), Mh @32768 (32KB, overlaps f32 qload),
//           Ml @65536 (32KB), red @98304 (1KB), invr @99328 (256B) -> 99584 B
#define OUT_SMEM 99584
__global__ void __launch_bounds__(256, 2) k_out_mma(
    const float* __restrict__ b_out,
    const float* __restrict__ g_out,
    float* __restrict__ out) {
    extern __shared__ char dyn[];
    u32 base = smem_u32(dyn);
    float* msf = reinterpret_cast<float*>(dyn + 32768);   // f32 q load region (reused as Mh stage)
    float* red = reinterpret_cast<float*>(dyn + 98304);   // [4][64]
    float* invr = reinterpret_cast<float*>(dyn + 99328);  // [64]
    int tid = threadIdx.x, lane = tid & 31, wid = tid >> 5;
    int p0 = blockIdx.x * 64, b = blockIdx.y;

    // --- load q f32 tile [128 rows][64 pixels] ---
#pragma unroll
    for (int i = 0; i < 8; i++) {
        int f4 = tid + i * 256;                 // 2048 float4
        int r = f4 >> 4, c4 = (f4 & 15) << 2;
        *reinterpret_cast<float4*>(&msf[r * 64 + c4]) =
            *reinterpret_cast<const float4*>(&g_qkv[((size_t)b * QROWS + r) * PN + p0 + c4]);
    }
    __syncthreads();

    // --- softmax over head_dim per (head, pixel); write fp16 Q tiles (hi only) ---
    {
        int p = tid & 63, h = tid >> 6;          // 4 heads x 64 pixels
        float e[PHD];
        float m = -1e30f;
#pragma unroll
        for (int dd = 0; dd < PHD; dd++) m = fmaxf(m, msf[(h * PHD + dd) * 64 + p]);
        float s = 0.0f;
#pragma unroll
        for (int dd = 0; dd < PHD; dd++) { e[dd] = __expf(msf[(h * PHD + dd) * 64 + p] - m); s += e[dd]; }
        float sc = 0.17677669529663687f / s;     // (1/sqrt(32)) / sumexp
        int kc = h >> 1;
        int klb = (h & 1) * 32;
        u32 qh_off = (u32)(kc * 8192);
        __syncthreads();                          // msf reads complete before Mh staging reuse
#pragma unroll
        for (int dd = 0; dd < PHD; dd += 2) {
            float v0 = e[dd] * sc, v1 = e[dd + 1] * sc;
            u32 h0 = f16_rn(v0), h1 = f16_rn(v1);
            u32 bo = (u32)(p * 128 + (klb + dd) * 2);
            bo ^= (bo >> 3) & 0x70;
            *reinterpret_cast<u32*>(dyn + qh_off + bo) = (h1 << 16) | h0;
        }
    }
    __syncthreads();

    // --- GEMM: 8 warps = 4(m: 64 rows) x 2(n: 32 cols) ---
    int wm = wid & 3, wn = wid >> 2;
    float acc[4][4][4];
#pragma unroll
    for (int im = 0; im < 4; im++)
#pragma unroll
        for (int jn = 0; jn < 4; jn++)
#pragma unroll
            for (int q = 0; q < 4; q++) acc[im][jn][q] = 0.0f;

    u32 a_off[4], b_off[2];
#pragma unroll
    for (int im = 0; im < 4; im++) {
        int arow = wm * 64 + im * 16 + (lane & 15);
        u32 bo = (u32)(arow * 128) + ((lane >> 4) << 4);
        a_off[im] = bo ^ ((bo >> 3) & 0x70);
    }
#pragma unroll
    for (int j2 = 0; j2 < 2; j2++) {
        int nrow = wn * 32 + j2 * 16 + ((lane >> 4) << 3) + (lane & 7);
        u32 bo = (u32)(nrow * 128) + (((lane >> 3) & 1) << 4);
        b_off[j2] = bo ^ ((bo >> 3) & 0x70);
    }
    u32 mh_base = base + 32768u, ml_base = base + 65536u;

    for (int kc = 0; kc < 2; kc++) {
        u32 qh = base + (u32)(kc * 8192);
        // stage Mh + Ml chunks [256 rows][64 k] fp16, SW128 swizzled
#pragma unroll
        for (int i = 0; i < 8; i++) {
            int u = tid + i * 256;                // 2048 uint4 each
            int r = u >> 3, c8 = (u & 7) << 3;
            u32 bo = (u32)((r << 7) + (c8 << 1));
            bo ^= (bo >> 3) & 0x70;
            int gi = (b * PC + r) * PHID + kc * 64 + c8;
            *reinterpret_cast<uint4*>(dyn + 32768 + bo) =
                *reinterpret_cast<const uint4*>(&g_Mh[gi]);
            *reinterpret_cast<uint4*>(dyn + 65536 + bo) =
                *reinterpret_cast<const uint4*>(&g_Ml[gi]);
        }
        __syncthreads();
#pragma unroll
        for (int kk = 0; kk < 4; kk++) {
            u32 kadd = (u32)(kk * 32);
            u32 a[4][4];
#pragma unroll
            for (int im = 0; im < 4; im++) ldsm4(a[im], mh_base + (a_off[im] ^ kadd));
            u32 al[4][4];
#pragma unroll
            for (int im = 0; im < 4; im++) ldsm4(al[im], ml_base + (a_off[im] ^ kadd));
            u32 bh[4][2];
#pragma unroll
            for (int j2 = 0; j2 < 2; j2++) {
                u32 r4[4];
                ldsm4(r4, qh + (b_off[j2] ^ kadd));
                bh[2 * j2][0] = r4[0]; bh[2 * j2][1] = r4[1];
                bh[2 * j2 + 1][0] = r4[2]; bh[2 * j2 + 1][1] = r4[3];
            }
#pragma unroll
            for (int im = 0; im < 4; im++)
#pragma unroll
                for (int jn = 0; jn < 4; jn++)
                    mma16816(acc[im][jn], a[im], bh[jn]);
#pragma unroll
            for (int im = 0; im < 4; im++)
#pragma unroll
                for (int jn = 0; jn < 4; jn++)
                    mma16816(acc[im][jn], al[im], bh[jn]);
        }
        __syncthreads();
    }

    // --- epilogue: bias, per-pixel RMS over all 256 channels, g_out scale, store ---
    float bo0[4], bo8[4], go0[4], go8[4];
#pragma unroll
    for (int im = 0; im < 4; im++) {
        int r = wm * 64 + im * 16 + (lane >> 2);
        bo0[im] = b_out[r];  bo8[im] = b_out[r + 8];
        go0[im] = g_out[r];  go8[im] = g_out[r + 8];
    }
#pragma unroll
    for (int jn = 0; jn < 4; jn++) {
        float sq0 = 0.f, sq1 = 0.f;
#pragma unroll
        for (int im = 0; im < 4; im++) {
            acc[im][jn][0] += bo0[im]; acc[im][jn][1] += bo0[im];
            acc[im][jn][2] += bo8[im]; acc[im][jn][3] += bo8[im];
            sq0 += acc[im][jn][0] * acc[im][jn][0] + acc[im][jn][2] * acc[im][jn][2];
            sq1 += acc[im][jn][1] * acc[im][jn][1] + acc[im][jn][3] * acc[im][jn][3];
        }
#pragma unroll
        for (int off = 4; off < 32; off <<= 1) {
            sq0 += __shfl_xor_sync(0xffffffffu, sq0, off);
            sq1 += __shfl_xor_sync(0xffffffffu, sq1, off);
        }
        if (lane < 4) {
            int c = wn * 32 + jn * 8 + lane * 2;
            red[wm * 64 + c] = sq0;
            red[wm * 64 + c + 1] = sq1;
        }
    }
    __syncthreads();
    if (tid < 64) {
        float s = red[tid] + red[64 + tid] + red[128 + tid] + red[192 + tid];
        invr[tid] = 16.0f / fmaxf(sqrtf(s), 1e-12f);
    }
    __syncthreads();
#pragma unroll
    for (int im = 0; im < 4; im++) {
        int r = wm * 64 + im * 16 + (lane >> 2);
#pragma unroll
        for (int jn = 0; jn < 4; jn++) {
            int c = wn * 32 + jn * 8 + (lane & 3) * 2;
            float iv0 = invr[c], iv1 = invr[c + 1];
            float2 v0 = {acc[im][jn][0] * iv0 * go0[im], acc[im][jn][1] * iv1 * go0[im]};
            float2 v1 = {acc[im][jn][2] * iv0 * go8[im], acc[im][jn][3] * iv1 * go8[im]};
            *reinterpret_cast<float2*>(&out[((size_t)(b * PC + r)) * PN + p0 + c]) = v0;
            *reinterpret_cast<float2*>(&out[((size_t)(b * PC + r + 8)) * PN + p0 + c]) = v1;
        }
    }
}

// ---------------- launch ----------------
extern "C" void kernel_launch(void* const* d_in, const int* in_sizes, int n_in,
                              void* d_out, int out_size) {
    const float* x      = (const float*)d_in[0];
    const float* g_in   = (const float*)d_in[1];
    const float* mem_kv = (const float*)d_in[2];
    const float* w_qkv  = (const float*)d_in[3];
    const float* w_out  = (const float*)d_in[4];
    const float* b_out  = (const float*)d_in[5];
    const float* g_out  = (const float*)d_in[6];
    float* out = (float*)d_out;

    static int attr_done = 0;
    if (!attr_done) {
        cudaFuncSetAttribute(k_normx,   cudaFuncAttributeMaxDynamicSharedMemorySize, NORMX_SMEM);
        cudaFuncSetAttribute(k_qkv_mma, cudaFuncAttributeMaxDynamicSharedMemorySize, QKV_SMEM);
        cudaFuncSetAttribute(k_out_mma, cudaFuncAttributeMaxDynamicSharedMemorySize, OUT_SMEM);
        attr_done = 1;
    }

    k_convw  <<<QROWS, 256>>>(w_qkv, g_in);
    k_normx  <<<dim3(PN / 64, PB), 256, NORMX_SMEM>>>(x);
    k_qkv_mma<<<dim3(PN / 128, QROWS / 128, PB), 256, QKV_SMEM>>>();
    k_kstats <<<512, 128>>>(mem_kv);
    k_context<<<dim3(8, PNH, PB), 256>>>(mem_kv);
    k_fold   <<<PB, 256>>>(w_out);
    k_out_mma<<<dim3(PN / 64, PB), 256, OUT_SMEM>>>(b_out, g_out, out);
}

// round 15
// speedup vs baseline: 1.8247x; 1.0114x over previous
#include <cuda_runtime.h>
#include <cuda_fp16.h>
#include <math.h>
#include <stdint.h>

// Problem constants
#define PB   16      // batch
#define PC   256     // channels
#define PN   4096    // H*W
#define PNH  4       // heads
#define PHD  32      // head dim
#define PNM  4       // memory tokens
#define PHID 128     // NH*HD
#define QROWS 384    // 3*HID

typedef unsigned long long u64;
typedef unsigned int u32;

// ---------------- scratch (static device memory; no allocation) ----------------
__device__ unsigned short g_wh[QROWS * PC];            // fp16 hi of scaled qkv weights
__device__ unsigned short g_wl[QROWS * PC];            // fp16 lo
__device__ unsigned short g_xh[(size_t)PB * PN * PC];  // fp16 of normalized x, [b][n][c]
__device__ float g_q[(size_t)PB * PHID * PN];          // q activations f32 (~33 MB)
__device__ unsigned short g_kv16[(size_t)PB * 256 * PN]; // k rows 0-127, v rows 128-255, fp16 (~33 MB)
__device__ float g_stat[2][PB * PNH * PHD];            // k softmax: rowmax, 1/rowsum
__device__ float g_ctxp[8][PB * PNH * PHD * PHD];      // partial contexts (8 token chunks)
__device__ unsigned short g_Mh[PB * PC * PHID];        // folded M = w_out . ctx, fp16 hi
__device__ unsigned short g_Ml[PB * PC * PHID];        // fp16 lo

// ---------------- small helpers ----------------
__device__ __forceinline__ u32 f16_rn(float v) {
    return (u32)__half_as_ushort(__float2half_rn(v));
}
__device__ __forceinline__ float f16_tof(u32 b) {
    return __half2float(__ushort_as_half((unsigned short)b));
}

__device__ __forceinline__ u32 smem_u32(const void* p) {
    u32 a;
    asm("{ .reg .u64 t; cvta.to.shared.u64 t, %1; cvt.u32.u64 %0, t; }" : "=r"(a) : "l"(p));
    return a;
}

// f32x2 packed helpers (k_context)
__device__ __forceinline__ u64 fma2(u64 a, u64 b, u64 c) {
    u64 d; asm("fma.rn.f32x2 %0, %1, %2, %3;" : "=l"(d) : "l"(a), "l"(b), "l"(c)); return d;
}
__device__ __forceinline__ u64 pack2(float lo, float hi) {
    u64 r; asm("mov.b64 %0, {%1, %2};" : "=l"(r) : "f"(lo), "f"(hi)); return r;
}
__device__ __forceinline__ float2 unpack2(u64 v) {
    float2 r; asm("mov.b64 {%0, %1}, %2;" : "=f"(r.x), "=f"(r.y) : "l"(v)); return r;
}

// ---------------- HMMA helpers ----------------
__device__ __forceinline__ void ldsm4(u32* r, u32 addr) {
    asm volatile("ldmatrix.sync.aligned.m8n8.x4.shared.b16 {%0,%1,%2,%3}, [%4];"
                 : "=r"(r[0]), "=r"(r[1]), "=r"(r[2]), "=r"(r[3]) : "r"(addr));
}
__device__ __forceinline__ void mma16816(float* d, const u32* a, const u32* b) {
    asm volatile(
        "mma.sync.aligned.m16n8k16.row.col.f32.f16.f16.f32 "
        "{%0,%1,%2,%3}, {%4,%5,%6,%7}, {%8,%9}, {%0,%1,%2,%3};"
        : "+f"(d[0]), "+f"(d[1]), "+f"(d[2]), "+f"(d[3])
        : "r"(a[0]), "r"(a[1]), "r"(a[2]), "r"(a[3]), "r"(b[0]), "r"(b[1]));
}
__device__ __forceinline__ void cpa16(u32 dst, const void* src) {
    asm volatile("cp.async.ca.shared.global [%0], [%1], 16;" :: "r"(dst), "l"(src));
}
__device__ __forceinline__ void cpa_commit() {
    asm volatile("cp.async.commit_group;" ::: "memory");
}
__device__ __forceinline__ void cpa_wait1() {
    asm volatile("cp.async.wait_group 1;" ::: "memory");
}
__device__ __forceinline__ void cpa_wait0() {
    asm volatile("cp.async.wait_group 0;" ::: "memory");
}

// ---------------- K0a: weight convert  fp16 hi/lo of (w_qkv * g_in * sqrt(C)) ----------------
__global__ void k_convw(const float* __restrict__ w_qkv, const float* __restrict__ g_in) {
    int i = blockIdx.x * 256 + threadIdx.x;
    if (i < QROWS * PC) {
        int c = i & 255;
        float v = w_qkv[i] * g_in[c] * 16.0f;  // sqrt(256) = 16
        u32 hb = f16_rn(v);
        u32 lb = f16_rn(v - f16_tof(hb));
        g_wh[i] = (unsigned short)hb;
        g_wl[i] = (unsigned short)lb;
    }
}

// ---------------- K0b: fused channel-RMS + transpose + fp16 convert ----------------
#define NORMX_SMEM 68864
__global__ void __launch_bounds__(256) k_normx(const float* __restrict__ x) {
    extern __shared__ char dsm[];
    float* xs = reinterpret_cast<float*>(dsm);            // [c][p], pitch 66
    float* ss = reinterpret_cast<float*>(dsm + 67584);    // [4][64]
    float* inv = reinterpret_cast<float*>(dsm + 68608);   // [64]
    int n0 = blockIdx.x * 64, b = blockIdx.y;
    int tid = threadIdx.x;

#pragma unroll
    for (int i = 0; i < 16; i++) {
        int f4 = tid + i * 256;
        int c = f4 >> 4, p4 = (f4 & 15) << 2;
        float4 v = *reinterpret_cast<const float4*>(
            &x[((size_t)b * PC + c) * PN + n0 + p4]);
        float* row = &xs[c * 66 + p4];
        row[0] = v.x; row[1] = v.y; row[2] = v.z; row[3] = v.w;
    }
    __syncthreads();

    {
        int p = tid & 63, q = tid >> 6;
        float s = 0.0f;
#pragma unroll 8
        for (int c2 = 0; c2 < 64; c2++) {
            float v = xs[(q * 64 + c2) * 66 + p];
            s += v * v;
        }
        ss[q * 64 + p] = s;
    }
    __syncthreads();
    if (tid < 64) {
        float s = ss[tid] + ss[64 + tid] + ss[128 + tid] + ss[192 + tid];
        inv[tid] = 1.0f / fmaxf(sqrtf(s), 1e-12f);
    }
    __syncthreads();

#pragma unroll
    for (int i = 0; i < 32; i++) {
        int e2 = tid + i * 256;
        int n_ = e2 >> 7, cp = (e2 & 127) << 1;
        float iv = inv[n_];
        float v0 = xs[cp * 66 + n_] * iv;
        float v1 = xs[(cp + 1) * 66 + n_] * iv;
        u32 h0 = f16_rn(v0), h1 = f16_rn(v1);
        size_t e = ((size_t)b * PN + n0 + n_) * PC + cp;
        reinterpret_cast<u32*>(g_xh)[e >> 1] = (h1 << 16) | h0;
    }
}

// ---------------- K2: qkv GEMM on HMMA; 2-term fp16; q->f32, k/v->fp16 outputs ----------------
#define QKV_SMEM 98304
__global__ void __launch_bounds__(256, 2) k_qkv_mma() {
    extern __shared__ char dyn[];
    u32 base = smem_u32(dyn);
    int tid = threadIdx.x, lane = tid & 31, wid = tid >> 5;
    int nb = blockIdx.x * 128, mb = blockIdx.y * 128, b = blockIdx.z;
    int wm = (wid & 3) * 32, wn = (wid >> 2) * 64;

    float acc[2][8][4];
#pragma unroll
    for (int im = 0; im < 2; im++)
#pragma unroll
        for (int jn = 0; jn < 8; jn++)
#pragma unroll
            for (int q = 0; q < 4; q++) acc[im][jn][q] = 0.0f;

    u32 st_bo[4];
    const unsigned short* st_wsrc[4];
    const unsigned short* st_xsrc[4];
    bool st_xok[4];
#pragma unroll
    for (int i = 0; i < 4; i++) {
        int u = tid + i * 256;
        int r = u >> 3, c8 = (u & 7) << 3;
        u32 bo = (u32)((r << 7) + (c8 << 1));
        st_bo[i] = bo ^ ((bo >> 3) & 0x70);
        if (c8 < 32) {
            st_wsrc[i] = &g_wh[(size_t)(mb + r) * PC + c8];
            st_xsrc[i] = &g_xh[((size_t)b * PN + nb + r) * PC + c8];
            st_xok[i] = true;
        } else {
            st_wsrc[i] = &g_wl[(size_t)(mb + r) * PC + c8 - 32];
            st_xsrc[i] = 0;
            st_xok[i] = false;
        }
    }
    u32 a_off[2], b_off[4];
#pragma unroll
    for (int im = 0; im < 2; im++) {
        int arow = wm + im * 16 + (lane & 15);
        u32 bo = (u32)(arow * 128) + ((lane >> 4) << 4);
        a_off[im] = bo ^ ((bo >> 3) & 0x70);
    }
#pragma unroll
    for (int j2 = 0; j2 < 4; j2++) {
        int nrow = wn + j2 * 16 + ((lane >> 4) << 3) + (lane & 7);
        u32 bo = (u32)(nrow * 128) + (((lane >> 3) & 1) << 4);
        b_off[j2] = bo ^ ((bo >> 3) & 0x70);
    }

#pragma unroll
    for (int s = 0; s < 2; s++) {
        u32 sb = base + (u32)(s * 32768);
        int co = s * 32;
#pragma unroll
        for (int i = 0; i < 4; i++) {
            cpa16(sb + st_bo[i], st_wsrc[i] + co);
            if (st_xok[i]) cpa16(sb + 16384 + st_bo[i], st_xsrc[i] + co);
        }
        cpa_commit();
    }

    for (int ch = 0; ch < 8; ch++) {
        if (ch < 7) cpa_wait1(); else cpa_wait0();
        __syncthreads();
        if (ch + 2 < 8) {
            u32 sb = base + (u32)(((ch + 2) % 3) * 32768);
            int co = (ch + 2) * 32;
#pragma unroll
            for (int i = 0; i < 4; i++) {
                cpa16(sb + st_bo[i], st_wsrc[i] + co);
                if (st_xok[i]) cpa16(sb + 16384 + st_bo[i], st_xsrc[i] + co);
            }
            cpa_commit();
        }
        u32 aU = base + (u32)((ch % 3) * 32768);
        u32 bU = aU + 16384u;
#pragma unroll
        for (int kkh = 0; kkh < 2; kkh++) {
            u32 kA = (u32)(kkh * 32);
            u32 ah[2][4];
            ldsm4(ah[0], aU + (a_off[0] ^ kA));
            ldsm4(ah[1], aU + (a_off[1] ^ kA));
            u32 al[2][4];
            ldsm4(al[0], aU + (a_off[0] ^ (kA + 64)));
            ldsm4(al[1], aU + (a_off[1] ^ (kA + 64)));
            u32 bh[8][2];
#pragma unroll
            for (int j2 = 0; j2 < 4; j2++) {
                u32 r4[4];
                ldsm4(r4, bU + (b_off[j2] ^ kA));
                bh[2 * j2][0] = r4[0]; bh[2 * j2][1] = r4[1];
                bh[2 * j2 + 1][0] = r4[2]; bh[2 * j2 + 1][1] = r4[3];
            }
#pragma unroll
            for (int im = 0; im < 2; im++)
#pragma unroll
                for (int jn = 0; jn < 8; jn++)
                    mma16816(acc[im][jn], ah[im], bh[jn]);
#pragma unroll
            for (int im = 0; im < 2; im++)
#pragma unroll
                for (int jn = 0; jn < 8; jn++)
                    mma16816(acc[im][jn], al[im], bh[jn]);
        }
    }

    // epilogue: q block -> f32 g_q; k/v blocks -> fp16 g_kv16
    int r0 = wm + (lane >> 2);
    int cb = wn + (lane & 3) * 2;
    if (mb == 0) {
#pragma unroll
        for (int im = 0; im < 2; im++) {
#pragma unroll
            for (int jn = 0; jn < 8; jn++) {
                int c = cb + jn * 8;
                size_t rowA = (size_t)b * PHID + r0 + im * 16;
                float2 v0 = {acc[im][jn][0], acc[im][jn][1]};
                float2 v1 = {acc[im][jn][2], acc[im][jn][3]};
                *reinterpret_cast<float2*>(&g_q[rowA * PN + nb + c]) = v0;
                *reinterpret_cast<float2*>(&g_q[(rowA + 8) * PN + nb + c]) = v1;
            }
        }
    } else {
        int kvbase = b * 256 + (mb - 128);   // k rows 0-127, v rows 128-255
#pragma unroll
        for (int im = 0; im < 2; im++) {
#pragma unroll
            for (int jn = 0; jn < 8; jn++) {
                int c = cb + jn * 8;
                size_t row = (size_t)(kvbase + r0 + im * 16);
                __half2 h0 = __floats2half2_rn(acc[im][jn][0], acc[im][jn][1]);
                __half2 h1 = __floats2half2_rn(acc[im][jn][2], acc[im][jn][3]);
                *reinterpret_cast<__half2*>(&g_kv16[row * PN + nb + c]) = h0;
                *reinterpret_cast<__half2*>(&g_kv16[(row + 8) * PN + nb + c]) = h1;
            }
        }
    }
}

// ---------------- K3a: k row softmax stats (fp16 k, uint4 loads) ----------------
__global__ void k_kstats(const float* __restrict__ mem_kv) {
    int gwarp = (blockIdx.x * blockDim.x + threadIdx.x) >> 5;
    int lane = threadIdx.x & 31;
    if (gwarp >= PB * PNH * PHD) return;
    int d = gwarp & 31, h = (gwarp >> 5) & 3, b = gwarp >> 7;
    const unsigned short* krow = &g_kv16[(size_t)(b * 256 + h * PHD + d) * PN];

    // pass 1: max — 2 independent chains, 8 halves per load
    float m0 = -1e30f, m1 = -1e30f;
    for (int p = lane * 8; p < PN; p += 512) {
        uint4 va = *reinterpret_cast<const uint4*>(&krow[p]);
        uint4 vb = *reinterpret_cast<const uint4*>(&krow[p + 256]);
        const __half2* ha = reinterpret_cast<const __half2*>(&va);
        const __half2* hb = reinterpret_cast<const __half2*>(&vb);
#pragma unroll
        for (int j = 0; j < 4; j++) {
            float2 fa = __half22float2(ha[j]);
            float2 fb = __half22float2(hb[j]);
            m0 = fmaxf(m0, fmaxf(fa.x, fa.y));
            m1 = fmaxf(m1, fmaxf(fb.x, fb.y));
        }
    }
    float m = fmaxf(m0, m1);
    if (lane < PNM)
        m = fmaxf(m, mem_kv[((0 * PNH + h) * PHD + d) * PNM + lane]);
#pragma unroll
    for (int o = 16; o > 0; o >>= 1)
        m = fmaxf(m, __shfl_xor_sync(0xffffffffu, m, o));

    // pass 2: sum exp — 2 chains
    float s0 = 0.f, s1 = 0.f;
    for (int p = lane * 8; p < PN; p += 512) {
        uint4 va = *reinterpret_cast<const uint4*>(&krow[p]);
        uint4 vb = *reinterpret_cast<const uint4*>(&krow[p + 256]);
        const __half2* ha = reinterpret_cast<const __half2*>(&va);
        const __half2* hb = reinterpret_cast<const __half2*>(&vb);
#pragma unroll
        for (int j = 0; j < 4; j++) {
            float2 fa = __half22float2(ha[j]);
            float2 fb = __half22float2(hb[j]);
            s0 += __expf(fa.x - m) + __expf(fa.y - m);
            s1 += __expf(fb.x - m) + __expf(fb.y - m);
        }
    }
    float s = s0 + s1;
    if (lane < PNM)
        s += __expf(mem_kv[((0 * PNH + h) * PHD + d) * PNM + lane] - m);
#pragma unroll
    for (int o = 16; o > 0; o >>= 1)
        s += __shfl_xor_sync(0xffffffffu, s, o);
    if (lane == 0) { g_stat[0][gwarp] = m; g_stat[1][gwarp] = 1.0f / s; }
}

// ---------------- K3b: partial context (fp16 k/v loads) ----------------
__global__ void k_context(const float* __restrict__ mem_kv) {
    __shared__ float Ks[PHD][68];
    __shared__ float Vt[64][34];
    __shared__ float rmax[PHD], rinv[PHD];
    int tc = blockIdx.x, h = blockIdx.y, b = blockIdx.z;
    int tid = threadIdx.x;
    if (tid < PHD) {
        int rowid = (b * PNH + h) * PHD + tid;
        rmax[tid] = g_stat[0][rowid];
        rinv[tid] = g_stat[1][rowid];
    }
    __syncthreads();
    int d = tid >> 3;
    int eg = (tid & 7) << 2;
    float macc[4] = {0.f, 0.f, 0.f, 0.f};
    if (tc == 0) {
#pragma unroll
        for (int m = 0; m < PNM; m++) {
            float kv = __expf(mem_kv[((0 * PNH + h) * PHD + d) * PNM + m] - rmax[d]) * rinv[d];
#pragma unroll
            for (int i = 0; i < 4; i++)
                macc[i] += kv * mem_kv[((1 * PNH + h) * PHD + eg + i) * PNM + m];
        }
    }
    u64 accp[2] = {0ull, 0ull};
    int pbase = tc * 512;
    for (int t = 0; t < 8; t++) {
        int p0 = pbase + t * 64;
        // K tile 32x64 halves, exp-normalized at load (1 uint4/thread)
        {
            int r = tid >> 3, c8 = (tid & 7) << 3;
            uint4 v = *reinterpret_cast<const uint4*>(
                &g_kv16[(size_t)(b * 256 + h * PHD + r) * PN + p0 + c8]);
            const __half2* hp = reinterpret_cast<const __half2*>(&v);
            float mx = rmax[r], ri = rinv[r];
#pragma unroll
            for (int j = 0; j < 4; j++) {
                float2 f = __half22float2(hp[j]);
                Ks[r][c8 + 2 * j]     = __expf(f.x - mx) * ri;
                Ks[r][c8 + 2 * j + 1] = __expf(f.y - mx) * ri;
            }
        }
        // V tile 32x64 halves -> transposed f32
        {
            int r = tid >> 3, c8 = (tid & 7) << 3;
            uint4 v = *reinterpret_cast<const uint4*>(
                &g_kv16[(size_t)(b * 256 + 128 + h * PHD + r) * PN + p0 + c8]);
            const __half2* hp = reinterpret_cast<const __half2*>(&v);
#pragma unroll
            for (int j = 0; j < 4; j++) {
                float2 f = __half22float2(hp[j]);
                Vt[c8 + 2 * j][r] = f.x;
                Vt[c8 + 2 * j + 1][r] = f.y;
            }
        }
        __syncthreads();
#pragma unroll
        for (int n = 0; n < 64; n++) {
            u64 kv2 = pack2(Ks[d][n], Ks[d][n]);
            u64 v0 = *reinterpret_cast<const u64*>(&Vt[n][eg]);
            u64 v1 = *reinterpret_cast<const u64*>(&Vt[n][eg + 2]);
            accp[0] = fma2(kv2, v0, accp[0]);
            accp[1] = fma2(kv2, v1, accp[1]);
        }
        __syncthreads();
    }
    size_t base = ((size_t)(b * PNH + h) * PHD + d) * PHD + eg;
    float2 p0 = unpack2(accp[0]);
    float2 p1 = unpack2(accp[1]);
    g_ctxp[tc][base + 0] = p0.x + macc[0];
    g_ctxp[tc][base + 1] = p0.y + macc[1];
    g_ctxp[tc][base + 2] = p1.x + macc[2];
    g_ctxp[tc][base + 3] = p1.y + macc[3];
}

// ---------------- K4: reduce partials + fold M = w_out . ctx -> fp16 hi/lo ----------------
__global__ void k_fold(const float* __restrict__ w_out) {
    __shared__ float ctx[PNH * PHD * PHD];
    int b = blockIdx.x;
    int tid = threadIdx.x;
    for (int idx = tid; idx < PNH * PHD * PHD; idx += 256) {
        float s = 0.0f;
#pragma unroll
        for (int tc = 0; tc < 8; tc++) s += g_ctxp[tc][b * (PNH * PHD * PHD) + idx];
        ctx[idx] = s;
    }
    __syncthreads();
    int o = tid;
    for (int h = 0; h < PNH; h++) {
        float w[PHD];
#pragma unroll
        for (int e = 0; e < PHD; e++) w[e] = w_out[o * PHID + h * PHD + e];
        for (int dd = 0; dd < PHD; dd++) {
            float s = 0.0f;
#pragma unroll
            for (int e = 0; e < PHD; e++) s += w[e] * ctx[(h * PHD + dd) * PHD + e];
            u32 hb = f16_rn(s);
            u32 lb = f16_rn(s - f16_tof(hb));
            int idx = (b * PC + o) * PHID + h * PHD + dd;
            g_Mh[idx] = (unsigned short)hb;
            g_Ml[idx] = (unsigned short)lb;
        }
    }
}

// ---------------- K5: fused q-softmax + output GEMM (HMMA) + bias + RMS norm ----------------
#define OUT_SMEM 99584
__global__ void __launch_bounds__(256, 2) k_out_mma(
    const float* __restrict__ b_out,
    const float* __restrict__ g_out,
    float* __restrict__ out) {
    extern __shared__ char dyn[];
    u32 base = smem_u32(dyn);
    float* msf = reinterpret_cast<float*>(dyn + 32768);
    float* red = reinterpret_cast<float*>(dyn + 98304);
    float* invr = reinterpret_cast<float*>(dyn + 99328);
    int tid = threadIdx.x, lane = tid & 31, wid = tid >> 5;
    int p0 = blockIdx.x * 64, b = blockIdx.y;

    // --- load q f32 tile [128 rows][64 pixels] ---
#pragma unroll
    for (int i = 0; i < 8; i++) {
        int f4 = tid + i * 256;
        int r = f4 >> 4, c4 = (f4 & 15) << 2;
        *reinterpret_cast<float4*>(&msf[r * 64 + c4]) =
            *reinterpret_cast<const float4*>(&g_q[((size_t)b * PHID + r) * PN + p0 + c4]);
    }
    __syncthreads();

    // --- softmax over head_dim per (head, pixel); write fp16 Q tiles ---
    {
        int p = tid & 63, h = tid >> 6;
        float e[PHD];
        float m = -1e30f;
#pragma unroll
        for (int dd = 0; dd < PHD; dd++) m = fmaxf(m, msf[(h * PHD + dd) * 64 + p]);
        float s = 0.0f;
#pragma unroll
        for (int dd = 0; dd < PHD; dd++) { e[dd] = __expf(msf[(h * PHD + dd) * 64 + p] - m); s += e[dd]; }
        float sc = 0.17677669529663687f / s;
        int kc = h >> 1;
        int klb = (h & 1) * 32;
        u32 qh_off = (u32)(kc * 8192);
        __syncthreads();
#pragma unroll
        for (int dd = 0; dd < PHD; dd += 2) {
            float v0 = e[dd] * sc, v1 = e[dd + 1] * sc;
            u32 h0 = f16_rn(v0), h1 = f16_rn(v1);
            u32 bo = (u32)(p * 128 + (klb + dd) * 2);
            bo ^= (bo >> 3) & 0x70;
            *reinterpret_cast<u32*>(dyn + qh_off + bo) = (h1 << 16) | h0;
        }
    }
    __syncthreads();

    // --- GEMM: 8 warps = 4(m) x 2(n) ---
    int wm = wid & 3, wn = wid >> 2;
    float acc[4][4][4];
#pragma unroll
    for (int im = 0; im < 4; im++)
#pragma unroll
        for (int jn = 0; jn < 4; jn++)
#pragma unroll
            for (int q = 0; q < 4; q++) acc[im][jn][q] = 0.0f;

    u32 a_off[4], b_off[2];
#pragma unroll
    for (int im = 0; im < 4; im++) {
        int arow = wm * 64 + im * 16 + (lane & 15);
        u32 bo = (u32)(arow * 128) + ((lane >> 4) << 4);
        a_off[im] = bo ^ ((bo >> 3) & 0x70);
    }
#pragma unroll
    for (int j2 = 0; j2 < 2; j2++) {
        int nrow = wn * 32 + j2 * 16 + ((lane >> 4) << 3) + (lane & 7);
        u32 bo = (u32)(nrow * 128) + (((lane >> 3) & 1) << 4);
        b_off[j2] = bo ^ ((bo >> 3) & 0x70);
    }
    u32 mh_base = base + 32768u, ml_base = base + 65536u;

    for (int kc = 0; kc < 2; kc++) {
        u32 qh = base + (u32)(kc * 8192);
#pragma unroll
        for (int i = 0; i < 8; i++) {
            int u = tid + i * 256;
            int r = u >> 3, c8 = (u & 7) << 3;
            u32 bo = (u32)((r << 7) + (c8 << 1));
            bo ^= (bo >> 3) & 0x70;
            int gi = (b * PC + r) * PHID + kc * 64 + c8;
            *reinterpret_cast<uint4*>(dyn + 32768 + bo) =
                *reinterpret_cast<const uint4*>(&g_Mh[gi]);
            *reinterpret_cast<uint4*>(dyn + 65536 + bo) =
                *reinterpret_cast<const uint4*>(&g_Ml[gi]);
        }
        __syncthreads();
#pragma unroll
        for (int kk = 0; kk < 4; kk++) {
            u32 kadd = (u32)(kk * 32);
            u32 a[4][4];
#pragma unroll
            for (int im = 0; im < 4; im++) ldsm4(a[im], mh_base + (a_off[im] ^ kadd));
            u32 al[4][4];
#pragma unroll
            for (int im = 0; im < 4; im++) ldsm4(al[im], ml_base + (a_off[im] ^ kadd));
            u32 bh[4][2];
#pragma unroll
            for (int j2 = 0; j2 < 2; j2++) {
                u32 r4[4];
                ldsm4(r4, qh + (b_off[j2] ^ kadd));
                bh[2 * j2][0] = r4[0]; bh[2 * j2][1] = r4[1];
                bh[2 * j2 + 1][0] = r4[2]; bh[2 * j2 + 1][1] = r4[3];
            }
#pragma unroll
            for (int im = 0; im < 4; im++)
#pragma unroll
                for (int jn = 0; jn < 4; jn++)
                    mma16816(acc[im][jn], a[im], bh[jn]);
#pragma unroll
            for (int im = 0; im < 4; im++)
#pragma unroll
                for (int jn = 0; jn < 4; jn++)
                    mma16816(acc[im][jn], al[im], bh[jn]);
        }
        __syncthreads();
    }

    // --- epilogue: bias, per-pixel RMS, g_out scale, store ---
    float bo0[4], bo8[4], go0[4], go8[4];
#pragma unroll
    for (int im = 0; im < 4; im++) {
        int r = wm * 64 + im * 16 + (lane >> 2);
        bo0[im] = b_out[r];  bo8[im] = b_out[r + 8];
        go0[im] = g_out[r];  go8[im] = g_out[r + 8];
    }
#pragma unroll
    for (int jn = 0; jn < 4; jn++) {
        float sq0 = 0.f, sq1 = 0.f;
#pragma unroll
        for (int im = 0; im < 4; im++) {
            acc[im][jn][0] += bo0[im]; acc[im][jn][1] += bo0[im];
            acc[im][jn][2] += bo8[im]; acc[im][jn][3] += bo8[im];
            sq0 += acc[im][jn][0] * acc[im][jn][0] + acc[im][jn][2] * acc[im][jn][2];
            sq1 += acc[im][jn][1] * acc[im][jn][1] + acc[im][jn][3] * acc[im][jn][3];
        }
#pragma unroll
        for (int off = 4; off < 32; off <<= 1) {
            sq0 += __shfl_xor_sync(0xffffffffu, sq0, off);
            sq1 += __shfl_xor_sync(0xffffffffu, sq1, off);
        }
        if (lane < 4) {
            int c = wn * 32 + jn * 8 + lane * 2;
            red[wm * 64 + c] = sq0;
            red[wm * 64 + c + 1] = sq1;
        }
    }
    __syncthreads();
    if (tid < 64) {
        float s = red[tid] + red[64 + tid] + red[128 + tid] + red[192 + tid];
        invr[tid] = 16.0f / fmaxf(sqrtf(s), 1e-12f);
    }
    __syncthreads();
#pragma unroll
    for (int im = 0; im < 4; im++) {
        int r = wm * 64 + im * 16 + (lane >> 2);
#pragma unroll
        for (int jn = 0; jn < 4; jn++) {
            int c = wn * 32 + jn * 8 + (lane & 3) * 2;
            float iv0 = invr[c], iv1 = invr[c + 1];
            float2 v0 = {acc[im][jn][0] * iv0 * go0[im], acc[im][jn][1] * iv1 * go0[im]};
            float2 v1 = {acc[im][jn][2] * iv0 * go8[im], acc[im][jn][3] * iv1 * go8[im]};
            *reinterpret_cast<float2*>(&out[((size_t)(b * PC + r)) * PN + p0 + c]) = v0;
            *reinterpret_cast<float2*>(&out[((size_t)(b * PC + r + 8)) * PN + p0 + c]) = v1;
        }
    }
}

// ---------------- launch ----------------
extern "C" void kernel_launch(void* const* d_in, const int* in_sizes, int n_in,
                              void* d_out, int out_size) {
    const float* x      = (const float*)d_in[0];
    const float* g_in   = (const float*)d_in[1];
    const float* mem_kv = (const float*)d_in[2];
    const float* w_qkv  = (const float*)d_in[3];
    const float* w_out  = (const float*)d_in[4];
    const float* b_out  = (const float*)d_in[5];
    const float* g_out  = (const float*)d_in[6];
    float* out = (float*)d_out;

    static int attr_done = 0;
    if (!attr_done) {
        cudaFuncSetAttribute(k_normx,   cudaFuncAttributeMaxDynamicSharedMemorySize, NORMX_SMEM);
        cudaFuncSetAttribute(k_qkv_mma, cudaFuncAttributeMaxDynamicSharedMemorySize, QKV_SMEM);
        cudaFuncSetAttribute(k_out_mma, cudaFuncAttributeMaxDynamicSharedMemorySize, OUT_SMEM);
        attr_done = 1;
    }

    k_convw  <<<QROWS, 256>>>(w_qkv, g_in);
    k_normx  <<<dim3(PN / 64, PB), 256, NORMX_SMEM>>>(x);
    k_qkv_mma<<<dim3(PN / 128, QROWS / 128, PB), 256, QKV_SMEM>>>();
    k_kstats <<<512, 128>>>(mem_kv);
    k_context<<<dim3(8, PNH, PB), 256>>>(mem_kv);
    k_fold   <<<PB, 256>>>(w_out);
    k_out_mma<<<dim3(PN / 64, PB), 256, OUT_SMEM>>>(b_out, g_out, out);
}

// round 16
// speedup vs baseline: 1.8753x; 1.0277x over previous
#include <cuda_runtime.h>
#include <cuda_fp16.h>
#include <math.h>
#include <stdint.h>

// Problem constants
#define PB   16      // batch
#define PC   256     // channels
#define PN   4096    // H*W
#define PNH  4       // heads
#define PHD  32      // head dim
#define PNM  4       // memory tokens
#define PHID 128     // NH*HD
#define QROWS 384    // 3*HID

typedef unsigned long long u64;
typedef unsigned int u32;

// ---------------- scratch (static device memory; no allocation) ----------------
__device__ unsigned short g_wh[QROWS * PC];            // fp16 hi of scaled qkv weights
__device__ unsigned short g_wl[QROWS * PC];            // fp16 lo
__device__ unsigned short g_xh[(size_t)PB * PN * PC];  // fp16 of normalized x, [b][n][c]
__device__ float g_q[(size_t)PB * PHID * PN];          // q activations f32 (~33 MB)
__device__ unsigned short g_kv16[(size_t)PB * 256 * PN]; // k rows 0-127, v rows 128-255, fp16 (~33 MB)
__device__ float g_stat[2][PB * PNH * PHD];            // k softmax: rowmax, 1/rowsum
__device__ float g_ctxp[8][PB * PNH * PHD * PHD];      // partial contexts (8 token chunks)
__device__ unsigned short g_Mh[PB * PC * PHID];        // folded M = w_out . ctx, fp16 hi
__device__ unsigned short g_Ml[PB * PC * PHID];        // fp16 lo

// ---------------- small helpers ----------------
__device__ __forceinline__ u32 f16_rn(float v) {
    return (u32)__half_as_ushort(__float2half_rn(v));
}
__device__ __forceinline__ float f16_tof(u32 b) {
    return __half2float(__ushort_as_half((unsigned short)b));
}

__device__ __forceinline__ u32 smem_u32(const void* p) {
    u32 a;
    asm("{ .reg .u64 t; cvta.to.shared.u64 t, %1; cvt.u32.u64 %0, t; }" : "=r"(a) : "l"(p));
    return a;
}

// f32x2 packed helpers (k_context)
__device__ __forceinline__ u64 fma2(u64 a, u64 b, u64 c) {
    u64 d; asm("fma.rn.f32x2 %0, %1, %2, %3;" : "=l"(d) : "l"(a), "l"(b), "l"(c)); return d;
}
__device__ __forceinline__ u64 pack2(float lo, float hi) {
    u64 r; asm("mov.b64 %0, {%1, %2};" : "=l"(r) : "f"(lo), "f"(hi)); return r;
}
__device__ __forceinline__ float2 unpack2(u64 v) {
    float2 r; asm("mov.b64 {%0, %1}, %2;" : "=f"(r.x), "=f"(r.y) : "l"(v)); return r;
}

// ---------------- HMMA helpers ----------------
__device__ __forceinline__ void ldsm4(u32* r, u32 addr) {
    asm volatile("ldmatrix.sync.aligned.m8n8.x4.shared.b16 {%0,%1,%2,%3}, [%4];"
                 : "=r"(r[0]), "=r"(r[1]), "=r"(r[2]), "=r"(r[3]) : "r"(addr));
}
__device__ __forceinline__ void mma16816(float* d, const u32* a, const u32* b) {
    asm volatile(
        "mma.sync.aligned.m16n8k16.row.col.f32.f16.f16.f32 "
        "{%0,%1,%2,%3}, {%4,%5,%6,%7}, {%8,%9}, {%0,%1,%2,%3};"
        : "+f"(d[0]), "+f"(d[1]), "+f"(d[2]), "+f"(d[3])
        : "r"(a[0]), "r"(a[1]), "r"(a[2]), "r"(a[3]), "r"(b[0]), "r"(b[1]));
}
__device__ __forceinline__ void cpa16(u32 dst, const void* src) {
    asm volatile("cp.async.ca.shared.global [%0], [%1], 16;" :: "r"(dst), "l"(src));
}
__device__ __forceinline__ void cpa_commit() {
    asm volatile("cp.async.commit_group;" ::: "memory");
}
__device__ __forceinline__ void cpa_wait1() {
    asm volatile("cp.async.wait_group 1;" ::: "memory");
}
__device__ __forceinline__ void cpa_wait0() {
    asm volatile("cp.async.wait_group 0;" ::: "memory");
}

// ---------------- K0a: weight convert  fp16 hi/lo of (w_qkv * g_in * sqrt(C)) ----------------
__global__ void k_convw(const float* __restrict__ w_qkv, const float* __restrict__ g_in) {
    int i = blockIdx.x * 256 + threadIdx.x;
    if (i < QROWS * PC) {
        int c = i & 255;
        float v = w_qkv[i] * g_in[c] * 16.0f;  // sqrt(256) = 16
        u32 hb = f16_rn(v);
        u32 lb = f16_rn(v - f16_tof(hb));
        g_wh[i] = (unsigned short)hb;
        g_wl[i] = (unsigned short)lb;
    }
}

// ---------------- K0b: fused channel-RMS + transpose + fp16 convert ----------------
#define NORMX_SMEM 68864
__global__ void __launch_bounds__(256) k_normx(const float* __restrict__ x) {
    extern __shared__ char dsm[];
    float* xs = reinterpret_cast<float*>(dsm);            // [c][p], pitch 66
    float* ss = reinterpret_cast<float*>(dsm + 67584);    // [4][64]
    float* inv = reinterpret_cast<float*>(dsm + 68608);   // [64]
    int n0 = blockIdx.x * 64, b = blockIdx.y;
    int tid = threadIdx.x;

#pragma unroll
    for (int i = 0; i < 16; i++) {
        int f4 = tid + i * 256;
        int c = f4 >> 4, p4 = (f4 & 15) << 2;
        float4 v = *reinterpret_cast<const float4*>(
            &x[((size_t)b * PC + c) * PN + n0 + p4]);
        float* row = &xs[c * 66 + p4];
        row[0] = v.x; row[1] = v.y; row[2] = v.z; row[3] = v.w;
    }
    __syncthreads();

    {
        int p = tid & 63, q = tid >> 6;
        float s = 0.0f;
#pragma unroll 8
        for (int c2 = 0; c2 < 64; c2++) {
            float v = xs[(q * 64 + c2) * 66 + p];
            s += v * v;
        }
        ss[q * 64 + p] = s;
    }
    __syncthreads();
    if (tid < 64) {
        float s = ss[tid] + ss[64 + tid] + ss[128 + tid] + ss[192 + tid];
        inv[tid] = 1.0f / fmaxf(sqrtf(s), 1e-12f);
    }
    __syncthreads();

#pragma unroll
    for (int i = 0; i < 32; i++) {
        int e2 = tid + i * 256;
        int n_ = e2 >> 7, cp = (e2 & 127) << 1;
        float iv = inv[n_];
        float v0 = xs[cp * 66 + n_] * iv;
        float v1 = xs[(cp + 1) * 66 + n_] * iv;
        u32 h0 = f16_rn(v0), h1 = f16_rn(v1);
        size_t e = ((size_t)b * PN + n0 + n_) * PC + cp;
        reinterpret_cast<u32*>(g_xh)[e >> 1] = (h1 << 16) | h0;
    }
}

// ---------------- K2: qkv GEMM on HMMA ----------------
// q block (mb==0): 2-term (Wh+Wl)*Xh, f32 output.
// k/v blocks (mb=128/256): 1-term Wh*Xh — lo term is below the fp16 output
// quantization, so it is pure waste there.
#define QKV_SMEM 98304
__global__ void __launch_bounds__(256, 2) k_qkv_mma() {
    extern __shared__ char dyn[];
    u32 base = smem_u32(dyn);
    int tid = threadIdx.x, lane = tid & 31, wid = tid >> 5;
    int nb = blockIdx.x * 128, mb = blockIdx.y * 128, b = blockIdx.z;
    int wm = (wid & 3) * 32, wn = (wid >> 2) * 64;
    const bool need_lo = (mb == 0);

    float acc[2][8][4];
#pragma unroll
    for (int im = 0; im < 2; im++)
#pragma unroll
        for (int jn = 0; jn < 8; jn++)
#pragma unroll
            for (int q = 0; q < 4; q++) acc[im][jn][q] = 0.0f;

    u32 st_bo[4];
    const unsigned short* st_wsrc[4];
    const unsigned short* st_xsrc[4];
    bool st_xok[4];   // true: this slot stages (wh, xh); false: stages wl (only if need_lo)
#pragma unroll
    for (int i = 0; i < 4; i++) {
        int u = tid + i * 256;
        int r = u >> 3, c8 = (u & 7) << 3;
        u32 bo = (u32)((r << 7) + (c8 << 1));
        st_bo[i] = bo ^ ((bo >> 3) & 0x70);
        if (c8 < 32) {
            st_wsrc[i] = &g_wh[(size_t)(mb + r) * PC + c8];
            st_xsrc[i] = &g_xh[((size_t)b * PN + nb + r) * PC + c8];
            st_xok[i] = true;
        } else {
            st_wsrc[i] = &g_wl[(size_t)(mb + r) * PC + c8 - 32];
            st_xsrc[i] = 0;
            st_xok[i] = false;
        }
    }
    u32 a_off[2], b_off[4];
#pragma unroll
    for (int im = 0; im < 2; im++) {
        int arow = wm + im * 16 + (lane & 15);
        u32 bo = (u32)(arow * 128) + ((lane >> 4) << 4);
        a_off[im] = bo ^ ((bo >> 3) & 0x70);
    }
#pragma unroll
    for (int j2 = 0; j2 < 4; j2++) {
        int nrow = wn + j2 * 16 + ((lane >> 4) << 3) + (lane & 7);
        u32 bo = (u32)(nrow * 128) + (((lane >> 3) & 1) << 4);
        b_off[j2] = bo ^ ((bo >> 3) & 0x70);
    }

#pragma unroll
    for (int s = 0; s < 2; s++) {
        u32 sb = base + (u32)(s * 32768);
        int co = s * 32;
#pragma unroll
        for (int i = 0; i < 4; i++) {
            if (st_xok[i]) {
                cpa16(sb + st_bo[i], st_wsrc[i] + co);
                cpa16(sb + 16384 + st_bo[i], st_xsrc[i] + co);
            } else if (need_lo) {
                cpa16(sb + st_bo[i], st_wsrc[i] + co);
            }
        }
        cpa_commit();
    }

    for (int ch = 0; ch < 8; ch++) {
        if (ch < 7) cpa_wait1(); else cpa_wait0();
        __syncthreads();
        if (ch + 2 < 8) {
            u32 sb = base + (u32)(((ch + 2) % 3) * 32768);
            int co = (ch + 2) * 32;
#pragma unroll
            for (int i = 0; i < 4; i++) {
                if (st_xok[i]) {
                    cpa16(sb + st_bo[i], st_wsrc[i] + co);
                    cpa16(sb + 16384 + st_bo[i], st_xsrc[i] + co);
                } else if (need_lo) {
                    cpa16(sb + st_bo[i], st_wsrc[i] + co);
                }
            }
            cpa_commit();
        }
        u32 aU = base + (u32)((ch % 3) * 32768);
        u32 bU = aU + 16384u;
#pragma unroll
        for (int kkh = 0; kkh < 2; kkh++) {
            u32 kA = (u32)(kkh * 32);
            u32 ah[2][4];
            ldsm4(ah[0], aU + (a_off[0] ^ kA));
            ldsm4(ah[1], aU + (a_off[1] ^ kA));
            u32 bh[8][2];
#pragma unroll
            for (int j2 = 0; j2 < 4; j2++) {
                u32 r4[4];
                ldsm4(r4, bU + (b_off[j2] ^ kA));
                bh[2 * j2][0] = r4[0]; bh[2 * j2][1] = r4[1];
                bh[2 * j2 + 1][0] = r4[2]; bh[2 * j2 + 1][1] = r4[3];
            }
#pragma unroll
            for (int im = 0; im < 2; im++)
#pragma unroll
                for (int jn = 0; jn < 8; jn++)
                    mma16816(acc[im][jn], ah[im], bh[jn]);
            if (need_lo) {
                u32 al[2][4];
                ldsm4(al[0], aU + (a_off[0] ^ (kA + 64)));
                ldsm4(al[1], aU + (a_off[1] ^ (kA + 64)));
#pragma unroll
                for (int im = 0; im < 2; im++)
#pragma unroll
                    for (int jn = 0; jn < 8; jn++)
                        mma16816(acc[im][jn], al[im], bh[jn]);
            }
        }
    }

    // epilogue: q block -> f32 g_q; k/v blocks -> fp16 g_kv16
    int r0 = wm + (lane >> 2);
    int cb = wn + (lane & 3) * 2;
    if (mb == 0) {
#pragma unroll
        for (int im = 0; im < 2; im++) {
#pragma unroll
            for (int jn = 0; jn < 8; jn++) {
                int c = cb + jn * 8;
                size_t rowA = (size_t)b * PHID + r0 + im * 16;
                float2 v0 = {acc[im][jn][0], acc[im][jn][1]};
                float2 v1 = {acc[im][jn][2], acc[im][jn][3]};
                *reinterpret_cast<float2*>(&g_q[rowA * PN + nb + c]) = v0;
                *reinterpret_cast<float2*>(&g_q[(rowA + 8) * PN + nb + c]) = v1;
            }
        }
    } else {
        int kvbase = b * 256 + (mb - 128);   // k rows 0-127, v rows 128-255
#pragma unroll
        for (int im = 0; im < 2; im++) {
#pragma unroll
            for (int jn = 0; jn < 8; jn++) {
                int c = cb + jn * 8;
                size_t row = (size_t)(kvbase + r0 + im * 16);
                __half2 h0 = __floats2half2_rn(acc[im][jn][0], acc[im][jn][1]);
                __half2 h1 = __floats2half2_rn(acc[im][jn][2], acc[im][jn][3]);
                *reinterpret_cast<__half2*>(&g_kv16[row * PN + nb + c]) = h0;
                *reinterpret_cast<__half2*>(&g_kv16[(row + 8) * PN + nb + c]) = h1;
            }
        }
    }
}

// ---------------- K3a: k row softmax stats (fp16 k, uint4 loads) ----------------
__global__ void k_kstats(const float* __restrict__ mem_kv) {
    int gwarp = (blockIdx.x * blockDim.x + threadIdx.x) >> 5;
    int lane = threadIdx.x & 31;
    if (gwarp >= PB * PNH * PHD) return;
    int d = gwarp & 31, h = (gwarp >> 5) & 3, b = gwarp >> 7;
    const unsigned short* krow = &g_kv16[(size_t)(b * 256 + h * PHD + d) * PN];

    float m0 = -1e30f, m1 = -1e30f;
    for (int p = lane * 8; p < PN; p += 512) {
        uint4 va = *reinterpret_cast<const uint4*>(&krow[p]);
        uint4 vb = *reinterpret_cast<const uint4*>(&krow[p + 256]);
        const __half2* ha = reinterpret_cast<const __half2*>(&va);
        const __half2* hb = reinterpret_cast<const __half2*>(&vb);
#pragma unroll
        for (int j = 0; j < 4; j++) {
            float2 fa = __half22float2(ha[j]);
            float2 fb = __half22float2(hb[j]);
            m0 = fmaxf(m0, fmaxf(fa.x, fa.y));
            m1 = fmaxf(m1, fmaxf(fb.x, fb.y));
        }
    }
    float m = fmaxf(m0, m1);
    if (lane < PNM)
        m = fmaxf(m, mem_kv[((0 * PNH + h) * PHD + d) * PNM + lane]);
#pragma unroll
    for (int o = 16; o > 0; o >>= 1)
        m = fmaxf(m, __shfl_xor_sync(0xffffffffu, m, o));

    float s0 = 0.f, s1 = 0.f;
    for (int p = lane * 8; p < PN; p += 512) {
        uint4 va = *reinterpret_cast<const uint4*>(&krow[p]);
        uint4 vb = *reinterpret_cast<const uint4*>(&krow[p + 256]);
        const __half2* ha = reinterpret_cast<const __half2*>(&va);
        const __half2* hb = reinterpret_cast<const __half2*>(&vb);
#pragma unroll
        for (int j = 0; j < 4; j++) {
            float2 fa = __half22float2(ha[j]);
            float2 fb = __half22float2(hb[j]);
            s0 += __expf(fa.x - m) + __expf(fa.y - m);
            s1 += __expf(fb.x - m) + __expf(fb.y - m);
        }
    }
    float s = s0 + s1;
    if (lane < PNM)
        s += __expf(mem_kv[((0 * PNH + h) * PHD + d) * PNM + lane] - m);
#pragma unroll
    for (int o = 16; o > 0; o >>= 1)
        s += __shfl_xor_sync(0xffffffffu, s, o);
    if (lane == 0) { g_stat[0][gwarp] = m; g_stat[1][gwarp] = 1.0f / s; }
}

// ---------------- K3b: partial context (fp16 k/v loads) ----------------
__global__ void k_context(const float* __restrict__ mem_kv) {
    __shared__ float Ks[PHD][68];
    __shared__ float Vt[64][34];
    __shared__ float rmax[PHD], rinv[PHD];
    int tc = blockIdx.x, h = blockIdx.y, b = blockIdx.z;
    int tid = threadIdx.x;
    if (tid < PHD) {
        int rowid = (b * PNH + h) * PHD + tid;
        rmax[tid] = g_stat[0][rowid];
        rinv[tid] = g_stat[1][rowid];
    }
    __syncthreads();
    int d = tid >> 3;
    int eg = (tid & 7) << 2;
    float macc[4] = {0.f, 0.f, 0.f, 0.f};
    if (tc == 0) {
#pragma unroll
        for (int m = 0; m < PNM; m++) {
            float kv = __expf(mem_kv[((0 * PNH + h) * PHD + d) * PNM + m] - rmax[d]) * rinv[d];
#pragma unroll
            for (int i = 0; i < 4; i++)
                macc[i] += kv * mem_kv[((1 * PNH + h) * PHD + eg + i) * PNM + m];
        }
    }
    u64 accp[2] = {0ull, 0ull};
    int pbase = tc * 512;
    for (int t = 0; t < 8; t++) {
        int p0 = pbase + t * 64;
        {
            int r = tid >> 3, c8 = (tid & 7) << 3;
            uint4 v = *reinterpret_cast<const uint4*>(
                &g_kv16[(size_t)(b * 256 + h * PHD + r) * PN + p0 + c8]);
            const __half2* hp = reinterpret_cast<const __half2*>(&v);
            float mx = rmax[r], ri = rinv[r];
#pragma unroll
            for (int j = 0; j < 4; j++) {
                float2 f = __half22float2(hp[j]);
                Ks[r][c8 + 2 * j]     = __expf(f.x - mx) * ri;
                Ks[r][c8 + 2 * j + 1] = __expf(f.y - mx) * ri;
            }
        }
        {
            int r = tid >> 3, c8 = (tid & 7) << 3;
            uint4 v = *reinterpret_cast<const uint4*>(
                &g_kv16[(size_t)(b * 256 + 128 + h * PHD + r) * PN + p0 + c8]);
            const __half2* hp = reinterpret_cast<const __half2*>(&v);
#pragma unroll
            for (int j = 0; j < 4; j++) {
                float2 f = __half22float2(hp[j]);
                Vt[c8 + 2 * j][r] = f.x;
                Vt[c8 + 2 * j + 1][r] = f.y;
            }
        }
        __syncthreads();
#pragma unroll
        for (int n = 0; n < 64; n++) {
            u64 kv2 = pack2(Ks[d][n], Ks[d][n]);
            u64 v0 = *reinterpret_cast<const u64*>(&Vt[n][eg]);
            u64 v1 = *reinterpret_cast<const u64*>(&Vt[n][eg + 2]);
            accp[0] = fma2(kv2, v0, accp[0]);
            accp[1] = fma2(kv2, v1, accp[1]);
        }
        __syncthreads();
    }
    size_t base = ((size_t)(b * PNH + h) * PHD + d) * PHD + eg;
    float2 p0 = unpack2(accp[0]);
    float2 p1 = unpack2(accp[1]);
    g_ctxp[tc][base + 0] = p0.x + macc[0];
    g_ctxp[tc][base + 1] = p0.y + macc[1];
    g_ctxp[tc][base + 2] = p1.x + macc[2];
    g_ctxp[tc][base + 3] = p1.y + macc[3];
}

// ---------------- K4: reduce partials + fold M = w_out . ctx -> fp16 hi/lo ----------------
__global__ void k_fold(const float* __restrict__ w_out) {
    __shared__ float ctx[PNH * PHD * PHD];
    int b = blockIdx.x;
    int tid = threadIdx.x;
    for (int idx = tid; idx < PNH * PHD * PHD; idx += 256) {
        float s = 0.0f;
#pragma unroll
        for (int tc = 0; tc < 8; tc++) s += g_ctxp[tc][b * (PNH * PHD * PHD) + idx];
        ctx[idx] = s;
    }
    __syncthreads();
    int o = tid;
    for (int h = 0; h < PNH; h++) {
        float w[PHD];
#pragma unroll
        for (int e = 0; e < PHD; e++) w[e] = w_out[o * PHID + h * PHD + e];
        for (int dd = 0; dd < PHD; dd++) {
            float s = 0.0f;
#pragma unroll
            for (int e = 0; e < PHD; e++) s += w[e] * ctx[(h * PHD + dd) * PHD + e];
            u32 hb = f16_rn(s);
            u32 lb = f16_rn(s - f16_tof(hb));
            int idx = (b * PC + o) * PHID + h * PHD + dd;
            g_Mh[idx] = (unsigned short)hb;
            g_Ml[idx] = (unsigned short)lb;
        }
    }
}

// ---------------- K5: fused q-softmax + output GEMM (HMMA) + bias + RMS norm ----------------
#define OUT_SMEM 99584
__global__ void __launch_bounds__(256, 2) k_out_mma(
    const float* __restrict__ b_out,
    const float* __restrict__ g_out,
    float* __restrict__ out) {
    extern __shared__ char dyn[];
    u32 base = smem_u32(dyn);
    float* msf = reinterpret_cast<float*>(dyn + 32768);
    float* red = reinterpret_cast<float*>(dyn + 98304);
    float* invr = reinterpret_cast<float*>(dyn + 99328);
    int tid = threadIdx.x, lane = tid & 31, wid = tid >> 5;
    int p0 = blockIdx.x * 64, b = blockIdx.y;

#pragma unroll
    for (int i = 0; i < 8; i++) {
        int f4 = tid + i * 256;
        int r = f4 >> 4, c4 = (f4 & 15) << 2;
        *reinterpret_cast<float4*>(&msf[r * 64 + c4]) =
            *reinterpret_cast<const float4*>(&g_q[((size_t)b * PHID + r) * PN + p0 + c4]);
    }
    __syncthreads();

    {
        int p = tid & 63, h = tid >> 6;
        float e[PHD];
        float m = -1e30f;
#pragma unroll
        for (int dd = 0; dd < PHD; dd++) m = fmaxf(m, msf[(h * PHD + dd) * 64 + p]);
        float s = 0.0f;
#pragma unroll
        for (int dd = 0; dd < PHD; dd++) { e[dd] = __expf(msf[(h * PHD + dd) * 64 + p] - m); s += e[dd]; }
        float sc = 0.17677669529663687f / s;
        int kc = h >> 1;
        int klb = (h & 1) * 32;
        u32 qh_off = (u32)(kc * 8192);
        __syncthreads();
#pragma unroll
        for (int dd = 0; dd < PHD; dd += 2) {
            float v0 = e[dd] * sc, v1 = e[dd + 1] * sc;
            u32 h0 = f16_rn(v0), h1 = f16_rn(v1);
            u32 bo = (u32)(p * 128 + (klb + dd) * 2);
            bo ^= (bo >> 3) & 0x70;
            *reinterpret_cast<u32*>(dyn + qh_off + bo) = (h1 << 16) | h0;
        }
    }
    __syncthreads();

    int wm = wid & 3, wn = wid >> 2;
    float acc[4][4][4];
#pragma unroll
    for (int im = 0; im < 4; im++)
#pragma unroll
        for (int jn = 0; jn < 4; jn++)
#pragma unroll
            for (int q = 0; q < 4; q++) acc[im][jn][q] = 0.0f;

    u32 a_off[4], b_off[2];
#pragma unroll
    for (int im = 0; im < 4; im++) {
        int arow = wm * 64 + im * 16 + (lane & 15);
        u32 bo = (u32)(arow * 128) + ((lane >> 4) << 4);
        a_off[im] = bo ^ ((bo >> 3) & 0x70);
    }
#pragma unroll
    for (int j2 = 0; j2 < 2; j2++) {
        int nrow = wn * 32 + j2 * 16 + ((lane >> 4) << 3) + (lane & 7);
        u32 bo = (u32)(nrow * 128) + (((lane >> 3) & 1) << 4);
        b_off[j2] = bo ^ ((bo >> 3) & 0x70);
    }
    u32 mh_base = base + 32768u, ml_base = base + 65536u;

    for (int kc = 0; kc < 2; kc++) {
        u32 qh = base + (u32)(kc * 8192);
#pragma unroll
        for (int i = 0; i < 8; i++) {
            int u = tid + i * 256;
            int r = u >> 3, c8 = (u & 7) << 3;
            u32 bo = (u32)((r << 7) + (c8 << 1));
            bo ^= (bo >> 3) & 0x70;
            int gi = (b * PC + r) * PHID + kc * 64 + c8;
            *reinterpret_cast<uint4*>(dyn + 32768 + bo) =
                *reinterpret_cast<const uint4*>(&g_Mh[gi]);
            *reinterpret_cast<uint4*>(dyn + 65536 + bo) =
                *reinterpret_cast<const uint4*>(&g_Ml[gi]);
        }
        __syncthreads();
#pragma unroll
        for (int kk = 0; kk < 4; kk++) {
            u32 kadd = (u32)(kk * 32);
            u32 a[4][4];
#pragma unroll
            for (int im = 0; im < 4; im++) ldsm4(a[im], mh_base + (a_off[im] ^ kadd));
            u32 al[4][4];
#pragma unroll
            for (int im = 0; im < 4; im++) ldsm4(al[im], ml_base + (a_off[im] ^ kadd));
            u32 bh[4][2];
#pragma unroll
            for (int j2 = 0; j2 < 2; j2++) {
                u32 r4[4];
                ldsm4(r4, qh + (b_off[j2] ^ kadd));
                bh[2 * j2][0] = r4[0]; bh[2 * j2][1] = r4[1];
                bh[2 * j2 + 1][0] = r4[2]; bh[2 * j2 + 1][1] = r4[3];
            }
#pragma unroll
            for (int im = 0; im < 4; im++)
#pragma unroll
                for (int jn = 0; jn < 4; jn++)
                    mma16816(acc[im][jn], a[im], bh[jn]);
#pragma unroll
            for (int im = 0; im < 4; im++)
#pragma unroll
                for (int jn = 0; jn < 4; jn++)
                    mma16816(acc[im][jn], al[im], bh[jn]);
        }
        __syncthreads();
    }

    float bo0[4], bo8[4], go0[4], go8[4];
#pragma unroll
    for (int im = 0; im < 4; im++) {
        int r = wm * 64 + im * 16 + (lane >> 2);
        bo0[im] = b_out[r];  bo8[im] = b_out[r + 8];
        go0[im] = g_out[r];  go8[im] = g_out[r + 8];
    }
#pragma unroll
    for (int jn = 0; jn < 4; jn++) {
        float sq0 = 0.f, sq1 = 0.f;
#pragma unroll
        for (int im = 0; im < 4; im++) {
            acc[im][jn][0] += bo0[im]; acc[im][jn][1] += bo0[im];
            acc[im][jn][2] += bo8[im]; acc[im][jn][3] += bo8[im];
            sq0 += acc[im][jn][0] * acc[im][jn][0] + acc[im][jn][2] * acc[im][jn][2];
            sq1 += acc[im][jn][1] * acc[im][jn][1] + acc[im][jn][3] * acc[im][jn][3];
        }
#pragma unroll
        for (int off = 4; off < 32; off <<= 1) {
            sq0 += __shfl_xor_sync(0xffffffffu, sq0, off);
            sq1 += __shfl_xor_sync(0xffffffffu, sq1, off);
        }
        if (lane < 4) {
            int c = wn * 32 + jn * 8 + lane * 2;
            red[wm * 64 + c] = sq0;
            red[wm * 64 + c + 1] = sq1;
        }
    }
    __syncthreads();
    if (tid < 64) {
        float s = red[tid] + red[64 + tid] + red[128 + tid] + red[192 + tid];
        invr[tid] = 16.0f / fmaxf(sqrtf(s), 1e-12f);
    }
    __syncthreads();
#pragma unroll
    for (int im = 0; im < 4; im++) {
        int r = wm * 64 + im * 16 + (lane >> 2);
#pragma unroll
        for (int jn = 0; jn < 4; jn++) {
            int c = wn * 32 + jn * 8 + (lane & 3) * 2;
            float iv0 = invr[c], iv1 = invr[c + 1];
            float2 v0 = {acc[im][jn][0] * iv0 * go0[im], acc[im][jn][1] * iv1 * go0[im]};
            float2 v1 = {acc[im][jn][2] * iv0 * go8[im], acc[im][jn][3] * iv1 * go8[im]};
            *reinterpret_cast<float2*>(&out[((size_t)(b * PC + r)) * PN + p0 + c]) = v0;
            *reinterpret_cast<float2*>(&out[((size_t)(b * PC + r + 8)) * PN + p0 + c]) = v1;
        }
    }
}

// ---------------- launch ----------------
extern "C" void kernel_launch(void* const* d_in, const int* in_sizes, int n_in,
                              void* d_out, int out_size) {
    const float* x      = (const float*)d_in[0];
    const float* g_in   = (const float*)d_in[1];
    const float* mem_kv = (const float*)d_in[2];
    const float* w_qkv  = (const float*)d_in[3];
    const float* w_out  = (const float*)d_in[4];
    const float* b_out  = (const float*)d_in[5];
    const float* g_out  = (const float*)d_in[6];
    float* out = (float*)d_out;

    static int attr_done = 0;
    if (!attr_done) {
        cudaFuncSetAttribute(k_normx,   cudaFuncAttributeMaxDynamicSharedMemorySize, NORMX_SMEM);
        cudaFuncSetAttribute(k_qkv_mma, cudaFuncAttributeMaxDynamicSharedMemorySize, QKV_SMEM);
        cudaFuncSetAttribute(k_out_mma, cudaFuncAttributeMaxDynamicSharedMemorySize, OUT_SMEM);
        attr_done = 1;
    }

    k_convw  <<<QROWS, 256>>>(w_qkv, g_in);
    k_normx  <<<dim3(PN / 64, PB), 256, NORMX_SMEM>>>(x);
    k_qkv_mma<<<dim3(PN / 128, QROWS / 128, PB), 256, QKV_SMEM>>>();
    k_kstats <<<512, 128>>>(mem_kv);
    k_context<<<dim3(8, PNH, PB), 256>>>(mem_kv);
    k_fold   <<<PB, 256>>>(w_out);
    k_out_mma<<<dim3(PN / 64, PB), 256, OUT_SMEM>>>(b_out, g_out, out);
}